// round 7
// baseline (speedup 1.0000x reference)
#include <cuda_runtime.h>
#include <cuda_bf16.h>
#include <cstdint>
#include <math.h>

#define NN 60000
#define NE 119998
#define NP 59999
#define TLOG (NN + NP)

typedef __nv_bfloat16 bf16;

// ---------------- fp32 scratch --------------------------------------------
__device__ float g_msg  [(size_t)NE * 256];
__device__ float g_suv  [(size_t)NE * 256];
__device__ float g_r    [(size_t)NE * 256];
__device__ float g_z    [(size_t)NE * 256];
__device__ float g_aggr [(size_t)NN * 256];
__device__ float g_xg   [(size_t)NN * 256];
__device__ float g_h1   [(size_t)NN * 512];
__device__ float g_logits[TLOG];
__device__ float g_red[2];

// ---------------- bf16 hi/lo scratch (one big arena) -----------------------
#define SZ_FEATS ((size_t)NE * 192)
#define SZ_E256  ((size_t)NE * 256)
#define SZ_X     ((size_t)NN * 128)
#define SZ_N256  ((size_t)NN * 256)
#define SZ_XE    ((size_t)NP * 512)

constexpr size_t O_FEATS_H = 0;
constexpr size_t O_FEATS_L = O_FEATS_H + SZ_FEATS;
constexpr size_t O_MSG_H   = O_FEATS_L + SZ_FEATS;
constexpr size_t O_MSG_L   = O_MSG_H + SZ_E256;
constexpr size_t O_SUV_H   = O_MSG_L + SZ_E256;
constexpr size_t O_SUV_L   = O_SUV_H + SZ_E256;
constexpr size_t O_RD_H    = O_SUV_L + SZ_E256;
constexpr size_t O_RD_L    = O_RD_H + SZ_E256;
constexpr size_t O_X_H     = O_RD_L + SZ_E256;
constexpr size_t O_X_L     = O_X_H + SZ_X;
constexpr size_t O_AG_H    = O_X_L + SZ_X;
constexpr size_t O_AG_L    = O_AG_H + SZ_N256;
constexpr size_t O_XG_H    = O_AG_L + SZ_N256;
constexpr size_t O_XG_L    = O_XG_H + SZ_N256;
constexpr size_t O_XE_H    = O_XG_L + SZ_N256;
constexpr size_t O_XE_L    = O_XE_H + SZ_XE;
constexpr size_t O_WZ1_H   = O_XE_L + SZ_XE;
constexpr size_t O_WZ1_L   = O_WZ1_H + 4 * 256 * 192;
constexpr size_t O_WZ2_H   = O_WZ1_L + 4 * 256 * 192;
constexpr size_t O_WZ2_L   = O_WZ2_H + 4 * 256 * 256;
constexpr size_t O_WR1_H   = O_WZ2_L + 4 * 256 * 256;
constexpr size_t O_WR1_L   = O_WR1_H + 4 * 256 * 192;
constexpr size_t O_WR2_H   = O_WR1_L + 4 * 256 * 192;
constexpr size_t O_WR2_L   = O_WR2_H + 4 * 256 * 256;
constexpr size_t O_WW_H    = O_WR2_L + 4 * 256 * 256;
constexpr size_t O_WW_L    = O_WW_H + 4 * 256 * 192;
constexpr size_t O_UW_H    = O_WW_L + 4 * 256 * 192;
constexpr size_t O_UW_L    = O_UW_H + 4 * 256 * 256;
constexpr size_t O_M1_H    = O_UW_L + 4 * 256 * 256;
constexpr size_t O_M1_L    = O_M1_H + 256 * 128;
constexpr size_t O_M2_H    = O_M1_L + 256 * 128;
constexpr size_t O_M2_L    = O_M2_H + 256 * 256;
constexpr size_t O_N1_H    = O_M2_L + 256 * 256;
constexpr size_t O_N1_L    = O_N1_H + 512 * 256;
constexpr size_t O_E1_H    = O_N1_L + 512 * 256;
constexpr size_t O_E1_L    = O_E1_H + 512 * 512;
constexpr size_t BF_TOTAL  = O_E1_L + 512 * 512;

__device__ bf16 g_bf[BF_TOTAL];

// ---------------- helpers --------------------------------------------------
__device__ __forceinline__ uint32_t s2u(const void* p) {
    uint32_t a;
    asm("{ .reg .u64 t; cvta.to.shared.u64 t, %1; cvt.u32.u64 %0, t; }" : "=r"(a) : "l"(p));
    return a;
}

__device__ __forceinline__ void mma16816(float* c, const uint32_t* a, const uint32_t* b) {
    asm volatile(
        "mma.sync.aligned.m16n8k16.row.col.f32.bf16.bf16.f32 "
        "{%0,%1,%2,%3}, {%4,%5,%6,%7}, {%8,%9}, {%0,%1,%2,%3};"
        : "+f"(c[0]), "+f"(c[1]), "+f"(c[2]), "+f"(c[3])
        : "r"(a[0]), "r"(a[1]), "r"(a[2]), "r"(a[3]), "r"(b[0]), "r"(b[1]));
}

__device__ __forceinline__ void ldsm4(uint32_t* r, uint32_t addr) {
    asm volatile("ldmatrix.sync.aligned.m8n8.x4.shared.b16 {%0,%1,%2,%3}, [%4];"
                 : "=r"(r[0]), "=r"(r[1]), "=r"(r[2]), "=r"(r[3]) : "r"(addr));
}

__device__ __forceinline__ void store_hl4(bf16* hp, bf16* lp, float4 v) {
    bf16 h0 = __float2bfloat16(v.x), h1 = __float2bfloat16(v.y);
    bf16 h2 = __float2bfloat16(v.z), h3 = __float2bfloat16(v.w);
    bf16 l0 = __float2bfloat16(v.x - __bfloat162float(h0));
    bf16 l1 = __float2bfloat16(v.y - __bfloat162float(h1));
    bf16 l2 = __float2bfloat16(v.z - __bfloat162float(h2));
    bf16 l3 = __float2bfloat16(v.w - __bfloat162float(h3));
    ((__nv_bfloat162*)hp)[0] = __halves2bfloat162(h0, h1);
    ((__nv_bfloat162*)hp)[1] = __halves2bfloat162(h2, h3);
    ((__nv_bfloat162*)lp)[0] = __halves2bfloat162(l0, l1);
    ((__nv_bfloat162*)lp)[1] = __halves2bfloat162(l2, l3);
}

__device__ __forceinline__ void store_hl2(bf16* hp, bf16* lp, float v0, float v1) {
    bf16 h0 = __float2bfloat16(v0), h1 = __float2bfloat16(v1);
    bf16 l0 = __float2bfloat16(v0 - __bfloat162float(h0));
    bf16 l1 = __float2bfloat16(v1 - __bfloat162float(h1));
    *(__nv_bfloat162*)hp = __halves2bfloat162(h0, h1);
    *(__nv_bfloat162*)lp = __halves2bfloat162(l0, l1);
}

// ---------------- small kernels --------------------------------------------
// feats hi/lo written directly (padded to 192 cols)
__global__ void featsk(const float* __restrict__ x, const float* __restrict__ ea,
                       const int* __restrict__ ei,
                       bf16* __restrict__ fh, bf16* __restrict__ fl) {
    int i = blockIdx.x * blockDim.x + threadIdx.x;
    if (i >= NE * 48) return;
    int e = i / 48;
    int q = i - e * 48;
    float4 v = make_float4(0.f, 0.f, 0.f, 0.f);
    if (q < 32) {
        int t = ei[NE + e];
        v = ((const float4*)x)[(size_t)t * 32 + q];
    } else if (q < 40) {
        v = ((const float4*)ea)[(size_t)e * 8 + (q - 32)];
    }
    size_t o = (size_t)e * 192 + q * 4;
    store_hl4(fh + o, fl + o, v);
}

__global__ void suvk(const int* __restrict__ nbr, bf16* __restrict__ sh, bf16* __restrict__ sl) {
    int i = blockIdx.x * blockDim.x + threadIdx.x;
    if (i >= NE * 64) return;
    int e = i >> 6, q = i & 63;
    const float4* m4 = (const float4*)g_msg;
    float4 acc = make_float4(0.f, 0.f, 0.f, 0.f);
#pragma unroll
    for (int j = 0; j < 3; ++j) {
        int idx = nbr[3 * (size_t)e + j];
        if (idx > 0) {
            float4 v = m4[(size_t)(idx - 1) * 64 + q];
            acc.x += v.x; acc.y += v.y; acc.z += v.z; acc.w += v.w;
        }
    }
    ((float4*)g_suv)[i] = acc;
    size_t o = (size_t)e * 256 + q * 4;
    store_hl4(sh + o, sl + o, acc);
}

__global__ void rdashk(const int* __restrict__ nbr, bf16* __restrict__ rh, bf16* __restrict__ rl) {
    int i = blockIdx.x * blockDim.x + threadIdx.x;
    if (i >= NE * 64) return;
    int e = i >> 6, q = i & 63;
    const float4* m4 = (const float4*)g_msg;
    const float4* r4 = (const float4*)g_r;
    float4 acc = make_float4(0.f, 0.f, 0.f, 0.f);
#pragma unroll
    for (int j = 0; j < 3; ++j) {
        int idx = nbr[3 * (size_t)e + j];
        if (idx > 0) {
            size_t o = (size_t)(idx - 1) * 64 + q;
            float4 g = m4[o];
            float4 rr = r4[o];
            acc.x = fmaf(rr.x, g.x, acc.x);
            acc.y = fmaf(rr.y, g.y, acc.y);
            acc.z = fmaf(rr.z, g.z, acc.z);
            acc.w = fmaf(rr.w, g.w, acc.w);
        }
    }
    size_t o = (size_t)e * 256 + q * 4;
    store_hl4(rh + o, rl + o, acc);
}

__global__ void aggrk(const int* __restrict__ ei) {
    int i = blockIdx.x * blockDim.x + threadIdx.x;
    if (i >= NE * 256) return;
    int e = i >> 8, h = i & 255;
    int t = ei[NE + e];
    atomicAdd(&g_aggr[(size_t)t * 256 + h], g_msg[i]);
}

__global__ void xedgek(const int* __restrict__ ei, bf16* __restrict__ xh, bf16* __restrict__ xl) {
    int i = blockIdx.x * blockDim.x + threadIdx.x;
    if (i >= NP * 64) return;
    int p = i >> 6, q = i & 63;
    int u = ei[2 * p];
    int v = ei[NE + 2 * p];
    const float4* X = (const float4*)g_xg;
    float4 a = X[(size_t)u * 64 + q];
    float4 b = X[(size_t)v * 64 + q];
    size_t o = (size_t)p * 512 + q * 4;
    store_hl4(xh + o, xl + o,
        make_float4(fabsf(a.x - b.x), fabsf(a.y - b.y), fabsf(a.z - b.z), fabsf(a.w - b.w)));
    store_hl4(xh + o + 256, xl + o + 256,
        make_float4(a.x + b.x, a.y + b.y, a.z + b.z, a.w + b.w));
}

// pad-convert fp32 -> bf16 hi/lo
__global__ void convk(const float* __restrict__ src, long long total, int K, int rowStride,
                      int colOff, int Kp, bf16* __restrict__ hi, bf16* __restrict__ lo) {
    long long i = (long long)blockIdx.x * blockDim.x + threadIdx.x;
    if (i >= total) return;
    int k = (int)(i % Kp);
    long long row = i / Kp;
    float v = (k < K) ? src[row * rowStride + colOff + k] : 0.f;
    bf16 h = __float2bfloat16(v);
    hi[i] = h;
    lo[i] = __float2bfloat16(v - __bfloat162float(h));
}

// ---------------- split-bf16 mma.sync GEMM ----------------------------------
// CTA tile 128(M) x 256(N), warp tile 64x64, K-chunk 32, 3-stage cp.async.
// C = act(A1@B1^T + A2@B2^T + bias); mode 0=sigmoid 1=GRU 2=relu
#define ROWB 80                        // 32 bf16 = 64B data + 16B pad
#define ATILE (128 * ROWB)             // 10240
#define BTILE (256 * ROWB)             // 20480
#define OF_AL ATILE
#define OF_BH (2 * ATILE)
#define OF_BL (2 * ATILE + BTILE)
#define STG (2 * ATILE + 2 * BTILE)    // 61440
#define SMEM_DYN (3 * STG)             // 184320

__global__ void __launch_bounds__(256) gemm_tc(
    const bf16* __restrict__ A1h, const bf16* __restrict__ A1l, int K1p,
    const bf16* __restrict__ B1h, const bf16* __restrict__ B1l,
    const bf16* __restrict__ A2h, const bf16* __restrict__ A2l, int K2p,
    const bf16* __restrict__ B2h, const bf16* __restrict__ B2l,
    const float* __restrict__ bias, float* __restrict__ C, int M, int N, int mode,
    const float* __restrict__ zb, const float* __restrict__ sb,
    bf16* __restrict__ outH, bf16* __restrict__ outL)
{
    extern __shared__ char dsm[];
    const uint32_t smem_u = s2u(dsm);
    const int tid  = threadIdx.x;
    const int warp = tid >> 5;
    const int lane = tid & 31;
    const int g    = lane >> 2;
    const int t    = lane & 3;
    const int wm   = warp & 1;       // 64-row half
    const int wn   = warp >> 1;      // 0..3 -> 64-col quarter of 256
    const int m0   = blockIdx.x * 128;
    const int n0   = blockIdx.y * 256;

    const int nch1 = K1p >> 5;
    const int nch2 = B2h ? (K2p >> 5) : 0;
    const int nch  = nch1 + nch2;

    // ldmatrix lane addresses (offsets within a stage)
    uint32_t aAddr[4], bAddr[4];
#pragma unroll
    for (int mt = 0; mt < 4; ++mt) {
        int row = wm * 64 + mt * 16 + ((lane >> 3) & 1) * 8 + (lane & 7);
        aAddr[mt] = (uint32_t)(row * ROWB + (lane >> 4) * 16);
    }
#pragma unroll
    for (int np = 0; np < 4; ++np) {
        int row = wn * 64 + np * 16 + ((lane >> 4) & 1) * 8 + (lane & 7);
        bAddr[np] = (uint32_t)(OF_BH + row * ROWB + ((lane >> 3) & 1) * 16);
    }

    float acc[4][8][4];
#pragma unroll
    for (int i = 0; i < 4; ++i)
#pragma unroll
        for (int j = 0; j < 8; ++j)
#pragma unroll
            for (int k = 0; k < 4; ++k) acc[i][j][k] = 0.f;

    auto issue = [&](int c) {
        const bf16 *Ah, *Al, *Bh, *Bl;
        int lda, kc;
        if (c < nch1) { Ah = A1h; Al = A1l; Bh = B1h; Bl = B1l; lda = K1p; kc = c << 5; }
        else          { Ah = A2h; Al = A2l; Bh = B2h; Bl = B2l; lda = K2p; kc = (c - nch1) << 5; }
        uint32_t dst0 = smem_u + (uint32_t)((c % 3) * STG);
#pragma unroll
        for (int it = 0; it < 12; ++it) {
            int u = tid + it * 256;
            const bf16* sm;
            uint32_t doff;
            int row, seg, sz = 16;
            long long grow;
            if (u < 1024) {
                int half = u >> 9;
                int rem  = u & 511;
                row = rem >> 2; seg = rem & 3;
                sm = half ? A1l : A1h;            // placeholder, fixed below
                sm = half ? Al : Ah;
                int gm = m0 + row;
                if (gm >= M) { gm = M - 1; sz = 0; }
                grow = gm;
                doff = (uint32_t)(half * ATILE + row * ROWB + seg * 16);
            } else {
                int v = u - 1024;
                int half = v >> 10;
                int rem  = v & 1023;
                row = rem >> 2; seg = rem & 3;
                sm = half ? Bl : Bh;
                grow = n0 + row;
                doff = (uint32_t)(OF_BH + half * BTILE + row * ROWB + seg * 16);
            }
            const char* src = (const char*)(sm + grow * (long long)lda + kc) + seg * 16;
            uint32_t du = dst0 + doff;
            asm volatile("cp.async.cg.shared.global [%0], [%1], 16, %2;"
                         :: "r"(du), "l"(src), "r"(sz) : "memory");
        }
        asm volatile("cp.async.commit_group;" ::: "memory");
    };

    issue(0);
    if (nch > 1) issue(1);
    for (int c = 0; c < nch; ++c) {
        if (c + 2 < nch) {
            issue(c + 2);
            asm volatile("cp.async.wait_group 2;" ::: "memory");
        } else if (c + 1 < nch) {
            asm volatile("cp.async.wait_group 1;" ::: "memory");
        } else {
            asm volatile("cp.async.wait_group 0;" ::: "memory");
        }
        __syncthreads();

        const uint32_t base = smem_u + (uint32_t)((c % 3) * STG);
#pragma unroll
        for (int ks = 0; ks < 2; ++ks) {
            const uint32_t ko = ks * 32;
            uint32_t ah[4][4], bh[4][4];
#pragma unroll
            for (int mt = 0; mt < 4; ++mt) ldsm4(ah[mt], base + aAddr[mt] + ko);
#pragma unroll
            for (int np = 0; np < 4; ++np) ldsm4(bh[np], base + bAddr[np] + ko);
#pragma unroll
            for (int mt = 0; mt < 4; ++mt)
#pragma unroll
                for (int nt = 0; nt < 8; ++nt)
                    mma16816(acc[mt][nt], ah[mt], &bh[nt >> 1][(nt & 1) * 2]);
            {   // term2: ah x bl
                uint32_t bl[4][4];
#pragma unroll
                for (int np = 0; np < 4; ++np) ldsm4(bl[np], base + bAddr[np] + BTILE + ko);
#pragma unroll
                for (int mt = 0; mt < 4; ++mt)
#pragma unroll
                    for (int nt = 0; nt < 8; ++nt)
                        mma16816(acc[mt][nt], ah[mt], &bl[nt >> 1][(nt & 1) * 2]);
            }
            {   // term3: al x bh
                uint32_t al[4][4];
#pragma unroll
                for (int mt = 0; mt < 4; ++mt) ldsm4(al[mt], base + aAddr[mt] + ATILE + ko);
#pragma unroll
                for (int mt = 0; mt < 4; ++mt)
#pragma unroll
                    for (int nt = 0; nt < 8; ++nt)
                        mma16816(acc[mt][nt], al[mt], &bh[nt >> 1][(nt & 1) * 2]);
            }
        }
        __syncthreads();
    }

    // ---------------- epilogue ----------------
#pragma unroll
    for (int mt = 0; mt < 4; ++mt) {
        int rg = m0 + wm * 64 + mt * 16 + g;
#pragma unroll
        for (int nt = 0; nt < 8; ++nt) {
            int cn = n0 + wn * 64 + nt * 8 + 2 * t;
            float b0 = bias[cn], b1 = bias[cn + 1];
#pragma unroll
            for (int h = 0; h < 2; ++h) {
                int row = rg + h * 8;
                if (row >= M) continue;
                float v0 = acc[mt][nt][2 * h]     + b0;
                float v1 = acc[mt][nt][2 * h + 1] + b1;
                size_t idx = (size_t)row * N + cn;
                if (mode == 0) {
                    v0 = 1.f / (1.f + expf(-v0));
                    v1 = 1.f / (1.f + expf(-v1));
                } else if (mode == 1) {
                    float z0 = zb[idx], z1 = zb[idx + 1];
                    v0 = (1.f - z0) * sb[idx]     + z0 * tanhf(v0);
                    v1 = (1.f - z1) * sb[idx + 1] + z1 * tanhf(v1);
                } else {
                    v0 = fmaxf(v0, 0.f);
                    v1 = fmaxf(v1, 0.f);
                }
                *(float2*)(C + idx) = make_float2(v0, v1);
                if (outH) store_hl2(outH + idx, outL + idx, v0, v1);
            }
        }
    }
}

// ---------------- head dot + softmax ---------------------------------------
__global__ void dotk(const float* __restrict__ w, const float* __restrict__ bptr,
                     float* __restrict__ out, int rows) {
    int gw = (blockIdx.x * blockDim.x + threadIdx.x) >> 5;
    int lane = threadIdx.x & 31;
    if (gw >= rows) return;
    const float* hrow = g_h1 + (size_t)gw * 512;
    float s = 0.f;
#pragma unroll
    for (int k = 0; k < 16; ++k) s = fmaf(hrow[lane + 32 * k], w[lane + 32 * k], s);
#pragma unroll
    for (int o = 16; o; o >>= 1) s += __shfl_down_sync(0xffffffffu, s, o);
    if (lane == 0) out[gw] = s + bptr[0];
}

__global__ void soft1k() {
    __shared__ float sm[1024];
    int tid = threadIdx.x;
    float mx = -1e30f;
    for (int i = tid; i < TLOG; i += 1024) mx = fmaxf(mx, g_logits[i]);
    sm[tid] = mx;
    __syncthreads();
    for (int s = 512; s > 0; s >>= 1) {
        if (tid < s) sm[tid] = fmaxf(sm[tid], sm[tid + s]);
        __syncthreads();
    }
    float gmax = sm[0];
    __syncthreads();
    float sum = 0.f;
    for (int i = tid; i < TLOG; i += 1024) sum += expf(g_logits[i] - gmax);
    sm[tid] = sum;
    __syncthreads();
    for (int s = 512; s > 0; s >>= 1) {
        if (tid < s) sm[tid] += sm[tid + s];
        __syncthreads();
    }
    if (tid == 0) { g_red[0] = gmax; g_red[1] = sm[0]; }
}

__global__ void soft2k(float* __restrict__ out) {
    int i = blockIdx.x * blockDim.x + threadIdx.x;
    if (i < TLOG) out[i] = expf(g_logits[i] - g_red[0]) / g_red[1];
}

// ---------------------------------------------------------------------------
extern "C" void kernel_launch(void* const* d_in, const int* in_sizes, int n_in,
                              void* d_out, int out_size) {
    (void)in_sizes; (void)n_in; (void)out_size;
    const float* x     = (const float*)d_in[0];
    const float* ea    = (const float*)d_in[1];
    const int*   ei    = (const int*)d_in[2];
    const int*   nbr   = (const int*)d_in[3];
    const float* Wz_w  = (const float*)d_in[4];
    const float* Wz_b  = (const float*)d_in[5];
    const float* Wr_w  = (const float*)d_in[6];
    const float* Wr_b  = (const float*)d_in[7];
    const float* W_w   = (const float*)d_in[8];
    const float* U_w   = (const float*)d_in[9];
    const float* U_b   = (const float*)d_in[10];
    const float* mlp_w = (const float*)d_in[11];
    const float* mlp_b = (const float*)d_in[12];
    const float* nc1_w = (const float*)d_in[13];
    const float* nc1_b = (const float*)d_in[14];
    const float* nc2_w = (const float*)d_in[15];
    const float* nc2_b = (const float*)d_in[16];
    const float* ec1_w = (const float*)d_in[17];
    const float* ec1_b = (const float*)d_in[18];
    const float* ec2_w = (const float*)d_in[19];
    const float* ec2_b = (const float*)d_in[20];
    float* out = (float*)d_out;

    float *msg, *suv, *r, *z, *aggr, *xg, *h1, *logits;
    bf16* bfb;
    cudaGetSymbolAddress((void**)&msg,    g_msg);
    cudaGetSymbolAddress((void**)&suv,    g_suv);
    cudaGetSymbolAddress((void**)&r,      g_r);
    cudaGetSymbolAddress((void**)&z,      g_z);
    cudaGetSymbolAddress((void**)&aggr,   g_aggr);
    cudaGetSymbolAddress((void**)&xg,     g_xg);
    cudaGetSymbolAddress((void**)&h1,     g_h1);
    cudaGetSymbolAddress((void**)&logits, g_logits);
    cudaGetSymbolAddress((void**)&bfb,    g_bf);

    cudaFuncSetAttribute(gemm_tc, cudaFuncAttributeMaxDynamicSharedMemorySize, SMEM_DYN);

    bf16 *fH = bfb + O_FEATS_H, *fL = bfb + O_FEATS_L;
    bf16 *mH = bfb + O_MSG_H,  *mL = bfb + O_MSG_L;
    bf16 *sH = bfb + O_SUV_H,  *sL = bfb + O_SUV_L;
    bf16 *rH = bfb + O_RD_H,   *rL = bfb + O_RD_L;
    bf16 *xH = bfb + O_X_H,    *xL = bfb + O_X_L;
    bf16 *aH = bfb + O_AG_H,   *aL = bfb + O_AG_L;
    bf16 *gH = bfb + O_XG_H,   *gL = bfb + O_XG_L;
    bf16 *eH = bfb + O_XE_H,   *eL = bfb + O_XE_L;

    cudaMemsetAsync(msg, 0, (size_t)NE * 256 * 4, 0);
    cudaMemsetAsync(mH, 0, SZ_E256 * 2, 0);
    cudaMemsetAsync(mL, 0, SZ_E256 * 2, 0);

    featsk<<<(NE * 48 + 255) / 256, 256>>>(x, ea, ei, fH, fL);

#define CONV(src, tot, K, stride, off, Kp, hi, lo) \
    convk<<<(int)(((long long)(tot) + 255) / 256), 256>>>(src, (long long)(tot), K, stride, off, Kp, hi, lo)

    CONV(x, (long long)NN * 128, 128, 128, 0, 128, xH, xL);
    CONV(Wz_w, 4 * 256 * 192, 160, 416, 0, 192, bfb + O_WZ1_H, bfb + O_WZ1_L);
    CONV(Wz_w, 4 * 256 * 256, 256, 416, 160, 256, bfb + O_WZ2_H, bfb + O_WZ2_L);
    CONV(Wr_w, 4 * 256 * 192, 160, 416, 0, 192, bfb + O_WR1_H, bfb + O_WR1_L);
    CONV(Wr_w, 4 * 256 * 256, 256, 416, 160, 256, bfb + O_WR2_H, bfb + O_WR2_L);
    CONV(W_w, 4 * 256 * 192, 160, 160, 0, 192, bfb + O_WW_H, bfb + O_WW_L);
    CONV(U_w, 4 * 256 * 256, 256, 256, 0, 256, bfb + O_UW_H, bfb + O_UW_L);
    CONV(mlp_w, 256 * 128, 128, 384, 0, 128, bfb + O_M1_H, bfb + O_M1_L);
    CONV(mlp_w, 256 * 256, 256, 384, 128, 256, bfb + O_M2_H, bfb + O_M2_L);
    CONV(nc1_w, 512 * 256, 256, 256, 0, 256, bfb + O_N1_H, bfb + O_N1_L);
    CONV(ec1_w, 512 * 512, 512, 512, 0, 512, bfb + O_E1_H, bfb + O_E1_L);

    const int MBE = (NE + 127) / 128;   // 938
    const int MBN = (NN + 127) / 128;   // 469
    const int MBP = (NP + 127) / 128;   // 469

    for (int l = 0; l < 4; ++l) {
        bf16* wz1H = bfb + O_WZ1_H + (size_t)l * 49152;
        bf16* wz1L = bfb + O_WZ1_L + (size_t)l * 49152;
        bf16* wz2H = bfb + O_WZ2_H + (size_t)l * 65536;
        bf16* wz2L = bfb + O_WZ2_L + (size_t)l * 65536;
        bf16* wr1H = bfb + O_WR1_H + (size_t)l * 49152;
        bf16* wr1L = bfb + O_WR1_L + (size_t)l * 49152;
        bf16* wr2H = bfb + O_WR2_H + (size_t)l * 65536;
        bf16* wr2L = bfb + O_WR2_L + (size_t)l * 65536;
        bf16* wwH  = bfb + O_WW_H + (size_t)l * 49152;
        bf16* wwL  = bfb + O_WW_L + (size_t)l * 49152;
        bf16* uwH  = bfb + O_UW_H + (size_t)l * 65536;
        bf16* uwL  = bfb + O_UW_L + (size_t)l * 65536;

        suvk<<<(NE * 64 + 255) / 256, 256>>>(nbr, sH, sL);
        gemm_tc<<<dim3(MBE, 1), 256, SMEM_DYN>>>(
            fH, fL, 192, wz1H, wz1L, sH, sL, 256, wz2H, wz2L,
            Wz_b + (size_t)l * 256, z, NE, 256, 0, nullptr, nullptr, nullptr, nullptr);
        gemm_tc<<<dim3(MBE, 1), 256, SMEM_DYN>>>(
            fH, fL, 192, wr1H, wr1L, mH, mL, 256, wr2H, wr2L,
            Wr_b + (size_t)l * 256, r, NE, 256, 0, nullptr, nullptr, nullptr, nullptr);
        rdashk<<<(NE * 64 + 255) / 256, 256>>>(nbr, rH, rL);
        gemm_tc<<<dim3(MBE, 1), 256, SMEM_DYN>>>(
            fH, fL, 192, wwH, wwL, rH, rL, 256, uwH, uwL,
            U_b + (size_t)l * 256, msg, NE, 256, 1, z, suv, mH, mL);
    }

    cudaMemsetAsync(aggr, 0, (size_t)NN * 256 * 4, 0);
    aggrk<<<(NE * 256 + 255) / 256, 256>>>(ei);
    CONV(aggr, (long long)NN * 256, 256, 256, 0, 256, aH, aL);

    gemm_tc<<<dim3(MBN, 1), 256, SMEM_DYN>>>(
        xH, xL, 128, bfb + O_M1_H, bfb + O_M1_L, aH, aL, 256, bfb + O_M2_H, bfb + O_M2_L,
        mlp_b, xg, NN, 256, 2, nullptr, nullptr, gH, gL);

    gemm_tc<<<dim3(MBN, 2), 256, SMEM_DYN>>>(
        gH, gL, 256, bfb + O_N1_H, bfb + O_N1_L, nullptr, nullptr, 0, nullptr, nullptr,
        nc1_b, h1, NN, 512, 2, nullptr, nullptr, nullptr, nullptr);
    dotk<<<(NN * 32 + 255) / 256, 256>>>(nc2_w, nc2_b, logits, NN);

    xedgek<<<(NP * 64 + 255) / 256, 256>>>(ei, eH, eL);
    gemm_tc<<<dim3(MBP, 2), 256, SMEM_DYN>>>(
        eH, eL, 512, bfb + O_E1_H, bfb + O_E1_L, nullptr, nullptr, 0, nullptr, nullptr,
        ec1_b, h1, NP, 512, 2, nullptr, nullptr, nullptr, nullptr);
    dotk<<<(NP * 32 + 255) / 256, 256>>>(ec2_w, ec2_b, logits + NN, NP);

    soft1k<<<1, 1024>>>();
    soft2k<<<(TLOG + 255) / 256, 256>>>(out);
}

// round 8
// speedup vs baseline: 1.1545x; 1.1545x over previous
#include <cuda_runtime.h>
#include <cuda_bf16.h>
#include <cstdint>
#include <math.h>

#define NN 60000
#define NE 119998
#define NP 59999
#define TLOG (NN + NP)

typedef __nv_bfloat16 bf16;

// ---------------- fp32 scratch --------------------------------------------
__device__ float g_msg  [(size_t)NE * 256];
__device__ float g_suv  [(size_t)NE * 256];
__device__ float g_r    [(size_t)NE * 256];
__device__ float g_z    [(size_t)NE * 256];
__device__ float g_aggr [(size_t)NN * 256];
__device__ float g_xg   [(size_t)NN * 256];
__device__ float g_h1   [(size_t)NN * 512];
__device__ float g_logits[TLOG];
__device__ float g_red[2];

// ---------------- bf16 hi/lo scratch (one big arena) -----------------------
#define SZ_FEATS ((size_t)NE * 192)
#define SZ_E256  ((size_t)NE * 256)
#define SZ_X     ((size_t)NN * 128)
#define SZ_N256  ((size_t)NN * 256)
#define SZ_XE    ((size_t)NP * 512)

constexpr size_t O_FEATS_H = 0;
constexpr size_t O_FEATS_L = O_FEATS_H + SZ_FEATS;
constexpr size_t O_MSG_H   = O_FEATS_L + SZ_FEATS;
constexpr size_t O_MSG_L   = O_MSG_H + SZ_E256;
constexpr size_t O_SUV_H   = O_MSG_L + SZ_E256;
constexpr size_t O_SUV_L   = O_SUV_H + SZ_E256;
constexpr size_t O_RD_H    = O_SUV_L + SZ_E256;
constexpr size_t O_RD_L    = O_RD_H + SZ_E256;
constexpr size_t O_X_H     = O_RD_L + SZ_E256;
constexpr size_t O_X_L     = O_X_H + SZ_X;
constexpr size_t O_AG_H    = O_X_L + SZ_X;
constexpr size_t O_AG_L    = O_AG_H + SZ_N256;
constexpr size_t O_XG_H    = O_AG_L + SZ_N256;
constexpr size_t O_XG_L    = O_XG_H + SZ_N256;
constexpr size_t O_XE_H    = O_XG_L + SZ_N256;
constexpr size_t O_XE_L    = O_XE_H + SZ_XE;
constexpr size_t O_WZ1_H   = O_XE_L + SZ_XE;
constexpr size_t O_WZ1_L   = O_WZ1_H + 4 * 256 * 192;
constexpr size_t O_WZ2_H   = O_WZ1_L + 4 * 256 * 192;
constexpr size_t O_WZ2_L   = O_WZ2_H + 4 * 256 * 256;
constexpr size_t O_WR1_H   = O_WZ2_L + 4 * 256 * 256;
constexpr size_t O_WR1_L   = O_WR1_H + 4 * 256 * 192;
constexpr size_t O_WR2_H   = O_WR1_L + 4 * 256 * 192;
constexpr size_t O_WR2_L   = O_WR2_H + 4 * 256 * 256;
constexpr size_t O_WW_H    = O_WR2_L + 4 * 256 * 256;
constexpr size_t O_WW_L    = O_WW_H + 4 * 256 * 192;
constexpr size_t O_UW_H    = O_WW_L + 4 * 256 * 192;
constexpr size_t O_UW_L    = O_UW_H + 4 * 256 * 256;
constexpr size_t O_M1_H    = O_UW_L + 4 * 256 * 256;
constexpr size_t O_M1_L    = O_M1_H + 256 * 128;
constexpr size_t O_M2_H    = O_M1_L + 256 * 128;
constexpr size_t O_M2_L    = O_M2_H + 256 * 256;
constexpr size_t O_N1_H    = O_M2_L + 256 * 256;
constexpr size_t O_N1_L    = O_N1_H + 512 * 256;
constexpr size_t O_E1_H    = O_N1_L + 512 * 256;
constexpr size_t O_E1_L    = O_E1_H + 512 * 512;
constexpr size_t BF_TOTAL  = O_E1_L + 512 * 512;

__device__ bf16 g_bf[BF_TOTAL];

// ---------------- helpers --------------------------------------------------
__device__ __forceinline__ uint32_t s2u(const void* p) {
    uint32_t a;
    asm("{ .reg .u64 t; cvta.to.shared.u64 t, %1; cvt.u32.u64 %0, t; }" : "=r"(a) : "l"(p));
    return a;
}

__device__ __forceinline__ void mma16816(float* c, const uint32_t* a, const uint32_t* b) {
    asm volatile(
        "mma.sync.aligned.m16n8k16.row.col.f32.bf16.bf16.f32 "
        "{%0,%1,%2,%3}, {%4,%5,%6,%7}, {%8,%9}, {%0,%1,%2,%3};"
        : "+f"(c[0]), "+f"(c[1]), "+f"(c[2]), "+f"(c[3])
        : "r"(a[0]), "r"(a[1]), "r"(a[2]), "r"(a[3]), "r"(b[0]), "r"(b[1]));
}

__device__ __forceinline__ void ldsm4(uint32_t* r, uint32_t addr) {
    asm volatile("ldmatrix.sync.aligned.m8n8.x4.shared.b16 {%0,%1,%2,%3}, [%4];"
                 : "=r"(r[0]), "=r"(r[1]), "=r"(r[2]), "=r"(r[3]) : "r"(addr));
}

__device__ __forceinline__ void store_hl4(bf16* hp, bf16* lp, float4 v) {
    bf16 h0 = __float2bfloat16(v.x), h1 = __float2bfloat16(v.y);
    bf16 h2 = __float2bfloat16(v.z), h3 = __float2bfloat16(v.w);
    bf16 l0 = __float2bfloat16(v.x - __bfloat162float(h0));
    bf16 l1 = __float2bfloat16(v.y - __bfloat162float(h1));
    bf16 l2 = __float2bfloat16(v.z - __bfloat162float(h2));
    bf16 l3 = __float2bfloat16(v.w - __bfloat162float(h3));
    ((__nv_bfloat162*)hp)[0] = __halves2bfloat162(h0, h1);
    ((__nv_bfloat162*)hp)[1] = __halves2bfloat162(h2, h3);
    ((__nv_bfloat162*)lp)[0] = __halves2bfloat162(l0, l1);
    ((__nv_bfloat162*)lp)[1] = __halves2bfloat162(l2, l3);
}

__device__ __forceinline__ void store_hl2(bf16* hp, bf16* lp, float v0, float v1) {
    bf16 h0 = __float2bfloat16(v0), h1 = __float2bfloat16(v1);
    bf16 l0 = __float2bfloat16(v0 - __bfloat162float(h0));
    bf16 l1 = __float2bfloat16(v1 - __bfloat162float(h1));
    *(__nv_bfloat162*)hp = __halves2bfloat162(h0, h1);
    *(__nv_bfloat162*)lp = __halves2bfloat162(l0, l1);
}

// ---------------- small kernels --------------------------------------------
// feats hi/lo written directly (padded to 192 cols)
__global__ void featsk(const float* __restrict__ x, const float* __restrict__ ea,
                       const int* __restrict__ ei,
                       bf16* __restrict__ fh, bf16* __restrict__ fl) {
    int i = blockIdx.x * blockDim.x + threadIdx.x;
    if (i >= NE * 48) return;
    int e = i / 48;
    int q = i - e * 48;
    float4 v = make_float4(0.f, 0.f, 0.f, 0.f);
    if (q < 32) {
        int t = ei[NE + e];
        v = ((const float4*)x)[(size_t)t * 32 + q];
    } else if (q < 40) {
        v = ((const float4*)ea)[(size_t)e * 8 + (q - 32)];
    }
    size_t o = (size_t)e * 192 + q * 4;
    store_hl4(fh + o, fl + o, v);
}

__global__ void suvk(const int* __restrict__ nbr, bf16* __restrict__ sh, bf16* __restrict__ sl) {
    int i = blockIdx.x * blockDim.x + threadIdx.x;
    if (i >= NE * 64) return;
    int e = i >> 6, q = i & 63;
    const float4* m4 = (const float4*)g_msg;
    float4 acc = make_float4(0.f, 0.f, 0.f, 0.f);
#pragma unroll
    for (int j = 0; j < 3; ++j) {
        int idx = nbr[3 * (size_t)e + j];
        if (idx > 0) {
            float4 v = m4[(size_t)(idx - 1) * 64 + q];
            acc.x += v.x; acc.y += v.y; acc.z += v.z; acc.w += v.w;
        }
    }
    ((float4*)g_suv)[i] = acc;
    size_t o = (size_t)e * 256 + q * 4;
    store_hl4(sh + o, sl + o, acc);
}

__global__ void rdashk(const int* __restrict__ nbr, bf16* __restrict__ rh, bf16* __restrict__ rl) {
    int i = blockIdx.x * blockDim.x + threadIdx.x;
    if (i >= NE * 64) return;
    int e = i >> 6, q = i & 63;
    const float4* m4 = (const float4*)g_msg;
    const float4* r4 = (const float4*)g_r;
    float4 acc = make_float4(0.f, 0.f, 0.f, 0.f);
#pragma unroll
    for (int j = 0; j < 3; ++j) {
        int idx = nbr[3 * (size_t)e + j];
        if (idx > 0) {
            size_t o = (size_t)(idx - 1) * 64 + q;
            float4 g = m4[o];
            float4 rr = r4[o];
            acc.x = fmaf(rr.x, g.x, acc.x);
            acc.y = fmaf(rr.y, g.y, acc.y);
            acc.z = fmaf(rr.z, g.z, acc.z);
            acc.w = fmaf(rr.w, g.w, acc.w);
        }
    }
    size_t o = (size_t)e * 256 + q * 4;
    store_hl4(rh + o, rl + o, acc);
}

__global__ void aggrk(const int* __restrict__ ei) {
    int i = blockIdx.x * blockDim.x + threadIdx.x;
    if (i >= NE * 256) return;
    int e = i >> 8, h = i & 255;
    int t = ei[NE + e];
    atomicAdd(&g_aggr[(size_t)t * 256 + h], g_msg[i]);
}

__global__ void xedgek(const int* __restrict__ ei, bf16* __restrict__ xh, bf16* __restrict__ xl) {
    int i = blockIdx.x * blockDim.x + threadIdx.x;
    if (i >= NP * 64) return;
    int p = i >> 6, q = i & 63;
    int u = ei[2 * p];
    int v = ei[NE + 2 * p];
    const float4* X = (const float4*)g_xg;
    float4 a = X[(size_t)u * 64 + q];
    float4 b = X[(size_t)v * 64 + q];
    size_t o = (size_t)p * 512 + q * 4;
    store_hl4(xh + o, xl + o,
        make_float4(fabsf(a.x - b.x), fabsf(a.y - b.y), fabsf(a.z - b.z), fabsf(a.w - b.w)));
    store_hl4(xh + o + 256, xl + o + 256,
        make_float4(a.x + b.x, a.y + b.y, a.z + b.z, a.w + b.w));
}

// pad-convert fp32 -> bf16 hi/lo
__global__ void convk(const float* __restrict__ src, long long total, int K, int rowStride,
                      int colOff, int Kp, bf16* __restrict__ hi, bf16* __restrict__ lo) {
    long long i = (long long)blockIdx.x * blockDim.x + threadIdx.x;
    if (i >= total) return;
    int k = (int)(i % Kp);
    long long row = i / Kp;
    float v = (k < K) ? src[row * rowStride + colOff + k] : 0.f;
    bf16 h = __float2bfloat16(v);
    hi[i] = h;
    lo[i] = __float2bfloat16(v - __bfloat162float(h));
}

// ---------------- split-bf16 mma.sync GEMM ----------------------------------
// CTA tile 128x128, 4 warps (2x2) of 64x64, K-chunk 32, double buffer, 2 CTA/SM.
// C = act(A1@B1^T + A2@B2^T + bias); mode 0=sigmoid 1=GRU 2=relu
#define ROWB 80                       // 32 bf16 = 64B data + 16B pad
#define TILEB (128 * ROWB)            // 10240
#define STAGE_B (4 * TILEB)           // 40960: Ah, Al, Bh, Bl
#define SMEM_DYN (2 * STAGE_B)        // 81920 -> 2 CTAs/SM

__global__ void __launch_bounds__(128, 2) gemm_tc(
    const bf16* __restrict__ A1h, const bf16* __restrict__ A1l, int K1p,
    const bf16* __restrict__ B1h, const bf16* __restrict__ B1l,
    const bf16* __restrict__ A2h, const bf16* __restrict__ A2l, int K2p,
    const bf16* __restrict__ B2h, const bf16* __restrict__ B2l,
    const float* __restrict__ bias, float* __restrict__ C, int M, int N, int mode,
    const float* __restrict__ zb, const float* __restrict__ sb,
    bf16* __restrict__ outH, bf16* __restrict__ outL)
{
    extern __shared__ char dsm[];
    const uint32_t smem_u = s2u(dsm);
    const int tid  = threadIdx.x;
    const int warp = tid >> 5;       // 0..3
    const int lane = tid & 31;
    const int g    = lane >> 2;
    const int t    = lane & 3;
    const int wm   = warp & 1;       // 64-row half
    const int wn   = warp >> 1;      // 0..1 -> 64-col half
    const int m0   = blockIdx.x * 128;
    const int n0   = blockIdx.y * 128;

    const int nch1 = K1p >> 5;
    const int nch2 = B2h ? (K2p >> 5) : 0;
    const int nch  = nch1 + nch2;

    // ldmatrix lane addresses (offsets within a stage)
    uint32_t aAddr[4], bAddr[4];
#pragma unroll
    for (int mt = 0; mt < 4; ++mt) {
        int row = wm * 64 + mt * 16 + ((lane >> 3) & 1) * 8 + (lane & 7);
        aAddr[mt] = (uint32_t)(row * ROWB + (lane >> 4) * 16);
    }
#pragma unroll
    for (int np = 0; np < 4; ++np) {
        int row = wn * 64 + np * 16 + ((lane >> 4) & 1) * 8 + (lane & 7);
        bAddr[np] = (uint32_t)(2 * TILEB + row * ROWB + ((lane >> 3) & 1) * 16);
    }

    float acc[4][8][4];
#pragma unroll
    for (int i = 0; i < 4; ++i)
#pragma unroll
        for (int j = 0; j < 8; ++j)
#pragma unroll
            for (int k = 0; k < 4; ++k) acc[i][j][k] = 0.f;

    auto issue = [&](int c) {
        const bf16 *Ah, *Al, *Bh, *Bl;
        int lda, kc;
        if (c < nch1) { Ah = A1h; Al = A1l; Bh = B1h; Bl = B1l; lda = K1p; kc = c << 5; }
        else          { Ah = A2h; Al = A2l; Bh = B2h; Bl = B2l; lda = K2p; kc = (c - nch1) << 5; }
        uint32_t dst0 = smem_u + (uint32_t)((c & 1) * STAGE_B);
#pragma unroll
        for (int it = 0; it < 16; ++it) {
            int u = tid + it * 128;
            int which = u >> 9;            // 0 Ah, 1 Al, 2 Bh, 3 Bl
            int rem   = u & 511;
            int row   = rem >> 2;
            int seg   = rem & 3;
            const bf16* sm = (which == 0) ? Ah : (which == 1) ? Al : (which == 2) ? Bh : Bl;
            int sz = 16;
            long long grow;
            if (which < 2) {
                int gm = m0 + row;
                if (gm >= M) { gm = M - 1; sz = 0; }
                grow = gm;
            } else {
                grow = n0 + row;
            }
            const char* src = (const char*)(sm + grow * (long long)lda + kc) + seg * 16;
            uint32_t du = dst0 + (uint32_t)(which * TILEB + row * ROWB + seg * 16);
            asm volatile("cp.async.cg.shared.global [%0], [%1], 16, %2;"
                         :: "r"(du), "l"(src), "r"(sz) : "memory");
        }
        asm volatile("cp.async.commit_group;" ::: "memory");
    };

    issue(0);
    for (int c = 0; c < nch; ++c) {
        if (c + 1 < nch) {
            issue(c + 1);
            asm volatile("cp.async.wait_group 1;" ::: "memory");
        } else {
            asm volatile("cp.async.wait_group 0;" ::: "memory");
        }
        __syncthreads();

        const uint32_t base = smem_u + (uint32_t)((c & 1) * STAGE_B);
#pragma unroll
        for (int ks = 0; ks < 2; ++ks) {
            const uint32_t ko = ks * 32;
            uint32_t ah[4][4], bh[4][4];
#pragma unroll
            for (int mt = 0; mt < 4; ++mt) ldsm4(ah[mt], base + aAddr[mt] + ko);
#pragma unroll
            for (int np = 0; np < 4; ++np) ldsm4(bh[np], base + bAddr[np] + ko);
#pragma unroll
            for (int mt = 0; mt < 4; ++mt)
#pragma unroll
                for (int nt = 0; nt < 8; ++nt)
                    mma16816(acc[mt][nt], ah[mt], &bh[nt >> 1][(nt & 1) * 2]);
            {   // term2: ah x bl
                uint32_t bl[4][4];
#pragma unroll
                for (int np = 0; np < 4; ++np) ldsm4(bl[np], base + bAddr[np] + TILEB + ko);
#pragma unroll
                for (int mt = 0; mt < 4; ++mt)
#pragma unroll
                    for (int nt = 0; nt < 8; ++nt)
                        mma16816(acc[mt][nt], ah[mt], &bl[nt >> 1][(nt & 1) * 2]);
            }
            {   // term3: al x bh
                uint32_t al[4][4];
#pragma unroll
                for (int mt = 0; mt < 4; ++mt) ldsm4(al[mt], base + aAddr[mt] + TILEB + ko);
#pragma unroll
                for (int mt = 0; mt < 4; ++mt)
#pragma unroll
                    for (int nt = 0; nt < 8; ++nt)
                        mma16816(acc[mt][nt], al[mt], &bh[nt >> 1][(nt & 1) * 2]);
            }
        }
        __syncthreads();
    }

    // ---------------- epilogue ----------------
#pragma unroll
    for (int mt = 0; mt < 4; ++mt) {
        int rg = m0 + wm * 64 + mt * 16 + g;
#pragma unroll
        for (int nt = 0; nt < 8; ++nt) {
            int cn = n0 + wn * 64 + nt * 8 + 2 * t;
            float b0 = bias[cn], b1 = bias[cn + 1];
#pragma unroll
            for (int h = 0; h < 2; ++h) {
                int row = rg + h * 8;
                if (row >= M) continue;
                float v0 = acc[mt][nt][2 * h]     + b0;
                float v1 = acc[mt][nt][2 * h + 1] + b1;
                size_t idx = (size_t)row * N + cn;
                if (mode == 0) {
                    v0 = 1.f / (1.f + expf(-v0));
                    v1 = 1.f / (1.f + expf(-v1));
                } else if (mode == 1) {
                    float z0 = zb[idx], z1 = zb[idx + 1];
                    v0 = (1.f - z0) * sb[idx]     + z0 * tanhf(v0);
                    v1 = (1.f - z1) * sb[idx + 1] + z1 * tanhf(v1);
                } else {
                    v0 = fmaxf(v0, 0.f);
                    v1 = fmaxf(v1, 0.f);
                }
                *(float2*)(C + idx) = make_float2(v0, v1);
                if (outH) store_hl2(outH + idx, outL + idx, v0, v1);
            }
        }
    }
}

// ---------------- head dot + softmax ---------------------------------------
__global__ void dotk(const float* __restrict__ w, const float* __restrict__ bptr,
                     float* __restrict__ out, int rows) {
    int gw = (blockIdx.x * blockDim.x + threadIdx.x) >> 5;
    int lane = threadIdx.x & 31;
    if (gw >= rows) return;
    const float* hrow = g_h1 + (size_t)gw * 512;
    float s = 0.f;
#pragma unroll
    for (int k = 0; k < 16; ++k) s = fmaf(hrow[lane + 32 * k], w[lane + 32 * k], s);
#pragma unroll
    for (int o = 16; o; o >>= 1) s += __shfl_down_sync(0xffffffffu, s, o);
    if (lane == 0) out[gw] = s + bptr[0];
}

__global__ void soft1k() {
    __shared__ float sm[1024];
    int tid = threadIdx.x;
    float mx = -1e30f;
    for (int i = tid; i < TLOG; i += 1024) mx = fmaxf(mx, g_logits[i]);
    sm[tid] = mx;
    __syncthreads();
    for (int s = 512; s > 0; s >>= 1) {
        if (tid < s) sm[tid] = fmaxf(sm[tid], sm[tid + s]);
        __syncthreads();
    }
    float gmax = sm[0];
    __syncthreads();
    float sum = 0.f;
    for (int i = tid; i < TLOG; i += 1024) sum += expf(g_logits[i] - gmax);
    sm[tid] = sum;
    __syncthreads();
    for (int s = 512; s > 0; s >>= 1) {
        if (tid < s) sm[tid] += sm[tid + s];
        __syncthreads();
    }
    if (tid == 0) { g_red[0] = gmax; g_red[1] = sm[0]; }
}

__global__ void soft2k(float* __restrict__ out) {
    int i = blockIdx.x * blockDim.x + threadIdx.x;
    if (i < TLOG) out[i] = expf(g_logits[i] - g_red[0]) / g_red[1];
}

// ---------------------------------------------------------------------------
extern "C" void kernel_launch(void* const* d_in, const int* in_sizes, int n_in,
                              void* d_out, int out_size) {
    (void)in_sizes; (void)n_in; (void)out_size;
    const float* x     = (const float*)d_in[0];
    const float* ea    = (const float*)d_in[1];
    const int*   ei    = (const int*)d_in[2];
    const int*   nbr   = (const int*)d_in[3];
    const float* Wz_w  = (const float*)d_in[4];
    const float* Wz_b  = (const float*)d_in[5];
    const float* Wr_w  = (const float*)d_in[6];
    const float* Wr_b  = (const float*)d_in[7];
    const float* W_w   = (const float*)d_in[8];
    const float* U_w   = (const float*)d_in[9];
    const float* U_b   = (const float*)d_in[10];
    const float* mlp_w = (const float*)d_in[11];
    const float* mlp_b = (const float*)d_in[12];
    const float* nc1_w = (const float*)d_in[13];
    const float* nc1_b = (const float*)d_in[14];
    const float* nc2_w = (const float*)d_in[15];
    const float* nc2_b = (const float*)d_in[16];
    const float* ec1_w = (const float*)d_in[17];
    const float* ec1_b = (const float*)d_in[18];
    const float* ec2_w = (const float*)d_in[19];
    const float* ec2_b = (const float*)d_in[20];
    float* out = (float*)d_out;

    float *msg, *suv, *r, *z, *aggr, *xg, *h1, *logits;
    bf16* bfb;
    cudaGetSymbolAddress((void**)&msg,    g_msg);
    cudaGetSymbolAddress((void**)&suv,    g_suv);
    cudaGetSymbolAddress((void**)&r,      g_r);
    cudaGetSymbolAddress((void**)&z,      g_z);
    cudaGetSymbolAddress((void**)&aggr,   g_aggr);
    cudaGetSymbolAddress((void**)&xg,     g_xg);
    cudaGetSymbolAddress((void**)&h1,     g_h1);
    cudaGetSymbolAddress((void**)&logits, g_logits);
    cudaGetSymbolAddress((void**)&bfb,    g_bf);

    cudaFuncSetAttribute(gemm_tc, cudaFuncAttributeMaxDynamicSharedMemorySize, SMEM_DYN);

    bf16 *fH = bfb + O_FEATS_H, *fL = bfb + O_FEATS_L;
    bf16 *mH = bfb + O_MSG_H,  *mL = bfb + O_MSG_L;
    bf16 *sH = bfb + O_SUV_H,  *sL = bfb + O_SUV_L;
    bf16 *rH = bfb + O_RD_H,   *rL = bfb + O_RD_L;
    bf16 *xH = bfb + O_X_H,    *xL = bfb + O_X_L;
    bf16 *aH = bfb + O_AG_H,   *aL = bfb + O_AG_L;
    bf16 *gH = bfb + O_XG_H,   *gL = bfb + O_XG_L;
    bf16 *eH = bfb + O_XE_H,   *eL = bfb + O_XE_L;

    cudaMemsetAsync(msg, 0, (size_t)NE * 256 * 4, 0);
    cudaMemsetAsync(mH, 0, SZ_E256 * 2, 0);
    cudaMemsetAsync(mL, 0, SZ_E256 * 2, 0);

    featsk<<<(NE * 48 + 255) / 256, 256>>>(x, ea, ei, fH, fL);

#define CONV(src, tot, K, stride, off, Kp, hi, lo) \
    convk<<<(int)(((long long)(tot) + 255) / 256), 256>>>(src, (long long)(tot), K, stride, off, Kp, hi, lo)

    CONV(x, (long long)NN * 128, 128, 128, 0, 128, xH, xL);
    CONV(Wz_w, 4 * 256 * 192, 160, 416, 0, 192, bfb + O_WZ1_H, bfb + O_WZ1_L);
    CONV(Wz_w, 4 * 256 * 256, 256, 416, 160, 256, bfb + O_WZ2_H, bfb + O_WZ2_L);
    CONV(Wr_w, 4 * 256 * 192, 160, 416, 0, 192, bfb + O_WR1_H, bfb + O_WR1_L);
    CONV(Wr_w, 4 * 256 * 256, 256, 416, 160, 256, bfb + O_WR2_H, bfb + O_WR2_L);
    CONV(W_w, 4 * 256 * 192, 160, 160, 0, 192, bfb + O_WW_H, bfb + O_WW_L);
    CONV(U_w, 4 * 256 * 256, 256, 256, 0, 256, bfb + O_UW_H, bfb + O_UW_L);
    CONV(mlp_w, 256 * 128, 128, 384, 0, 128, bfb + O_M1_H, bfb + O_M1_L);
    CONV(mlp_w, 256 * 256, 256, 384, 128, 256, bfb + O_M2_H, bfb + O_M2_L);
    CONV(nc1_w, 512 * 256, 256, 256, 0, 256, bfb + O_N1_H, bfb + O_N1_L);
    CONV(ec1_w, 512 * 512, 512, 512, 0, 512, bfb + O_E1_H, bfb + O_E1_L);

    const int MBE = (NE + 127) / 128;   // 938
    const int MBN = (NN + 127) / 128;   // 469
    const int MBP = (NP + 127) / 128;   // 469

    for (int l = 0; l < 4; ++l) {
        bf16* wz1H = bfb + O_WZ1_H + (size_t)l * 49152;
        bf16* wz1L = bfb + O_WZ1_L + (size_t)l * 49152;
        bf16* wz2H = bfb + O_WZ2_H + (size_t)l * 65536;
        bf16* wz2L = bfb + O_WZ2_L + (size_t)l * 65536;
        bf16* wr1H = bfb + O_WR1_H + (size_t)l * 49152;
        bf16* wr1L = bfb + O_WR1_L + (size_t)l * 49152;
        bf16* wr2H = bfb + O_WR2_H + (size_t)l * 65536;
        bf16* wr2L = bfb + O_WR2_L + (size_t)l * 65536;
        bf16* wwH  = bfb + O_WW_H + (size_t)l * 49152;
        bf16* wwL  = bfb + O_WW_L + (size_t)l * 49152;
        bf16* uwH  = bfb + O_UW_H + (size_t)l * 65536;
        bf16* uwL  = bfb + O_UW_L + (size_t)l * 65536;

        suvk<<<(NE * 64 + 255) / 256, 256>>>(nbr, sH, sL);
        gemm_tc<<<dim3(MBE, 2), 128, SMEM_DYN>>>(
            fH, fL, 192, wz1H, wz1L, sH, sL, 256, wz2H, wz2L,
            Wz_b + (size_t)l * 256, z, NE, 256, 0, nullptr, nullptr, nullptr, nullptr);
        gemm_tc<<<dim3(MBE, 2), 128, SMEM_DYN>>>(
            fH, fL, 192, wr1H, wr1L, mH, mL, 256, wr2H, wr2L,
            Wr_b + (size_t)l * 256, r, NE, 256, 0, nullptr, nullptr, nullptr, nullptr);
        rdashk<<<(NE * 64 + 255) / 256, 256>>>(nbr, rH, rL);
        gemm_tc<<<dim3(MBE, 2), 128, SMEM_DYN>>>(
            fH, fL, 192, wwH, wwL, rH, rL, 256, uwH, uwL,
            U_b + (size_t)l * 256, msg, NE, 256, 1, z, suv, mH, mL);
    }

    cudaMemsetAsync(aggr, 0, (size_t)NN * 256 * 4, 0);
    aggrk<<<(NE * 256 + 255) / 256, 256>>>(ei);
    CONV(aggr, (long long)NN * 256, 256, 256, 0, 256, aH, aL);

    gemm_tc<<<dim3(MBN, 2), 128, SMEM_DYN>>>(
        xH, xL, 128, bfb + O_M1_H, bfb + O_M1_L, aH, aL, 256, bfb + O_M2_H, bfb + O_M2_L,
        mlp_b, xg, NN, 256, 2, nullptr, nullptr, gH, gL);

    gemm_tc<<<dim3(MBN, 4), 128, SMEM_DYN>>>(
        gH, gL, 256, bfb + O_N1_H, bfb + O_N1_L, nullptr, nullptr, 0, nullptr, nullptr,
        nc1_b, h1, NN, 512, 2, nullptr, nullptr, nullptr, nullptr);
    dotk<<<(NN * 32 + 255) / 256, 256>>>(nc2_w, nc2_b, logits, NN);

    xedgek<<<(NP * 64 + 255) / 256, 256>>>(ei, eH, eL);
    gemm_tc<<<dim3(MBP, 4), 128, SMEM_DYN>>>(
        eH, eL, 512, bfb + O_E1_H, bfb + O_E1_L, nullptr, nullptr, 0, nullptr, nullptr,
        ec1_b, h1, NP, 512, 2, nullptr, nullptr, nullptr, nullptr);
    dotk<<<(NP * 32 + 255) / 256, 256>>>(ec2_w, ec2_b, logits + NN, NP);

    soft1k<<<1, 1024>>>();
    soft2k<<<(TLOG + 255) / 256, 256>>>(out);
}

// round 10
// speedup vs baseline: 1.2797x; 1.1084x over previous
#include <cuda_runtime.h>
#include <cuda_bf16.h>
#include <cstdint>
#include <math.h>

#define NN 60000
#define NE 119998
#define NP 59999
#define TLOG (NN + NP)

typedef __nv_bfloat16 bf16;

// ---------------- fp32 scratch --------------------------------------------
__device__ float g_msg  [(size_t)NE * 256];
__device__ float g_suv  [(size_t)NE * 256];
__device__ float g_r    [(size_t)NE * 256];
__device__ float g_z    [(size_t)NE * 256];
__device__ float g_aggr [(size_t)NN * 256];
__device__ float g_xg   [(size_t)NN * 256];
__device__ float g_logits[TLOG];
__device__ float g_red[2];

// ---------------- bf16 hi/lo scratch (one big arena) -----------------------
#define SZ_FEATS ((size_t)NE * 192)
#define SZ_E256  ((size_t)NE * 256)
#define SZ_X     ((size_t)NN * 128)
#define SZ_N256  ((size_t)NN * 256)
#define SZ_XE    ((size_t)NP * 512)

constexpr size_t O_FEATS_H = 0;
constexpr size_t O_FEATS_L = O_FEATS_H + SZ_FEATS;
constexpr size_t O_MSG_H   = O_FEATS_L + SZ_FEATS;
constexpr size_t O_MSG_L   = O_MSG_H + SZ_E256;
constexpr size_t O_SUV_H   = O_MSG_L + SZ_E256;
constexpr size_t O_SUV_L   = O_SUV_H + SZ_E256;
constexpr size_t O_RD_H    = O_SUV_L + SZ_E256;
constexpr size_t O_RD_L    = O_RD_H + SZ_E256;
constexpr size_t O_X_H     = O_RD_L + SZ_E256;
constexpr size_t O_X_L     = O_X_H + SZ_X;
constexpr size_t O_AG_H    = O_X_L + SZ_X;
constexpr size_t O_AG_L    = O_AG_H + SZ_N256;
constexpr size_t O_XG_H    = O_AG_L + SZ_N256;
constexpr size_t O_XG_L    = O_XG_H + SZ_N256;
constexpr size_t O_XE_H    = O_XG_L + SZ_N256;
constexpr size_t O_XE_L    = O_XE_H + SZ_XE;
constexpr size_t O_WZ1_H   = O_XE_L + SZ_XE;
constexpr size_t O_WZ1_L   = O_WZ1_H + 4 * 256 * 192;
constexpr size_t O_WZ2_H   = O_WZ1_L + 4 * 256 * 192;
constexpr size_t O_WZ2_L   = O_WZ2_H + 4 * 256 * 256;
constexpr size_t O_WR1_H   = O_WZ2_L + 4 * 256 * 256;
constexpr size_t O_WR1_L   = O_WR1_H + 4 * 256 * 192;
constexpr size_t O_WR2_H   = O_WR1_L + 4 * 256 * 192;
constexpr size_t O_WR2_L   = O_WR2_H + 4 * 256 * 256;
constexpr size_t O_WW_H    = O_WR2_L + 4 * 256 * 256;
constexpr size_t O_WW_L    = O_WW_H + 4 * 256 * 192;
constexpr size_t O_UW_H    = O_WW_L + 4 * 256 * 192;
constexpr size_t O_UW_L    = O_UW_H + 4 * 256 * 256;
constexpr size_t O_M1_H    = O_UW_L + 4 * 256 * 256;
constexpr size_t O_M1_L    = O_M1_H + 256 * 128;
constexpr size_t O_M2_H    = O_M1_L + 256 * 128;
constexpr size_t O_M2_L    = O_M2_H + 256 * 256;
constexpr size_t O_N1_H    = O_M2_L + 256 * 256;
constexpr size_t O_N1_L    = O_N1_H + 512 * 256;
constexpr size_t O_E1_H    = O_N1_L + 512 * 256;
constexpr size_t O_E1_L    = O_E1_H + 512 * 512;
constexpr size_t BF_TOTAL  = O_E1_L + 512 * 512;

__device__ bf16 g_bf[BF_TOTAL];

// ---------------- helpers --------------------------------------------------
__device__ __forceinline__ uint32_t s2u(const void* p) {
    uint32_t a;
    asm("{ .reg .u64 t; cvta.to.shared.u64 t, %1; cvt.u32.u64 %0, t; }" : "=r"(a) : "l"(p));
    return a;
}

__device__ __forceinline__ void mma16816(float* c, const uint32_t* a, const uint32_t* b) {
    asm volatile(
        "mma.sync.aligned.m16n8k16.row.col.f32.bf16.bf16.f32 "
        "{%0,%1,%2,%3}, {%4,%5,%6,%7}, {%8,%9}, {%0,%1,%2,%3};"
        : "+f"(c[0]), "+f"(c[1]), "+f"(c[2]), "+f"(c[3])
        : "r"(a[0]), "r"(a[1]), "r"(a[2]), "r"(a[3]), "r"(b[0]), "r"(b[1]));
}

__device__ __forceinline__ void ldsm4(uint32_t* r, uint32_t addr) {
    asm volatile("ldmatrix.sync.aligned.m8n8.x4.shared.b16 {%0,%1,%2,%3}, [%4];"
                 : "=r"(r[0]), "=r"(r[1]), "=r"(r[2]), "=r"(r[3]) : "r"(addr));
}

__device__ __forceinline__ void store_hl4(bf16* hp, bf16* lp, float4 v) {
    bf16 h0 = __float2bfloat16(v.x), h1 = __float2bfloat16(v.y);
    bf16 h2 = __float2bfloat16(v.z), h3 = __float2bfloat16(v.w);
    bf16 l0 = __float2bfloat16(v.x - __bfloat162float(h0));
    bf16 l1 = __float2bfloat16(v.y - __bfloat162float(h1));
    bf16 l2 = __float2bfloat16(v.z - __bfloat162float(h2));
    bf16 l3 = __float2bfloat16(v.w - __bfloat162float(h3));
    ((__nv_bfloat162*)hp)[0] = __halves2bfloat162(h0, h1);
    ((__nv_bfloat162*)hp)[1] = __halves2bfloat162(h2, h3);
    ((__nv_bfloat162*)lp)[0] = __halves2bfloat162(l0, l1);
    ((__nv_bfloat162*)lp)[1] = __halves2bfloat162(l2, l3);
}

__device__ __forceinline__ void store_hl2(bf16* hp, bf16* lp, float v0, float v1) {
    bf16 h0 = __float2bfloat16(v0), h1 = __float2bfloat16(v1);
    bf16 l0 = __float2bfloat16(v0 - __bfloat162float(h0));
    bf16 l1 = __float2bfloat16(v1 - __bfloat162float(h1));
    *(__nv_bfloat162*)hp = __halves2bfloat162(h0, h1);
    *(__nv_bfloat162*)lp = __halves2bfloat162(l0, l1);
}

// ---------------- small kernels --------------------------------------------
// feats hi/lo written directly (padded to 192 cols)
__global__ void featsk(const float* __restrict__ x, const float* __restrict__ ea,
                       const int* __restrict__ ei,
                       bf16* __restrict__ fh, bf16* __restrict__ fl) {
    int i = blockIdx.x * blockDim.x + threadIdx.x;
    if (i >= NE * 48) return;
    int e = i / 48;
    int q = i - e * 48;
    float4 v = make_float4(0.f, 0.f, 0.f, 0.f);
    if (q < 32) {
        int t = ei[NE + e];
        v = ((const float4*)x)[(size_t)t * 32 + q];
    } else if (q < 40) {
        v = ((const float4*)ea)[(size_t)e * 8 + (q - 32)];
    }
    size_t o = (size_t)e * 192 + q * 4;
    store_hl4(fh + o, fl + o, v);
}

__global__ void suvk(const int* __restrict__ nbr, bf16* __restrict__ sh, bf16* __restrict__ sl) {
    int i = blockIdx.x * blockDim.x + threadIdx.x;
    if (i >= NE * 64) return;
    int e = i >> 6, q = i & 63;
    const float4* m4 = (const float4*)g_msg;
    float4 acc = make_float4(0.f, 0.f, 0.f, 0.f);
#pragma unroll
    for (int j = 0; j < 3; ++j) {
        int idx = nbr[3 * (size_t)e + j];
        if (idx > 0) {
            float4 v = m4[(size_t)(idx - 1) * 64 + q];
            acc.x += v.x; acc.y += v.y; acc.z += v.z; acc.w += v.w;
        }
    }
    ((float4*)g_suv)[i] = acc;
    size_t o = (size_t)e * 256 + q * 4;
    store_hl4(sh + o, sl + o, acc);
}

__global__ void rdashk(const int* __restrict__ nbr, bf16* __restrict__ rh, bf16* __restrict__ rl) {
    int i = blockIdx.x * blockDim.x + threadIdx.x;
    if (i >= NE * 64) return;
    int e = i >> 6, q = i & 63;
    const float4* m4 = (const float4*)g_msg;
    const float4* r4 = (const float4*)g_r;
    float4 acc = make_float4(0.f, 0.f, 0.f, 0.f);
#pragma unroll
    for (int j = 0; j < 3; ++j) {
        int idx = nbr[3 * (size_t)e + j];
        if (idx > 0) {
            size_t o = (size_t)(idx - 1) * 64 + q;
            float4 g = m4[o];
            float4 rr = r4[o];
            acc.x = fmaf(rr.x, g.x, acc.x);
            acc.y = fmaf(rr.y, g.y, acc.y);
            acc.z = fmaf(rr.z, g.z, acc.z);
            acc.w = fmaf(rr.w, g.w, acc.w);
        }
    }
    size_t o = (size_t)e * 256 + q * 4;
    store_hl4(rh + o, rl + o, acc);
}

__global__ void aggrk(const int* __restrict__ ei) {
    int i = blockIdx.x * blockDim.x + threadIdx.x;
    if (i >= NE * 256) return;
    int e = i >> 8, h = i & 255;
    int t = ei[NE + e];
    atomicAdd(&g_aggr[(size_t)t * 256 + h], g_msg[i]);
}

__global__ void xedgek(const int* __restrict__ ei, bf16* __restrict__ xh, bf16* __restrict__ xl) {
    int i = blockIdx.x * blockDim.x + threadIdx.x;
    if (i >= NP * 64) return;
    int p = i >> 6, q = i & 63;
    int u = ei[2 * p];
    int v = ei[NE + 2 * p];
    const float4* X = (const float4*)g_xg;
    float4 a = X[(size_t)u * 64 + q];
    float4 b = X[(size_t)v * 64 + q];
    size_t o = (size_t)p * 512 + q * 4;
    store_hl4(xh + o, xl + o,
        make_float4(fabsf(a.x - b.x), fabsf(a.y - b.y), fabsf(a.z - b.z), fabsf(a.w - b.w)));
    store_hl4(xh + o + 256, xl + o + 256,
        make_float4(a.x + b.x, a.y + b.y, a.z + b.z, a.w + b.w));
}

// pad-convert fp32 -> bf16 hi/lo
__global__ void convk(const float* __restrict__ src, long long total, int K, int rowStride,
                      int colOff, int Kp, bf16* __restrict__ hi, bf16* __restrict__ lo) {
    long long i = (long long)blockIdx.x * blockDim.x + threadIdx.x;
    if (i >= total) return;
    int k = (int)(i % Kp);
    long long row = i / Kp;
    float v = (k < K) ? src[row * rowStride + colOff + k] : 0.f;
    bf16 h = __float2bfloat16(v);
    hi[i] = h;
    lo[i] = __float2bfloat16(v - __bfloat162float(h));
}

// ---------------- split-bf16 mma.sync GEMM (R6 config, pinned) --------------
// CTA tile 128x128, 8 warps (2x4) of 64x32, K-chunk 32, double buffer, 2 CTA/SM.
// mode 0=sigmoid 1=GRU 2=relu 3=relu-dot->atomicAdd(lgt)
// If B1h2 != null: grid.y is split in half; upper half uses the "2" operand set.
#define KC 32
#define ROWB 80
#define TILEB (128 * ROWB)            // 10240
#define STAGE_B (4 * TILEB)           // 40960
#define SMEM_DYN (2 * STAGE_B)        // 81920 -> 2 CTAs/SM

__global__ void __launch_bounds__(256, 2) gemm_tc(
    const bf16* __restrict__ A1h, const bf16* __restrict__ A1l, int K1p,
    const bf16* __restrict__ B1h, const bf16* __restrict__ B1l,
    const bf16* __restrict__ A2h, const bf16* __restrict__ A2l, int K2p,
    const bf16* __restrict__ B2h, const bf16* __restrict__ B2l,
    const float* __restrict__ bias, float* __restrict__ C, int M, int N, int mode,
    const float* __restrict__ zb, const float* __restrict__ sb,
    bf16* __restrict__ outH, bf16* __restrict__ outL,
    const bf16* __restrict__ A2h2, const bf16* __restrict__ A2l2,
    const bf16* __restrict__ B1h2, const bf16* __restrict__ B1l2,
    const bf16* __restrict__ B2h2, const bf16* __restrict__ B2l2,
    const float* __restrict__ bias2, float* __restrict__ C2,
    const float* __restrict__ w2, float* __restrict__ lgt)
{
    extern __shared__ char dsm[];
    const uint32_t smem_u = s2u(dsm);
    const int tid  = threadIdx.x;
    const int warp = tid >> 5;
    const int lane = tid & 31;
    const int g    = lane >> 2;
    const int t    = lane & 3;
    const int wm   = warp & 1;
    const int wn   = warp >> 1;
    const int m0   = blockIdx.x * 128;

    // select operand set (fused dual-GEMM support)
    const bf16 *cA2h = A2h, *cA2l = A2l, *cB1h = B1h, *cB1l = B1l, *cB2h = B2h, *cB2l = B2l;
    const float* cbias = bias;
    float* cC = C;
    int ytile = blockIdx.y;
    if (B1h2 != nullptr) {
        int half = gridDim.y >> 1;
        if (ytile >= half) {
            ytile -= half;
            cA2h = A2h2; cA2l = A2l2; cB1h = B1h2; cB1l = B1l2;
            cB2h = B2h2; cB2l = B2l2; cbias = bias2; cC = C2;
        }
    }
    const int n0 = ytile * 128;

    const int nch1 = K1p >> 5;
    const int nch2 = cB2h ? (K2p >> 5) : 0;
    const int nch  = nch1 + nch2;

    uint32_t aAddr[4], bAddr[2];
#pragma unroll
    for (int mt = 0; mt < 4; ++mt) {
        int row = wm * 64 + mt * 16 + ((lane >> 3) & 1) * 8 + (lane & 7);
        aAddr[mt] = (uint32_t)(row * ROWB + (lane >> 4) * 16);
    }
#pragma unroll
    for (int np = 0; np < 2; ++np) {
        int row = wn * 32 + np * 16 + ((lane >> 4) & 1) * 8 + (lane & 7);
        bAddr[np] = (uint32_t)(2 * TILEB + row * ROWB + ((lane >> 3) & 1) * 16);
    }

    float acc[4][4][4];
#pragma unroll
    for (int i = 0; i < 4; ++i)
#pragma unroll
        for (int j = 0; j < 4; ++j)
#pragma unroll
            for (int k = 0; k < 4; ++k) acc[i][j][k] = 0.f;

    auto issue = [&](int c) {
        const bf16 *Ah, *Al, *Bh, *Bl;
        int lda, kc;
        if (c < nch1) { Ah = A1h; Al = A1l; Bh = cB1h; Bl = cB1l; lda = K1p; kc = c << 5; }
        else          { Ah = cA2h; Al = cA2l; Bh = cB2h; Bl = cB2l; lda = K2p; kc = (c - nch1) << 5; }
        uint32_t dst0 = smem_u + (uint32_t)((c & 1) * STAGE_B);
#pragma unroll
        for (int it = 0; it < 8; ++it) {
            int u = tid + it * 256;
            int which = u >> 9;
            int rem   = u & 511;
            int row   = rem >> 2;
            int seg   = rem & 3;
            const bf16* sm = (which == 0) ? Ah : (which == 1) ? Al : (which == 2) ? Bh : Bl;
            int sz = 16;
            long long grow;
            if (which < 2) {
                int gm = m0 + row;
                if (gm >= M) { gm = M - 1; sz = 0; }
                grow = gm;
            } else {
                grow = n0 + row;
            }
            const char* src = (const char*)(sm + grow * (long long)lda + kc) + seg * 16;
            uint32_t du = dst0 + (uint32_t)(which * TILEB + row * ROWB + seg * 16);
            asm volatile("cp.async.cg.shared.global [%0], [%1], 16, %2;"
                         :: "r"(du), "l"(src), "r"(sz) : "memory");
        }
        asm volatile("cp.async.commit_group;" ::: "memory");
    };

    issue(0);
    for (int c = 0; c < nch; ++c) {
        if (c + 1 < nch) {
            issue(c + 1);
            asm volatile("cp.async.wait_group 1;" ::: "memory");
        } else {
            asm volatile("cp.async.wait_group 0;" ::: "memory");
        }
        __syncthreads();

        const uint32_t base = smem_u + (uint32_t)((c & 1) * STAGE_B);
#pragma unroll
        for (int ks = 0; ks < 2; ++ks) {
            const uint32_t ko = ks * 32;
            uint32_t ah[4][4], bh[2][4];
#pragma unroll
            for (int mt = 0; mt < 4; ++mt) ldsm4(ah[mt], base + aAddr[mt] + ko);
#pragma unroll
            for (int np = 0; np < 2; ++np) ldsm4(bh[np], base + bAddr[np] + ko);
#pragma unroll
            for (int mt = 0; mt < 4; ++mt)
#pragma unroll
                for (int nt = 0; nt < 4; ++nt)
                    mma16816(acc[mt][nt], ah[mt], &bh[nt >> 1][(nt & 1) * 2]);
            {   // ah x bl
                uint32_t bl[2][4];
#pragma unroll
                for (int np = 0; np < 2; ++np) ldsm4(bl[np], base + bAddr[np] + TILEB + ko);
#pragma unroll
                for (int mt = 0; mt < 4; ++mt)
#pragma unroll
                    for (int nt = 0; nt < 4; ++nt)
                        mma16816(acc[mt][nt], ah[mt], &bl[nt >> 1][(nt & 1) * 2]);
            }
            {   // al x bh
                uint32_t al[4][4];
#pragma unroll
                for (int mt = 0; mt < 4; ++mt) ldsm4(al[mt], base + aAddr[mt] + TILEB + ko);
#pragma unroll
                for (int mt = 0; mt < 4; ++mt)
#pragma unroll
                    for (int nt = 0; nt < 4; ++nt)
                        mma16816(acc[mt][nt], al[mt], &bh[nt >> 1][(nt & 1) * 2]);
            }
        }
        __syncthreads();
    }

    // ---------------- epilogue ----------------
    if (mode == 3) {
        // relu(acc+bias) . w2 -> atomicAdd per row
#pragma unroll
        for (int mt = 0; mt < 4; ++mt) {
            int rg = m0 + wm * 64 + mt * 16 + g;
#pragma unroll
            for (int h = 0; h < 2; ++h) {
                int row = rg + h * 8;
                float s = 0.f;
#pragma unroll
                for (int nt = 0; nt < 4; ++nt) {
                    int cn = n0 + wn * 32 + nt * 8 + 2 * t;
                    float v0 = fmaxf(acc[mt][nt][2 * h]     + cbias[cn],     0.f);
                    float v1 = fmaxf(acc[mt][nt][2 * h + 1] + cbias[cn + 1], 0.f);
                    s = fmaf(v0, w2[cn], s);
                    s = fmaf(v1, w2[cn + 1], s);
                }
                s += __shfl_xor_sync(0xffffffffu, s, 1);
                s += __shfl_xor_sync(0xffffffffu, s, 2);
                if (t == 0 && row < M) atomicAdd(&lgt[row], s);
            }
        }
        return;
    }

#pragma unroll
    for (int mt = 0; mt < 4; ++mt) {
        int rg = m0 + wm * 64 + mt * 16 + g;
#pragma unroll
        for (int nt = 0; nt < 4; ++nt) {
            int cn = n0 + wn * 32 + nt * 8 + 2 * t;
            float b0 = cbias[cn], b1 = cbias[cn + 1];
#pragma unroll
            for (int h = 0; h < 2; ++h) {
                int row = rg + h * 8;
                if (row >= M) continue;
                float v0 = acc[mt][nt][2 * h]     + b0;
                float v1 = acc[mt][nt][2 * h + 1] + b1;
                size_t idx = (size_t)row * N + cn;
                if (mode == 0) {
                    v0 = 1.f / (1.f + expf(-v0));
                    v1 = 1.f / (1.f + expf(-v1));
                } else if (mode == 1) {
                    float z0 = zb[idx], z1 = zb[idx + 1];
                    v0 = (1.f - z0) * sb[idx]     + z0 * tanhf(v0);
                    v1 = (1.f - z1) * sb[idx + 1] + z1 * tanhf(v1);
                } else {
                    v0 = fmaxf(v0, 0.f);
                    v1 = fmaxf(v1, 0.f);
                }
                *(float2*)(cC + idx) = make_float2(v0, v1);
                if (outH) store_hl2(outH + idx, outL + idx, v0, v1);
            }
        }
    }
}

// ---------------- softmax (with per-segment scalar bias) --------------------
__global__ void soft1k(const float* __restrict__ ncb, const float* __restrict__ ecb) {
    __shared__ float sm[1024];
    int tid = threadIdx.x;
    float bn = ncb[0], be = ecb[0];
    float mx = -1e30f;
    for (int i = tid; i < TLOG; i += 1024)
        mx = fmaxf(mx, g_logits[i] + (i < NN ? bn : be));
    sm[tid] = mx;
    __syncthreads();
    for (int s = 512; s > 0; s >>= 1) {
        if (tid < s) sm[tid] = fmaxf(sm[tid], sm[tid + s]);
        __syncthreads();
    }
    float gmax = sm[0];
    __syncthreads();
    float sum = 0.f;
    for (int i = tid; i < TLOG; i += 1024)
        sum += expf(g_logits[i] + (i < NN ? bn : be) - gmax);
    sm[tid] = sum;
    __syncthreads();
    for (int s = 512; s > 0; s >>= 1) {
        if (tid < s) sm[tid] += sm[tid + s];
        __syncthreads();
    }
    if (tid == 0) { g_red[0] = gmax; g_red[1] = sm[0]; }
}

__global__ void soft2k(float* __restrict__ out, const float* __restrict__ ncb,
                       const float* __restrict__ ecb) {
    int i = blockIdx.x * blockDim.x + threadIdx.x;
    if (i < TLOG)
        out[i] = expf(g_logits[i] + (i < NN ? ncb[0] : ecb[0]) - g_red[0]) / g_red[1];
}

// ---------------------------------------------------------------------------
extern "C" void kernel_launch(void* const* d_in, const int* in_sizes, int n_in,
                              void* d_out, int out_size) {
    (void)in_sizes; (void)n_in; (void)out_size;
    const float* x     = (const float*)d_in[0];
    const float* ea    = (const float*)d_in[1];
    const int*   ei    = (const int*)d_in[2];
    const int*   nbr   = (const int*)d_in[3];
    const float* Wz_w  = (const float*)d_in[4];
    const float* Wz_b  = (const float*)d_in[5];
    const float* Wr_w  = (const float*)d_in[6];
    const float* Wr_b  = (const float*)d_in[7];
    const float* W_w   = (const float*)d_in[8];
    const float* U_w   = (const float*)d_in[9];
    const float* U_b   = (const float*)d_in[10];
    const float* mlp_w = (const float*)d_in[11];
    const float* mlp_b = (const float*)d_in[12];
    const float* nc1_w = (const float*)d_in[13];
    const float* nc1_b = (const float*)d_in[14];
    const float* nc2_w = (const float*)d_in[15];
    const float* nc2_b = (const float*)d_in[16];
    const float* ec1_w = (const float*)d_in[17];
    const float* ec1_b = (const float*)d_in[18];
    const float* ec2_w = (const float*)d_in[19];
    const float* ec2_b = (const float*)d_in[20];
    float* out = (float*)d_out;

    float *msg, *suv, *r, *z, *aggr, *xg, *logits;
    bf16* bfb;
    cudaGetSymbolAddress((void**)&msg,    g_msg);
    cudaGetSymbolAddress((void**)&suv,    g_suv);
    cudaGetSymbolAddress((void**)&r,      g_r);
    cudaGetSymbolAddress((void**)&z,      g_z);
    cudaGetSymbolAddress((void**)&aggr,   g_aggr);
    cudaGetSymbolAddress((void**)&xg,     g_xg);
    cudaGetSymbolAddress((void**)&logits, g_logits);
    cudaGetSymbolAddress((void**)&bfb,    g_bf);

    cudaFuncSetAttribute(gemm_tc, cudaFuncAttributeMaxDynamicSharedMemorySize, SMEM_DYN);

    bf16 *fH = bfb + O_FEATS_H, *fL = bfb + O_FEATS_L;
    bf16 *mH = bfb + O_MSG_H,  *mL = bfb + O_MSG_L;
    bf16 *sH = bfb + O_SUV_H,  *sL = bfb + O_SUV_L;
    bf16 *rH = bfb + O_RD_H,   *rL = bfb + O_RD_L;
    bf16 *xH = bfb + O_X_H,    *xL = bfb + O_X_L;
    bf16 *aH = bfb + O_AG_H,   *aL = bfb + O_AG_L;
    bf16 *gH = bfb + O_XG_H,   *gL = bfb + O_XG_L;
    bf16 *eH = bfb + O_XE_H,   *eL = bfb + O_XE_L;

    cudaMemsetAsync(msg, 0, (size_t)NE * 256 * 4, 0);
    cudaMemsetAsync(mH, 0, SZ_E256 * 2, 0);
    cudaMemsetAsync(mL, 0, SZ_E256 * 2, 0);

    featsk<<<(NE * 48 + 255) / 256, 256>>>(x, ea, ei, fH, fL);

#define CONV(src, tot, K, stride, off, Kp, hi, lo) \
    convk<<<(int)(((long long)(tot) + 255) / 256), 256>>>(src, (long long)(tot), K, stride, off, Kp, hi, lo)

    CONV(x, (long long)NN * 128, 128, 128, 0, 128, xH, xL);
    CONV(Wz_w, 4 * 256 * 192, 160, 416, 0, 192, bfb + O_WZ1_H, bfb + O_WZ1_L);
    CONV(Wz_w, 4 * 256 * 256, 256, 416, 160, 256, bfb + O_WZ2_H, bfb + O_WZ2_L);
    CONV(Wr_w, 4 * 256 * 192, 160, 416, 0, 192, bfb + O_WR1_H, bfb + O_WR1_L);
    CONV(Wr_w, 4 * 256 * 256, 256, 416, 160, 256, bfb + O_WR2_H, bfb + O_WR2_L);
    CONV(W_w, 4 * 256 * 192, 160, 160, 0, 192, bfb + O_WW_H, bfb + O_WW_L);
    CONV(U_w, 4 * 256 * 256, 256, 256, 0, 256, bfb + O_UW_H, bfb + O_UW_L);
    CONV(mlp_w, 256 * 128, 128, 384, 0, 128, bfb + O_M1_H, bfb + O_M1_L);
    CONV(mlp_w, 256 * 256, 256, 384, 128, 256, bfb + O_M2_H, bfb + O_M2_L);
    CONV(nc1_w, 512 * 256, 256, 256, 0, 256, bfb + O_N1_H, bfb + O_N1_L);
    CONV(ec1_w, 512 * 512, 512, 512, 0, 512, bfb + O_E1_H, bfb + O_E1_L);

    const int MBE = (NE + 127) / 128;   // 938
    const int MBN = (NN + 127) / 128;   // 469
    const int MBP = (NP + 127) / 128;   // 469

#define NUL8 nullptr, nullptr, nullptr, nullptr, nullptr, nullptr, nullptr, nullptr

    for (int l = 0; l < 4; ++l) {
        bf16* wz1H = bfb + O_WZ1_H + (size_t)l * 49152;
        bf16* wz1L = bfb + O_WZ1_L + (size_t)l * 49152;
        bf16* wz2H = bfb + O_WZ2_H + (size_t)l * 65536;
        bf16* wz2L = bfb + O_WZ2_L + (size_t)l * 65536;
        bf16* wr1H = bfb + O_WR1_H + (size_t)l * 49152;
        bf16* wr1L = bfb + O_WR1_L + (size_t)l * 49152;
        bf16* wr2H = bfb + O_WR2_H + (size_t)l * 65536;
        bf16* wr2L = bfb + O_WR2_L + (size_t)l * 65536;
        bf16* wwH  = bfb + O_WW_H + (size_t)l * 49152;
        bf16* wwL  = bfb + O_WW_L + (size_t)l * 49152;
        bf16* uwH  = bfb + O_UW_H + (size_t)l * 65536;
        bf16* uwL  = bfb + O_UW_L + (size_t)l * 65536;

        suvk<<<(NE * 64 + 255) / 256, 256>>>(nbr, sH, sL);
        // fused z + r GEMM: y<2 -> z (A2=suv, Wz), y>=2 -> r (A2=msg, Wr)
        gemm_tc<<<dim3(MBE, 4), 256, SMEM_DYN>>>(
            fH, fL, 192, wz1H, wz1L, sH, sL, 256, wz2H, wz2L,
            Wz_b + (size_t)l * 256, z, NE, 256, 0, nullptr, nullptr, nullptr, nullptr,
            mH, mL, wr1H, wr1L, wr2H, wr2L, Wr_b + (size_t)l * 256, r,
            nullptr, nullptr);
        rdashk<<<(NE * 64 + 255) / 256, 256>>>(nbr, rH, rL);
        gemm_tc<<<dim3(MBE, 2), 256, SMEM_DYN>>>(
            fH, fL, 192, wwH, wwL, rH, rL, 256, uwH, uwL,
            U_b + (size_t)l * 256, msg, NE, 256, 1, z, suv, mH, mL,
            NUL8, nullptr, nullptr);
    }

    cudaMemsetAsync(aggr, 0, (size_t)NN * 256 * 4, 0);
    aggrk<<<(NE * 256 + 255) / 256, 256>>>(ei);
    CONV(aggr, (long long)NN * 256, 256, 256, 0, 256, aH, aL);

    gemm_tc<<<dim3(MBN, 2), 256, SMEM_DYN>>>(
        xH, xL, 128, bfb + O_M1_H, bfb + O_M1_L, aH, aL, 256, bfb + O_M2_H, bfb + O_M2_L,
        mlp_b, xg, NN, 256, 2, nullptr, nullptr, gH, gL,
        NUL8, nullptr, nullptr);

    cudaMemsetAsync(logits, 0, TLOG * 4, 0);

    // node head: fused nc1+relu+nc2 dot
    gemm_tc<<<dim3(MBN, 4), 256, SMEM_DYN>>>(
        gH, gL, 256, bfb + O_N1_H, bfb + O_N1_L, nullptr, nullptr, 0, nullptr, nullptr,
        nc1_b, nullptr, NN, 512, 3, nullptr, nullptr, nullptr, nullptr,
        NUL8, nc2_w, logits);

    xedgek<<<(NP * 64 + 255) / 256, 256>>>(ei, eH, eL);
    // edge head: fused ec1+relu+ec2 dot
    gemm_tc<<<dim3(MBP, 4), 256, SMEM_DYN>>>(
        eH, eL, 512, bfb + O_E1_H, bfb + O_E1_L, nullptr, nullptr, 0, nullptr, nullptr,
        ec1_b, nullptr, NP, 512, 3, nullptr, nullptr, nullptr, nullptr,
        NUL8, ec2_w, logits + NN);

    soft1k<<<1, 1024>>>(nc2_b, ec2_b);
    soft2k<<<(TLOG + 255) / 256, 256>>>(out, nc2_b, ec2_b);
}

// round 11
// speedup vs baseline: 1.2905x; 1.0085x over previous
#include <cuda_runtime.h>
#include <cuda_bf16.h>
#include <cstdint>
#include <math.h>

#define NN 60000
#define NE 119998
#define NP 59999
#define TLOG (NN + NP)

typedef __nv_bfloat16 bf16;

// ---------------- fp32 scratch --------------------------------------------
__device__ float g_r    [(size_t)NE * 256];
__device__ float g_z    [(size_t)NE * 256];
__device__ float g_aggr [(size_t)NN * 256];
__device__ float g_xg   [(size_t)NN * 256];
__device__ float g_logits[TLOG];
__device__ float g_red[2];

// ---------------- bf16 hi/lo scratch (one big arena) -----------------------
#define SZ_FEATS ((size_t)NE * 192)
#define SZ_E256  ((size_t)NE * 256)
#define SZ_X     ((size_t)NN * 128)
#define SZ_N256  ((size_t)NN * 256)
#define SZ_XE    ((size_t)NP * 512)

constexpr size_t O_FEATS_H = 0;
constexpr size_t O_FEATS_L = O_FEATS_H + SZ_FEATS;
constexpr size_t O_MSG_H   = O_FEATS_L + SZ_FEATS;
constexpr size_t O_MSG_L   = O_MSG_H + SZ_E256;
constexpr size_t O_SUV_H   = O_MSG_L + SZ_E256;
constexpr size_t O_SUV_L   = O_SUV_H + SZ_E256;
constexpr size_t O_RD_H    = O_SUV_L + SZ_E256;
constexpr size_t O_RD_L    = O_RD_H + SZ_E256;
constexpr size_t O_X_H     = O_RD_L + SZ_E256;
constexpr size_t O_X_L     = O_X_H + SZ_X;
constexpr size_t O_AG_H    = O_X_L + SZ_X;
constexpr size_t O_AG_L    = O_AG_H + SZ_N256;
constexpr size_t O_XG_H    = O_AG_L + SZ_N256;
constexpr size_t O_XG_L    = O_XG_H + SZ_N256;
constexpr size_t O_XE_H    = O_XG_L + SZ_N256;
constexpr size_t O_XE_L    = O_XE_H + SZ_XE;
constexpr size_t O_WZ1_H   = O_XE_L + SZ_XE;
constexpr size_t O_WZ1_L   = O_WZ1_H + 4 * 256 * 192;
constexpr size_t O_WZ2_H   = O_WZ1_L + 4 * 256 * 192;
constexpr size_t O_WZ2_L   = O_WZ2_H + 4 * 256 * 256;
constexpr size_t O_WR1_H   = O_WZ2_L + 4 * 256 * 256;
constexpr size_t O_WR1_L   = O_WR1_H + 4 * 256 * 192;
constexpr size_t O_WR2_H   = O_WR1_L + 4 * 256 * 192;
constexpr size_t O_WR2_L   = O_WR2_H + 4 * 256 * 256;
constexpr size_t O_WW_H    = O_WR2_L + 4 * 256 * 256;
constexpr size_t O_WW_L    = O_WW_H + 4 * 256 * 192;
constexpr size_t O_UW_H    = O_WW_L + 4 * 256 * 192;
constexpr size_t O_UW_L    = O_UW_H + 4 * 256 * 256;
constexpr size_t O_M1_H    = O_UW_L + 4 * 256 * 256;
constexpr size_t O_M1_L    = O_M1_H + 256 * 128;
constexpr size_t O_M2_H    = O_M1_L + 256 * 128;
constexpr size_t O_M2_L    = O_M2_H + 256 * 256;
constexpr size_t O_N1_H    = O_M2_L + 256 * 256;
constexpr size_t O_N1_L    = O_N1_H + 512 * 256;
constexpr size_t O_E1_H    = O_N1_L + 512 * 256;
constexpr size_t O_E1_L    = O_E1_H + 512 * 512;
constexpr size_t BF_TOTAL  = O_E1_L + 512 * 512;

__device__ bf16 g_bf[BF_TOTAL];

// ---------------- helpers --------------------------------------------------
__device__ __forceinline__ uint32_t s2u(const void* p) {
    uint32_t a;
    asm("{ .reg .u64 t; cvta.to.shared.u64 t, %1; cvt.u32.u64 %0, t; }" : "=r"(a) : "l"(p));
    return a;
}

__device__ __forceinline__ void mma16816(float* c, const uint32_t* a, const uint32_t* b) {
    asm volatile(
        "mma.sync.aligned.m16n8k16.row.col.f32.bf16.bf16.f32 "
        "{%0,%1,%2,%3}, {%4,%5,%6,%7}, {%8,%9}, {%0,%1,%2,%3};"
        : "+f"(c[0]), "+f"(c[1]), "+f"(c[2]), "+f"(c[3])
        : "r"(a[0]), "r"(a[1]), "r"(a[2]), "r"(a[3]), "r"(b[0]), "r"(b[1]));
}

__device__ __forceinline__ void ldsm4(uint32_t* r, uint32_t addr) {
    asm volatile("ldmatrix.sync.aligned.m8n8.x4.shared.b16 {%0,%1,%2,%3}, [%4];"
                 : "=r"(r[0]), "=r"(r[1]), "=r"(r[2]), "=r"(r[3]) : "r"(addr));
}

__device__ __forceinline__ void store_hl4(bf16* hp, bf16* lp, float4 v) {
    bf16 h0 = __float2bfloat16(v.x), h1 = __float2bfloat16(v.y);
    bf16 h2 = __float2bfloat16(v.z), h3 = __float2bfloat16(v.w);
    bf16 l0 = __float2bfloat16(v.x - __bfloat162float(h0));
    bf16 l1 = __float2bfloat16(v.y - __bfloat162float(h1));
    bf16 l2 = __float2bfloat16(v.z - __bfloat162float(h2));
    bf16 l3 = __float2bfloat16(v.w - __bfloat162float(h3));
    ((__nv_bfloat162*)hp)[0] = __halves2bfloat162(h0, h1);
    ((__nv_bfloat162*)hp)[1] = __halves2bfloat162(h2, h3);
    ((__nv_bfloat162*)lp)[0] = __halves2bfloat162(l0, l1);
    ((__nv_bfloat162*)lp)[1] = __halves2bfloat162(l2, l3);
}

__device__ __forceinline__ void store_hl2(bf16* hp, bf16* lp, float v0, float v1) {
    bf16 h0 = __float2bfloat16(v0), h1 = __float2bfloat16(v1);
    bf16 l0 = __float2bfloat16(v0 - __bfloat162float(h0));
    bf16 l1 = __float2bfloat16(v1 - __bfloat162float(h1));
    *(__nv_bfloat162*)hp = __halves2bfloat162(h0, h1);
    *(__nv_bfloat162*)lp = __halves2bfloat162(l0, l1);
}

// load 4 consecutive values from hi/lo pair
__device__ __forceinline__ float4 load_hl4(const bf16* hp, const bf16* lp) {
    uint2 vh = *(const uint2*)hp;
    uint2 vl = *(const uint2*)lp;
    float2 h0 = __bfloat1622float2(*(__nv_bfloat162*)&vh.x);
    float2 h1 = __bfloat1622float2(*(__nv_bfloat162*)&vh.y);
    float2 l0 = __bfloat1622float2(*(__nv_bfloat162*)&vl.x);
    float2 l1 = __bfloat1622float2(*(__nv_bfloat162*)&vl.y);
    return make_float4(h0.x + l0.x, h0.y + l0.y, h1.x + l1.x, h1.y + l1.y);
}

// ---------------- small kernels --------------------------------------------
__global__ void featsk(const float* __restrict__ x, const float* __restrict__ ea,
                       const int* __restrict__ ei,
                       bf16* __restrict__ fh, bf16* __restrict__ fl) {
    int i = blockIdx.x * blockDim.x + threadIdx.x;
    if (i >= NE * 48) return;
    int e = i / 48;
    int q = i - e * 48;
    float4 v = make_float4(0.f, 0.f, 0.f, 0.f);
    if (q < 32) {
        int t = ei[NE + e];
        v = ((const float4*)x)[(size_t)t * 32 + q];
    } else if (q < 40) {
        v = ((const float4*)ea)[(size_t)e * 8 + (q - 32)];
    }
    size_t o = (size_t)e * 192 + q * 4;
    store_hl4(fh + o, fl + o, v);
}

__global__ void suvk(const int* __restrict__ nbr, const bf16* __restrict__ mh,
                     const bf16* __restrict__ ml,
                     bf16* __restrict__ sh, bf16* __restrict__ sl) {
    int i = blockIdx.x * blockDim.x + threadIdx.x;
    if (i >= NE * 64) return;
    int e = i >> 6, q = i & 63;
    float4 acc = make_float4(0.f, 0.f, 0.f, 0.f);
#pragma unroll
    for (int j = 0; j < 3; ++j) {
        int idx = nbr[3 * (size_t)e + j];
        if (idx > 0) {
            size_t o = (size_t)(idx - 1) * 256 + q * 4;
            float4 v = load_hl4(mh + o, ml + o);
            acc.x += v.x; acc.y += v.y; acc.z += v.z; acc.w += v.w;
        }
    }
    size_t o = (size_t)e * 256 + q * 4;
    store_hl4(sh + o, sl + o, acc);
}

__global__ void rdashk(const int* __restrict__ nbr, const bf16* __restrict__ mh,
                       const bf16* __restrict__ ml,
                       bf16* __restrict__ rh, bf16* __restrict__ rl) {
    int i = blockIdx.x * blockDim.x + threadIdx.x;
    if (i >= NE * 64) return;
    int e = i >> 6, q = i & 63;
    const float4* r4 = (const float4*)g_r;
    float4 acc = make_float4(0.f, 0.f, 0.f, 0.f);
#pragma unroll
    for (int j = 0; j < 3; ++j) {
        int idx = nbr[3 * (size_t)e + j];
        if (idx > 0) {
            size_t o = (size_t)(idx - 1) * 256 + q * 4;
            float4 g = load_hl4(mh + o, ml + o);
            float4 rr = r4[(size_t)(idx - 1) * 64 + q];
            acc.x = fmaf(rr.x, g.x, acc.x);
            acc.y = fmaf(rr.y, g.y, acc.y);
            acc.z = fmaf(rr.z, g.z, acc.z);
            acc.w = fmaf(rr.w, g.w, acc.w);
        }
    }
    size_t o = (size_t)e * 256 + q * 4;
    store_hl4(rh + o, rl + o, acc);
}

__global__ void aggrk(const int* __restrict__ ei, const bf16* __restrict__ mh,
                      const bf16* __restrict__ ml) {
    int i = blockIdx.x * blockDim.x + threadIdx.x;
    if (i >= NE * 256) return;
    int e = i >> 8, h = i & 255;
    int t = ei[NE + e];
    float v = __bfloat162float(mh[i]) + __bfloat162float(ml[i]);
    atomicAdd(&g_aggr[(size_t)t * 256 + h], v);
}

__global__ void xedgek(const int* __restrict__ ei, bf16* __restrict__ xh, bf16* __restrict__ xl) {
    int i = blockIdx.x * blockDim.x + threadIdx.x;
    if (i >= NP * 64) return;
    int p = i >> 6, q = i & 63;
    int u = ei[2 * p];
    int v = ei[NE + 2 * p];
    const float4* X = (const float4*)g_xg;
    float4 a = X[(size_t)u * 64 + q];
    float4 b = X[(size_t)v * 64 + q];
    size_t o = (size_t)p * 512 + q * 4;
    store_hl4(xh + o, xl + o,
        make_float4(fabsf(a.x - b.x), fabsf(a.y - b.y), fabsf(a.z - b.z), fabsf(a.w - b.w)));
    store_hl4(xh + o + 256, xl + o + 256,
        make_float4(a.x + b.x, a.y + b.y, a.z + b.z, a.w + b.w));
}

// pad-convert fp32 -> bf16 hi/lo
__global__ void convk(const float* __restrict__ src, long long total, int K, int rowStride,
                      int colOff, int Kp, bf16* __restrict__ hi, bf16* __restrict__ lo) {
    long long i = (long long)blockIdx.x * blockDim.x + threadIdx.x;
    if (i >= total) return;
    int k = (int)(i % Kp);
    long long row = i / Kp;
    float v = (k < K) ? src[row * rowStride + colOff + k] : 0.f;
    bf16 h = __float2bfloat16(v);
    hi[i] = h;
    lo[i] = __float2bfloat16(v - __bfloat162float(h));
}

// ---------------- split-bf16 mma.sync GEMM (R6 config, pinned) --------------
// CTA tile 128x128, 8 warps (2x4) of 64x32, K-chunk 32, double buffer, 2 CTA/SM.
// mode 0=sigmoid 1=GRU 2=relu 3=relu-dot->atomicAdd(lgt)
#define KC 32
#define ROWB 80
#define TILEB (128 * ROWB)            // 10240
#define STAGE_B (4 * TILEB)           // 40960
#define SMEM_DYN (2 * STAGE_B)        // 81920 -> 2 CTAs/SM

__global__ void __launch_bounds__(256, 2) gemm_tc(
    const bf16* __restrict__ A1h, const bf16* __restrict__ A1l, int K1p,
    const bf16* __restrict__ B1h, const bf16* __restrict__ B1l,
    const bf16* __restrict__ A2h, const bf16* __restrict__ A2l, int K2p,
    const bf16* __restrict__ B2h, const bf16* __restrict__ B2l,
    const float* __restrict__ bias, float* __restrict__ C, int M, int N, int mode,
    const float* __restrict__ zb, const bf16* __restrict__ sbH, const bf16* __restrict__ sbL,
    bf16* __restrict__ outH, bf16* __restrict__ outL,
    const bf16* __restrict__ A2h2, const bf16* __restrict__ A2l2,
    const bf16* __restrict__ B1h2, const bf16* __restrict__ B1l2,
    const bf16* __restrict__ B2h2, const bf16* __restrict__ B2l2,
    const float* __restrict__ bias2, float* __restrict__ C2,
    const float* __restrict__ w2, float* __restrict__ lgt)
{
    extern __shared__ char dsm[];
    const uint32_t smem_u = s2u(dsm);
    const int tid  = threadIdx.x;
    const int warp = tid >> 5;
    const int lane = tid & 31;
    const int g    = lane >> 2;
    const int t    = lane & 3;
    const int wm   = warp & 1;
    const int wn   = warp >> 1;
    const int m0   = blockIdx.x * 128;

    const bf16 *cA2h = A2h, *cA2l = A2l, *cB1h = B1h, *cB1l = B1l, *cB2h = B2h, *cB2l = B2l;
    const float* cbias = bias;
    float* cC = C;
    int ytile = blockIdx.y;
    if (B1h2 != nullptr) {
        int half = gridDim.y >> 1;
        if (ytile >= half) {
            ytile -= half;
            cA2h = A2h2; cA2l = A2l2; cB1h = B1h2; cB1l = B1l2;
            cB2h = B2h2; cB2l = B2l2; cbias = bias2; cC = C2;
        }
    }
    const int n0 = ytile * 128;

    const int nch1 = K1p >> 5;
    const int nch2 = cB2h ? (K2p >> 5) : 0;
    const int nch  = nch1 + nch2;

    uint32_t aAddr[4], bAddr[2];
#pragma unroll
    for (int mt = 0; mt < 4; ++mt) {
        int row = wm * 64 + mt * 16 + ((lane >> 3) & 1) * 8 + (lane & 7);
        aAddr[mt] = (uint32_t)(row * ROWB + (lane >> 4) * 16);
    }
#pragma unroll
    for (int np = 0; np < 2; ++np) {
        int row = wn * 32 + np * 16 + ((lane >> 4) & 1) * 8 + (lane & 7);
        bAddr[np] = (uint32_t)(2 * TILEB + row * ROWB + ((lane >> 3) & 1) * 16);
    }

    float acc[4][4][4];
#pragma unroll
    for (int i = 0; i < 4; ++i)
#pragma unroll
        for (int j = 0; j < 4; ++j)
#pragma unroll
            for (int k = 0; k < 4; ++k) acc[i][j][k] = 0.f;

    auto issue = [&](int c) {
        const bf16 *Ah, *Al, *Bh, *Bl;
        int lda, kc;
        if (c < nch1) { Ah = A1h; Al = A1l; Bh = cB1h; Bl = cB1l; lda = K1p; kc = c << 5; }
        else          { Ah = cA2h; Al = cA2l; Bh = cB2h; Bl = cB2l; lda = K2p; kc = (c - nch1) << 5; }
        uint32_t dst0 = smem_u + (uint32_t)((c & 1) * STAGE_B);
#pragma unroll
        for (int it = 0; it < 8; ++it) {
            int u = tid + it * 256;
            int which = u >> 9;
            int rem   = u & 511;
            int row   = rem >> 2;
            int seg   = rem & 3;
            const bf16* sm = (which == 0) ? Ah : (which == 1) ? Al : (which == 2) ? Bh : Bl;
            int sz = 16;
            long long grow;
            if (which < 2) {
                int gm = m0 + row;
                if (gm >= M) { gm = M - 1; sz = 0; }
                grow = gm;
            } else {
                grow = n0 + row;
            }
            const char* src = (const char*)(sm + grow * (long long)lda + kc) + seg * 16;
            uint32_t du = dst0 + (uint32_t)(which * TILEB + row * ROWB + seg * 16);
            asm volatile("cp.async.cg.shared.global [%0], [%1], 16, %2;"
                         :: "r"(du), "l"(src), "r"(sz) : "memory");
        }
        asm volatile("cp.async.commit_group;" ::: "memory");
    };

    issue(0);
    for (int c = 0; c < nch; ++c) {
        if (c + 1 < nch) {
            issue(c + 1);
            asm volatile("cp.async.wait_group 1;" ::: "memory");
        } else {
            asm volatile("cp.async.wait_group 0;" ::: "memory");
        }
        __syncthreads();

        const uint32_t base = smem_u + (uint32_t)((c & 1) * STAGE_B);
#pragma unroll
        for (int ks = 0; ks < 2; ++ks) {
            const uint32_t ko = ks * 32;
            uint32_t ah[4][4], bh[2][4];
#pragma unroll
            for (int mt = 0; mt < 4; ++mt) ldsm4(ah[mt], base + aAddr[mt] + ko);
#pragma unroll
            for (int np = 0; np < 2; ++np) ldsm4(bh[np], base + bAddr[np] + ko);
#pragma unroll
            for (int mt = 0; mt < 4; ++mt)
#pragma unroll
                for (int nt = 0; nt < 4; ++nt)
                    mma16816(acc[mt][nt], ah[mt], &bh[nt >> 1][(nt & 1) * 2]);
            {   // ah x bl
                uint32_t bl[2][4];
#pragma unroll
                for (int np = 0; np < 2; ++np) ldsm4(bl[np], base + bAddr[np] + TILEB + ko);
#pragma unroll
                for (int mt = 0; mt < 4; ++mt)
#pragma unroll
                    for (int nt = 0; nt < 4; ++nt)
                        mma16816(acc[mt][nt], ah[mt], &bl[nt >> 1][(nt & 1) * 2]);
            }
            {   // al x bh
                uint32_t al[4][4];
#pragma unroll
                for (int mt = 0; mt < 4; ++mt) ldsm4(al[mt], base + aAddr[mt] + TILEB + ko);
#pragma unroll
                for (int mt = 0; mt < 4; ++mt)
#pragma unroll
                    for (int nt = 0; nt < 4; ++nt)
                        mma16816(acc[mt][nt], al[mt], &bh[nt >> 1][(nt & 1) * 2]);
            }
        }
        __syncthreads();
    }

    // ---------------- epilogue ----------------
    if (mode == 3) {
#pragma unroll
        for (int mt = 0; mt < 4; ++mt) {
            int rg = m0 + wm * 64 + mt * 16 + g;
#pragma unroll
            for (int h = 0; h < 2; ++h) {
                int row = rg + h * 8;
                float s = 0.f;
#pragma unroll
                for (int nt = 0; nt < 4; ++nt) {
                    int cn = n0 + wn * 32 + nt * 8 + 2 * t;
                    float v0 = fmaxf(acc[mt][nt][2 * h]     + cbias[cn],     0.f);
                    float v1 = fmaxf(acc[mt][nt][2 * h + 1] + cbias[cn + 1], 0.f);
                    s = fmaf(v0, w2[cn], s);
                    s = fmaf(v1, w2[cn + 1], s);
                }
                s += __shfl_xor_sync(0xffffffffu, s, 1);
                s += __shfl_xor_sync(0xffffffffu, s, 2);
                if (t == 0 && row < M) atomicAdd(&lgt[row], s);
            }
        }
        return;
    }

#pragma unroll
    for (int mt = 0; mt < 4; ++mt) {
        int rg = m0 + wm * 64 + mt * 16 + g;
#pragma unroll
        for (int nt = 0; nt < 4; ++nt) {
            int cn = n0 + wn * 32 + nt * 8 + 2 * t;
            float b0 = cbias[cn], b1 = cbias[cn + 1];
#pragma unroll
            for (int h = 0; h < 2; ++h) {
                int row = rg + h * 8;
                if (row >= M) continue;
                float v0 = acc[mt][nt][2 * h]     + b0;
                float v1 = acc[mt][nt][2 * h + 1] + b1;
                size_t idx = (size_t)row * N + cn;
                if (mode == 0) {
                    v0 = 1.f / (1.f + expf(-v0));
                    v1 = 1.f / (1.f + expf(-v1));
                } else if (mode == 1) {
                    float z0 = zb[idx], z1 = zb[idx + 1];
                    __nv_bfloat162 sh2 = *(const __nv_bfloat162*)(sbH + idx);
                    __nv_bfloat162 sl2 = *(const __nv_bfloat162*)(sbL + idx);
                    float s0 = __bfloat162float(sh2.x) + __bfloat162float(sl2.x);
                    float s1 = __bfloat162float(sh2.y) + __bfloat162float(sl2.y);
                    v0 = (1.f - z0) * s0 + z0 * tanhf(v0);
                    v1 = (1.f - z1) * s1 + z1 * tanhf(v1);
                } else {
                    v0 = fmaxf(v0, 0.f);
                    v1 = fmaxf(v1, 0.f);
                }
                if (cC) *(float2*)(cC + idx) = make_float2(v0, v1);
                if (outH) store_hl2(outH + idx, outL + idx, v0, v1);
            }
        }
    }
}

// ---------------- softmax (with per-segment scalar bias) --------------------
__global__ void soft1k(const float* __restrict__ ncb, const float* __restrict__ ecb) {
    __shared__ float sm[1024];
    int tid = threadIdx.x;
    float bn = ncb[0], be = ecb[0];
    float mx = -1e30f;
    for (int i = tid; i < TLOG; i += 1024)
        mx = fmaxf(mx, g_logits[i] + (i < NN ? bn : be));
    sm[tid] = mx;
    __syncthreads();
    for (int s = 512; s > 0; s >>= 1) {
        if (tid < s) sm[tid] = fmaxf(sm[tid], sm[tid + s]);
        __syncthreads();
    }
    float gmax = sm[0];
    __syncthreads();
    float sum = 0.f;
    for (int i = tid; i < TLOG; i += 1024)
        sum += expf(g_logits[i] + (i < NN ? bn : be) - gmax);
    sm[tid] = sum;
    __syncthreads();
    for (int s = 512; s > 0; s >>= 1) {
        if (tid < s) sm[tid] += sm[tid + s];
        __syncthreads();
    }
    if (tid == 0) { g_red[0] = gmax; g_red[1] = sm[0]; }
}

__global__ void soft2k(float* __restrict__ out, const float* __restrict__ ncb,
                       const float* __restrict__ ecb) {
    int i = blockIdx.x * blockDim.x + threadIdx.x;
    if (i < TLOG)
        out[i] = expf(g_logits[i] + (i < NN ? ncb[0] : ecb[0]) - g_red[0]) / g_red[1];
}

// ---------------------------------------------------------------------------
extern "C" void kernel_launch(void* const* d_in, const int* in_sizes, int n_in,
                              void* d_out, int out_size) {
    (void)in_sizes; (void)n_in; (void)out_size;
    const float* x     = (const float*)d_in[0];
    const float* ea    = (const float*)d_in[1];
    const int*   ei    = (const int*)d_in[2];
    const int*   nbr   = (const int*)d_in[3];
    const float* Wz_w  = (const float*)d_in[4];
    const float* Wz_b  = (const float*)d_in[5];
    const float* Wr_w  = (const float*)d_in[6];
    const float* Wr_b  = (const float*)d_in[7];
    const float* W_w   = (const float*)d_in[8];
    const float* U_w   = (const float*)d_in[9];
    const float* U_b   = (const float*)d_in[10];
    const float* mlp_w = (const float*)d_in[11];
    const float* mlp_b = (const float*)d_in[12];
    const float* nc1_w = (const float*)d_in[13];
    const float* nc1_b = (const float*)d_in[14];
    const float* nc2_w = (const float*)d_in[15];
    const float* nc2_b = (const float*)d_in[16];
    const float* ec1_w = (const float*)d_in[17];
    const float* ec1_b = (const float*)d_in[18];
    const float* ec2_w = (const float*)d_in[19];
    const float* ec2_b = (const float*)d_in[20];
    float* out = (float*)d_out;

    float *r, *z, *aggr, *xg, *logits;
    bf16* bfb;
    cudaGetSymbolAddress((void**)&r,      g_r);
    cudaGetSymbolAddress((void**)&z,      g_z);
    cudaGetSymbolAddress((void**)&aggr,   g_aggr);
    cudaGetSymbolAddress((void**)&xg,     g_xg);
    cudaGetSymbolAddress((void**)&logits, g_logits);
    cudaGetSymbolAddress((void**)&bfb,    g_bf);

    cudaFuncSetAttribute(gemm_tc, cudaFuncAttributeMaxDynamicSharedMemorySize, SMEM_DYN);

    // one auxiliary stream + events for captured fork/join (created once)
    static cudaStream_t sB = nullptr;
    static cudaEvent_t ev1 = nullptr, ev2 = nullptr;
    if (sB == nullptr) {
        cudaStreamCreate(&sB);
        cudaEventCreateWithFlags(&ev1, cudaEventDisableTiming);
        cudaEventCreateWithFlags(&ev2, cudaEventDisableTiming);
    }

    bf16 *fH = bfb + O_FEATS_H, *fL = bfb + O_FEATS_L;
    bf16 *mH = bfb + O_MSG_H,  *mL = bfb + O_MSG_L;
    bf16 *sH = bfb + O_SUV_H,  *sL = bfb + O_SUV_L;
    bf16 *rH = bfb + O_RD_H,   *rL = bfb + O_RD_L;
    bf16 *xH = bfb + O_X_H,    *xL = bfb + O_X_L;
    bf16 *aH = bfb + O_AG_H,   *aL = bfb + O_AG_L;
    bf16 *gH = bfb + O_XG_H,   *gL = bfb + O_XG_L;
    bf16 *eH = bfb + O_XE_H,   *eL = bfb + O_XE_L;

    cudaMemsetAsync(mH, 0, SZ_E256 * 2, 0);
    cudaMemsetAsync(mL, 0, SZ_E256 * 2, 0);

    featsk<<<(NE * 48 + 255) / 256, 256>>>(x, ea, ei, fH, fL);

#define CONV(src, tot, K, stride, off, Kp, hi, lo) \
    convk<<<(int)(((long long)(tot) + 255) / 256), 256>>>(src, (long long)(tot), K, stride, off, Kp, hi, lo)

    CONV(x, (long long)NN * 128, 128, 128, 0, 128, xH, xL);
    CONV(Wz_w, 4 * 256 * 192, 160, 416, 0, 192, bfb + O_WZ1_H, bfb + O_WZ1_L);
    CONV(Wz_w, 4 * 256 * 256, 256, 416, 160, 256, bfb + O_WZ2_H, bfb + O_WZ2_L);
    CONV(Wr_w, 4 * 256 * 192, 160, 416, 0, 192, bfb + O_WR1_H, bfb + O_WR1_L);
    CONV(Wr_w, 4 * 256 * 256, 256, 416, 160, 256, bfb + O_WR2_H, bfb + O_WR2_L);
    CONV(W_w, 4 * 256 * 192, 160, 160, 0, 192, bfb + O_WW_H, bfb + O_WW_L);
    CONV(U_w, 4 * 256 * 256, 256, 256, 0, 256, bfb + O_UW_H, bfb + O_UW_L);
    CONV(mlp_w, 256 * 128, 128, 384, 0, 128, bfb + O_M1_H, bfb + O_M1_L);
    CONV(mlp_w, 256 * 256, 256, 384, 128, 256, bfb + O_M2_H, bfb + O_M2_L);
    CONV(nc1_w, 512 * 256, 256, 256, 0, 256, bfb + O_N1_H, bfb + O_N1_L);
    CONV(ec1_w, 512 * 512, 512, 512, 0, 512, bfb + O_E1_H, bfb + O_E1_L);

    const int MBE = (NE + 127) / 128;   // 938
    const int MBN = (NN + 127) / 128;   // 469
    const int MBP = (NP + 127) / 128;   // 469

#define NUL8 nullptr, nullptr, nullptr, nullptr, nullptr, nullptr, nullptr, nullptr

    for (int l = 0; l < 4; ++l) {
        bf16* wz1H = bfb + O_WZ1_H + (size_t)l * 49152;
        bf16* wz1L = bfb + O_WZ1_L + (size_t)l * 49152;
        bf16* wz2H = bfb + O_WZ2_H + (size_t)l * 65536;
        bf16* wz2L = bfb + O_WZ2_L + (size_t)l * 65536;
        bf16* wr1H = bfb + O_WR1_H + (size_t)l * 49152;
        bf16* wr1L = bfb + O_WR1_L + (size_t)l * 49152;
        bf16* wr2H = bfb + O_WR2_H + (size_t)l * 65536;
        bf16* wr2L = bfb + O_WR2_L + (size_t)l * 65536;
        bf16* wwH  = bfb + O_WW_H + (size_t)l * 49152;
        bf16* wwL  = bfb + O_WW_L + (size_t)l * 49152;
        bf16* uwH  = bfb + O_UW_H + (size_t)l * 65536;
        bf16* uwL  = bfb + O_UW_L + (size_t)l * 65536;

        suvk<<<(NE * 64 + 255) / 256, 256>>>(nbr, mH, mL, sH, sL);

        // r = sigmoid([feats|msg] @ Wr^T + b)   (stream 0)
        gemm_tc<<<dim3(MBE, 2), 256, SMEM_DYN>>>(
            fH, fL, 192, wr1H, wr1L, mH, mL, 256, wr2H, wr2L,
            Wr_b + (size_t)l * 256, r, NE, 256, 0, nullptr, nullptr, nullptr,
            nullptr, nullptr, NUL8, nullptr, nullptr);
        cudaEventRecord(ev1, 0);

        // z = sigmoid([feats|suv] @ Wz^T + b)   (stream 0, overlaps rdashk)
        gemm_tc<<<dim3(MBE, 2), 256, SMEM_DYN>>>(
            fH, fL, 192, wz1H, wz1L, sH, sL, 256, wz2H, wz2L,
            Wz_b + (size_t)l * 256, z, NE, 256, 0, nullptr, nullptr, nullptr,
            nullptr, nullptr, NUL8, nullptr, nullptr);

        // rdashk on stream B after r is done
        cudaStreamWaitEvent(sB, ev1, 0);
        rdashk<<<(NE * 64 + 255) / 256, 256, 0, sB>>>(nbr, mH, mL, rH, rL);
        cudaEventRecord(ev2, sB);
        cudaStreamWaitEvent(0, ev2, 0);

        // msg = (1-z)*suv + z*tanh(feats@W^T + rdash@U^T + b)  -> hi/lo only
        gemm_tc<<<dim3(MBE, 2), 256, SMEM_DYN>>>(
            fH, fL, 192, wwH, wwL, rH, rL, 256, uwH, uwL,
            U_b + (size_t)l * 256, nullptr, NE, 256, 1, z, sH, sL, mH, mL,
            NUL8, nullptr, nullptr);
    }

    cudaMemsetAsync(aggr, 0, (size_t)NN * 256 * 4, 0);
    aggrk<<<(NE * 256 + 255) / 256, 256>>>(ei, mH, mL);
    CONV(aggr, (long long)NN * 256, 256, 256, 0, 256, aH, aL);

    cudaMemsetAsync(logits, 0, TLOG * 4, 0);

    // xg = relu([x|aggr] @ mlp^T + b)
    gemm_tc<<<dim3(MBN, 2), 256, SMEM_DYN>>>(
        xH, xL, 128, bfb + O_M1_H, bfb + O_M1_L, aH, aL, 256, bfb + O_M2_H, bfb + O_M2_L,
        mlp_b, xg, NN, 256, 2, nullptr, nullptr, nullptr, gH, gL,
        NUL8, nullptr, nullptr);
    cudaEventRecord(ev1, 0);

    // edge path on stream B: xedgek -> edge head
    cudaStreamWaitEvent(sB, ev1, 0);
    xedgek<<<(NP * 64 + 255) / 256, 256, 0, sB>>>(ei, eH, eL);
    gemm_tc<<<dim3(MBP, 4), 256, SMEM_DYN, sB>>>(
        eH, eL, 512, bfb + O_E1_H, bfb + O_E1_L, nullptr, nullptr, 0, nullptr, nullptr,
        ec1_b, nullptr, NP, 512, 3, nullptr, nullptr, nullptr, nullptr, nullptr,
        NUL8, ec2_w, logits + NN);
    cudaEventRecord(ev2, sB);

    // node head on stream 0 (concurrent with edge path)
    gemm_tc<<<dim3(MBN, 4), 256, SMEM_DYN>>>(
        gH, gL, 256, bfb + O_N1_H, bfb + O_N1_L, nullptr, nullptr, 0, nullptr, nullptr,
        nc1_b, nullptr, NN, 512, 3, nullptr, nullptr, nullptr, nullptr, nullptr,
        NUL8, nc2_w, logits);

    cudaStreamWaitEvent(0, ev2, 0);
    soft1k<<<1, 1024>>>(nc2_b, ec2_b);
    soft2k<<<(TLOG + 255) / 256, 256>>>(out, nc2_b, ec2_b);
}

// round 12
// speedup vs baseline: 1.5100x; 1.1701x over previous
#include <cuda_runtime.h>
#include <cuda_bf16.h>
#include <cstdint>
#include <math.h>

#define NN 60000
#define NE 119998
#define NP 59999
#define TLOG (NN + NP)

typedef __nv_bfloat16 bf16;

// ---------------- fp32 scratch --------------------------------------------
__device__ float g_r    [(size_t)NE * 256];
__device__ float g_z    [(size_t)NE * 256];
__device__ float g_aggr [(size_t)NN * 256];
__device__ float g_xg   [(size_t)NN * 256];
__device__ float g_logits[TLOG];
__device__ float g_red[2];

// ---------------- bf16 hi/lo scratch (one big arena) -----------------------
#define SZ_FEATS ((size_t)NE * 192)
#define SZ_E256  ((size_t)NE * 256)
#define SZ_X     ((size_t)NN * 128)
#define SZ_N256  ((size_t)NN * 256)
#define SZ_XE    ((size_t)NP * 512)

constexpr size_t O_FEATS_H = 0;
constexpr size_t O_FEATS_L = O_FEATS_H + SZ_FEATS;
constexpr size_t O_MSG_H   = O_FEATS_L + SZ_FEATS;
constexpr size_t O_MSG_L   = O_MSG_H + SZ_E256;
constexpr size_t O_SUV_H   = O_MSG_L + SZ_E256;
constexpr size_t O_SUV_L   = O_SUV_H + SZ_E256;
constexpr size_t O_RD_H    = O_SUV_L + SZ_E256;
constexpr size_t O_RD_L    = O_RD_H + SZ_E256;
constexpr size_t O_X_H     = O_RD_L + SZ_E256;
constexpr size_t O_X_L     = O_X_H + SZ_X;
constexpr size_t O_AG_H    = O_X_L + SZ_X;
constexpr size_t O_AG_L    = O_AG_H + SZ_N256;
constexpr size_t O_XG_H    = O_AG_L + SZ_N256;
constexpr size_t O_XG_L    = O_XG_H + SZ_N256;
constexpr size_t O_XE_H    = O_XG_L + SZ_N256;
constexpr size_t O_XE_L    = O_XE_H + SZ_XE;
constexpr size_t O_WZ1_H   = O_XE_L + SZ_XE;
constexpr size_t O_WZ1_L   = O_WZ1_H + 4 * 256 * 192;
constexpr size_t O_WZ2_H   = O_WZ1_L + 4 * 256 * 192;
constexpr size_t O_WZ2_L   = O_WZ2_H + 4 * 256 * 256;
constexpr size_t O_WR1_H   = O_WZ2_L + 4 * 256 * 256;
constexpr size_t O_WR1_L   = O_WR1_H + 4 * 256 * 192;
constexpr size_t O_WR2_H   = O_WR1_L + 4 * 256 * 192;
constexpr size_t O_WR2_L   = O_WR2_H + 4 * 256 * 256;
constexpr size_t O_WW_H    = O_WR2_L + 4 * 256 * 256;
constexpr size_t O_WW_L    = O_WW_H + 4 * 256 * 192;
constexpr size_t O_UW_H    = O_WW_L + 4 * 256 * 192;
constexpr size_t O_UW_L    = O_UW_H + 4 * 256 * 256;
constexpr size_t O_M1_H    = O_UW_L + 4 * 256 * 256;
constexpr size_t O_M1_L    = O_M1_H + 256 * 128;
constexpr size_t O_M2_H    = O_M1_L + 256 * 128;
constexpr size_t O_M2_L    = O_M2_H + 256 * 256;
constexpr size_t O_N1_H    = O_M2_L + 256 * 256;
constexpr size_t O_N1_L    = O_N1_H + 512 * 256;
constexpr size_t O_E1_H    = O_N1_L + 512 * 256;
constexpr size_t O_E1_L    = O_E1_H + 512 * 512;
constexpr size_t BF_TOTAL  = O_E1_L + 512 * 512;

__device__ bf16 g_bf[BF_TOTAL];

// ---------------- helpers --------------------------------------------------
__device__ __forceinline__ uint32_t s2u(const void* p) {
    uint32_t a;
    asm("{ .reg .u64 t; cvta.to.shared.u64 t, %1; cvt.u32.u64 %0, t; }" : "=r"(a) : "l"(p));
    return a;
}

__device__ __forceinline__ void mma16816(float* c, const uint32_t* a, const uint32_t* b) {
    asm volatile(
        "mma.sync.aligned.m16n8k16.row.col.f32.bf16.bf16.f32 "
        "{%0,%1,%2,%3}, {%4,%5,%6,%7}, {%8,%9}, {%0,%1,%2,%3};"
        : "+f"(c[0]), "+f"(c[1]), "+f"(c[2]), "+f"(c[3])
        : "r"(a[0]), "r"(a[1]), "r"(a[2]), "r"(a[3]), "r"(b[0]), "r"(b[1]));
}

__device__ __forceinline__ void ldsm4(uint32_t* r, uint32_t addr) {
    asm volatile("ldmatrix.sync.aligned.m8n8.x4.shared.b16 {%0,%1,%2,%3}, [%4];"
                 : "=r"(r[0]), "=r"(r[1]), "=r"(r[2]), "=r"(r[3]) : "r"(addr));
}

__device__ __forceinline__ void store_hl4(bf16* hp, bf16* lp, float4 v) {
    bf16 h0 = __float2bfloat16(v.x), h1 = __float2bfloat16(v.y);
    bf16 h2 = __float2bfloat16(v.z), h3 = __float2bfloat16(v.w);
    bf16 l0 = __float2bfloat16(v.x - __bfloat162float(h0));
    bf16 l1 = __float2bfloat16(v.y - __bfloat162float(h1));
    bf16 l2 = __float2bfloat16(v.z - __bfloat162float(h2));
    bf16 l3 = __float2bfloat16(v.w - __bfloat162float(h3));
    ((__nv_bfloat162*)hp)[0] = __halves2bfloat162(h0, h1);
    ((__nv_bfloat162*)hp)[1] = __halves2bfloat162(h2, h3);
    ((__nv_bfloat162*)lp)[0] = __halves2bfloat162(l0, l1);
    ((__nv_bfloat162*)lp)[1] = __halves2bfloat162(l2, l3);
}

__device__ __forceinline__ void store_hl2(bf16* hp, bf16* lp, float v0, float v1) {
    bf16 h0 = __float2bfloat16(v0), h1 = __float2bfloat16(v1);
    bf16 l0 = __float2bfloat16(v0 - __bfloat162float(h0));
    bf16 l1 = __float2bfloat16(v1 - __bfloat162float(h1));
    *(__nv_bfloat162*)hp = __halves2bfloat162(h0, h1);
    *(__nv_bfloat162*)lp = __halves2bfloat162(l0, l1);
}

__device__ __forceinline__ float4 load_hl4(const bf16* hp, const bf16* lp) {
    uint2 vh = *(const uint2*)hp;
    uint2 vl = *(const uint2*)lp;
    float2 h0 = __bfloat1622float2(*(__nv_bfloat162*)&vh.x);
    float2 h1 = __bfloat1622float2(*(__nv_bfloat162*)&vh.y);
    float2 l0 = __bfloat1622float2(*(__nv_bfloat162*)&vl.x);
    float2 l1 = __bfloat1622float2(*(__nv_bfloat162*)&vl.y);
    return make_float4(h0.x + l0.x, h0.y + l0.y, h1.x + l1.x, h1.y + l1.y);
}

// ---------------- small kernels --------------------------------------------
__global__ void featsk(const float* __restrict__ x, const float* __restrict__ ea,
                       const int* __restrict__ ei,
                       bf16* __restrict__ fh, bf16* __restrict__ fl) {
    int i = blockIdx.x * blockDim.x + threadIdx.x;
    if (i >= NE * 48) return;
    int e = i / 48;
    int q = i - e * 48;
    float4 v = make_float4(0.f, 0.f, 0.f, 0.f);
    if (q < 32) {
        int t = ei[NE + e];
        v = ((const float4*)x)[(size_t)t * 32 + q];
    } else if (q < 40) {
        v = ((const float4*)ea)[(size_t)e * 8 + (q - 32)];
    }
    size_t o = (size_t)e * 192 + q * 4;
    store_hl4(fh + o, fl + o, v);
}

__global__ void suvk(const int* __restrict__ nbr, const bf16* __restrict__ mh,
                     const bf16* __restrict__ ml,
                     bf16* __restrict__ sh, bf16* __restrict__ sl) {
    int i = blockIdx.x * blockDim.x + threadIdx.x;
    if (i >= NE * 64) return;
    int e = i >> 6, q = i & 63;
    float4 acc = make_float4(0.f, 0.f, 0.f, 0.f);
#pragma unroll
    for (int j = 0; j < 3; ++j) {
        int idx = nbr[3 * (size_t)e + j];
        if (idx > 0) {
            size_t o = (size_t)(idx - 1) * 256 + q * 4;
            float4 v = load_hl4(mh + o, ml + o);
            acc.x += v.x; acc.y += v.y; acc.z += v.z; acc.w += v.w;
        }
    }
    size_t o = (size_t)e * 256 + q * 4;
    store_hl4(sh + o, sl + o, acc);
}

__global__ void rdashk(const int* __restrict__ nbr, const bf16* __restrict__ mh,
                       const bf16* __restrict__ ml,
                       bf16* __restrict__ rh, bf16* __restrict__ rl) {
    int i = blockIdx.x * blockDim.x + threadIdx.x;
    if (i >= NE * 64) return;
    int e = i >> 6, q = i & 63;
    const float4* r4 = (const float4*)g_r;
    float4 acc = make_float4(0.f, 0.f, 0.f, 0.f);
#pragma unroll
    for (int j = 0; j < 3; ++j) {
        int idx = nbr[3 * (size_t)e + j];
        if (idx > 0) {
            size_t o = (size_t)(idx - 1) * 256 + q * 4;
            float4 g = load_hl4(mh + o, ml + o);
            float4 rr = r4[(size_t)(idx - 1) * 64 + q];
            acc.x = fmaf(rr.x, g.x, acc.x);
            acc.y = fmaf(rr.y, g.y, acc.y);
            acc.z = fmaf(rr.z, g.z, acc.z);
            acc.w = fmaf(rr.w, g.w, acc.w);
        }
    }
    size_t o = (size_t)e * 256 + q * 4;
    store_hl4(rh + o, rl + o, acc);
}

__global__ void xedgek(const int* __restrict__ ei, bf16* __restrict__ xh, bf16* __restrict__ xl) {
    int i = blockIdx.x * blockDim.x + threadIdx.x;
    if (i >= NP * 64) return;
    int p = i >> 6, q = i & 63;
    int u = ei[2 * p];
    int v = ei[NE + 2 * p];
    const float4* X = (const float4*)g_xg;
    float4 a = X[(size_t)u * 64 + q];
    float4 b = X[(size_t)v * 64 + q];
    size_t o = (size_t)p * 512 + q * 4;
    store_hl4(xh + o, xl + o,
        make_float4(fabsf(a.x - b.x), fabsf(a.y - b.y), fabsf(a.z - b.z), fabsf(a.w - b.w)));
    store_hl4(xh + o + 256, xl + o + 256,
        make_float4(a.x + b.x, a.y + b.y, a.z + b.z, a.w + b.w));
}

// pad-convert fp32 -> bf16 hi/lo
__global__ void convk(const float* __restrict__ src, long long total, int K, int rowStride,
                      int colOff, int Kp, bf16* __restrict__ hi, bf16* __restrict__ lo) {
    long long i = (long long)blockIdx.x * blockDim.x + threadIdx.x;
    if (i >= total) return;
    int k = (int)(i % Kp);
    long long row = i / Kp;
    float v = (k < K) ? src[row * rowStride + colOff + k] : 0.f;
    bf16 h = __float2bfloat16(v);
    hi[i] = h;
    lo[i] = __float2bfloat16(v - __bfloat162float(h));
}

// ---------------- split-bf16 mma.sync GEMM (R6 config, pinned) --------------
// CTA tile 128x128, 8 warps (2x4) of 64x32, K-chunk 32, double buffer, 2 CTA/SM.
// mode 0=sigmoid 1=GRU 2=relu 3=relu-dot->atomicAdd(lgt) 4=GRU->aggr atomics
//   mode 4: w2 = (const float*)(ei+NE)  (tgt index array), lgt = aggr
#define KC 32
#define ROWB 80
#define TILEB (128 * ROWB)            // 10240
#define STAGE_B (4 * TILEB)           // 40960
#define SMEM_DYN (2 * STAGE_B)        // 81920 -> 2 CTAs/SM

__global__ void __launch_bounds__(256, 2) gemm_tc(
    const bf16* __restrict__ A1h, const bf16* __restrict__ A1l, int K1p,
    const bf16* __restrict__ B1h, const bf16* __restrict__ B1l,
    const bf16* __restrict__ A2h, const bf16* __restrict__ A2l, int K2p,
    const bf16* __restrict__ B2h, const bf16* __restrict__ B2l,
    const float* __restrict__ bias, float* __restrict__ C, int M, int N, int mode,
    const float* __restrict__ zb, const bf16* __restrict__ sbH, const bf16* __restrict__ sbL,
    bf16* __restrict__ outH, bf16* __restrict__ outL,
    const float* __restrict__ w2, float* __restrict__ lgt)
{
    extern __shared__ char dsm[];
    const uint32_t smem_u = s2u(dsm);
    const int tid  = threadIdx.x;
    const int warp = tid >> 5;
    const int lane = tid & 31;
    const int g    = lane >> 2;
    const int t    = lane & 3;
    const int wm   = warp & 1;
    const int wn   = warp >> 1;
    const int m0   = blockIdx.x * 128;
    const int n0   = blockIdx.y * 128;

    const int nch1 = K1p >> 5;
    const int nch2 = B2h ? (K2p >> 5) : 0;
    const int nch  = nch1 + nch2;

    uint32_t aAddr[4], bAddr[2];
#pragma unroll
    for (int mt = 0; mt < 4; ++mt) {
        int row = wm * 64 + mt * 16 + ((lane >> 3) & 1) * 8 + (lane & 7);
        aAddr[mt] = (uint32_t)(row * ROWB + (lane >> 4) * 16);
    }
#pragma unroll
    for (int np = 0; np < 2; ++np) {
        int row = wn * 32 + np * 16 + ((lane >> 4) & 1) * 8 + (lane & 7);
        bAddr[np] = (uint32_t)(2 * TILEB + row * ROWB + ((lane >> 3) & 1) * 16);
    }

    float acc[4][4][4];
#pragma unroll
    for (int i = 0; i < 4; ++i)
#pragma unroll
        for (int j = 0; j < 4; ++j)
#pragma unroll
            for (int k = 0; k < 4; ++k) acc[i][j][k] = 0.f;

    auto issue = [&](int c) {
        const bf16 *Ah, *Al, *Bh, *Bl;
        int lda, kc;
        if (c < nch1) { Ah = A1h; Al = A1l; Bh = B1h; Bl = B1l; lda = K1p; kc = c << 5; }
        else          { Ah = A2h; Al = A2l; Bh = B2h; Bl = B2l; lda = K2p; kc = (c - nch1) << 5; }
        uint32_t dst0 = smem_u + (uint32_t)((c & 1) * STAGE_B);
#pragma unroll
        for (int it = 0; it < 8; ++it) {
            int u = tid + it * 256;
            int which = u >> 9;
            int rem   = u & 511;
            int row   = rem >> 2;
            int seg   = rem & 3;
            const bf16* sm = (which == 0) ? Ah : (which == 1) ? Al : (which == 2) ? Bh : Bl;
            int sz = 16;
            long long grow;
            if (which < 2) {
                int gm = m0 + row;
                if (gm >= M) { gm = M - 1; sz = 0; }
                grow = gm;
            } else {
                grow = n0 + row;
            }
            const char* src = (const char*)(sm + grow * (long long)lda + kc) + seg * 16;
            uint32_t du = dst0 + (uint32_t)(which * TILEB + row * ROWB + seg * 16);
            asm volatile("cp.async.cg.shared.global [%0], [%1], 16, %2;"
                         :: "r"(du), "l"(src), "r"(sz) : "memory");
        }
        asm volatile("cp.async.commit_group;" ::: "memory");
    };

    issue(0);
    for (int c = 0; c < nch; ++c) {
        if (c + 1 < nch) {
            issue(c + 1);
            asm volatile("cp.async.wait_group 1;" ::: "memory");
        } else {
            asm volatile("cp.async.wait_group 0;" ::: "memory");
        }
        __syncthreads();

        const uint32_t base = smem_u + (uint32_t)((c & 1) * STAGE_B);
#pragma unroll
        for (int ks = 0; ks < 2; ++ks) {
            const uint32_t ko = ks * 32;
            uint32_t ah[4][4], bh[2][4];
#pragma unroll
            for (int mt = 0; mt < 4; ++mt) ldsm4(ah[mt], base + aAddr[mt] + ko);
#pragma unroll
            for (int np = 0; np < 2; ++np) ldsm4(bh[np], base + bAddr[np] + ko);
#pragma unroll
            for (int mt = 0; mt < 4; ++mt)
#pragma unroll
                for (int nt = 0; nt < 4; ++nt)
                    mma16816(acc[mt][nt], ah[mt], &bh[nt >> 1][(nt & 1) * 2]);
            {   // ah x bl
                uint32_t bl[2][4];
#pragma unroll
                for (int np = 0; np < 2; ++np) ldsm4(bl[np], base + bAddr[np] + TILEB + ko);
#pragma unroll
                for (int mt = 0; mt < 4; ++mt)
#pragma unroll
                    for (int nt = 0; nt < 4; ++nt)
                        mma16816(acc[mt][nt], ah[mt], &bl[nt >> 1][(nt & 1) * 2]);
            }
            {   // al x bh
                uint32_t al[4][4];
#pragma unroll
                for (int mt = 0; mt < 4; ++mt) ldsm4(al[mt], base + aAddr[mt] + TILEB + ko);
#pragma unroll
                for (int mt = 0; mt < 4; ++mt)
#pragma unroll
                    for (int nt = 0; nt < 4; ++nt)
                        mma16816(acc[mt][nt], al[mt], &bh[nt >> 1][(nt & 1) * 2]);
            }
        }
        __syncthreads();
    }

    // ---------------- epilogue ----------------
    if (mode == 3) {
#pragma unroll
        for (int mt = 0; mt < 4; ++mt) {
            int rg = m0 + wm * 64 + mt * 16 + g;
#pragma unroll
            for (int h = 0; h < 2; ++h) {
                int row = rg + h * 8;
                float s = 0.f;
#pragma unroll
                for (int nt = 0; nt < 4; ++nt) {
                    int cn = n0 + wn * 32 + nt * 8 + 2 * t;
                    float v0 = fmaxf(acc[mt][nt][2 * h]     + bias[cn],     0.f);
                    float v1 = fmaxf(acc[mt][nt][2 * h + 1] + bias[cn + 1], 0.f);
                    s = fmaf(v0, w2[cn], s);
                    s = fmaf(v1, w2[cn + 1], s);
                }
                s += __shfl_xor_sync(0xffffffffu, s, 1);
                s += __shfl_xor_sync(0xffffffffu, s, 2);
                if (t == 0 && row < M) atomicAdd(&lgt[row], s);
            }
        }
        return;
    }

#pragma unroll
    for (int mt = 0; mt < 4; ++mt) {
        int rg = m0 + wm * 64 + mt * 16 + g;
#pragma unroll
        for (int nt = 0; nt < 4; ++nt) {
            int cn = n0 + wn * 32 + nt * 8 + 2 * t;
            float b0 = bias[cn], b1 = bias[cn + 1];
#pragma unroll
            for (int h = 0; h < 2; ++h) {
                int row = rg + h * 8;
                if (row >= M) continue;
                float v0 = acc[mt][nt][2 * h]     + b0;
                float v1 = acc[mt][nt][2 * h + 1] + b1;
                size_t idx = (size_t)row * N + cn;
                if (mode == 0) {
                    v0 = 1.f / (1.f + expf(-v0));
                    v1 = 1.f / (1.f + expf(-v1));
                } else if (mode == 2) {
                    v0 = fmaxf(v0, 0.f);
                    v1 = fmaxf(v1, 0.f);
                } else {  // 1 or 4: GRU combine
                    float z0 = zb[idx], z1 = zb[idx + 1];
                    float s0 = 0.f, s1 = 0.f;
                    if (sbH) {
                        __nv_bfloat162 sh2 = *(const __nv_bfloat162*)(sbH + idx);
                        __nv_bfloat162 sl2 = *(const __nv_bfloat162*)(sbL + idx);
                        s0 = __bfloat162float(sh2.x) + __bfloat162float(sl2.x);
                        s1 = __bfloat162float(sh2.y) + __bfloat162float(sl2.y);
                    }
                    v0 = (1.f - z0) * s0 + z0 * tanhf(v0);
                    v1 = (1.f - z1) * s1 + z1 * tanhf(v1);
                }
                if (mode == 4) {
                    const int* tgt = (const int*)w2;
                    int tr = tgt[row];
                    atomicAdd(&lgt[(size_t)tr * 256 + cn], v0);
                    atomicAdd(&lgt[(size_t)tr * 256 + cn + 1], v1);
                } else {
                    if (C) *(float2*)(C + idx) = make_float2(v0, v1);
                    if (outH) store_hl2(outH + idx, outL + idx, v0, v1);
                }
            }
        }
    }
}

// ---------------- softmax (with per-segment scalar bias) --------------------
__global__ void soft1k(const float* __restrict__ ncb, const float* __restrict__ ecb) {
    __shared__ float sm[1024];
    int tid = threadIdx.x;
    float bn = ncb[0], be = ecb[0];
    float mx = -1e30f;
    for (int i = tid; i < TLOG; i += 1024)
        mx = fmaxf(mx, g_logits[i] + (i < NN ? bn : be));
    sm[tid] = mx;
    __syncthreads();
    for (int s = 512; s > 0; s >>= 1) {
        if (tid < s) sm[tid] = fmaxf(sm[tid], sm[tid + s]);
        __syncthreads();
    }
    float gmax = sm[0];
    __syncthreads();
    float sum = 0.f;
    for (int i = tid; i < TLOG; i += 1024)
        sum += expf(g_logits[i] + (i < NN ? bn : be) - gmax);
    sm[tid] = sum;
    __syncthreads();
    for (int s = 512; s > 0; s >>= 1) {
        if (tid < s) sm[tid] += sm[tid + s];
        __syncthreads();
    }
    if (tid == 0) { g_red[0] = gmax; g_red[1] = sm[0]; }
}

__global__ void soft2k(float* __restrict__ out, const float* __restrict__ ncb,
                       const float* __restrict__ ecb) {
    int i = blockIdx.x * blockDim.x + threadIdx.x;
    if (i < TLOG)
        out[i] = expf(g_logits[i] + (i < NN ? ncb[0] : ecb[0]) - g_red[0]) / g_red[1];
}

// ---------------------------------------------------------------------------
extern "C" void kernel_launch(void* const* d_in, const int* in_sizes, int n_in,
                              void* d_out, int out_size) {
    (void)in_sizes; (void)n_in; (void)out_size;
    const float* x     = (const float*)d_in[0];
    const float* ea    = (const float*)d_in[1];
    const int*   ei    = (const int*)d_in[2];
    const int*   nbr   = (const int*)d_in[3];
    const float* Wz_w  = (const float*)d_in[4];
    const float* Wz_b  = (const float*)d_in[5];
    const float* Wr_w  = (const float*)d_in[6];
    const float* Wr_b  = (const float*)d_in[7];
    const float* W_w   = (const float*)d_in[8];
    const float* U_w   = (const float*)d_in[9];
    const float* U_b   = (const float*)d_in[10];
    const float* mlp_w = (const float*)d_in[11];
    const float* mlp_b = (const float*)d_in[12];
    const float* nc1_w = (const float*)d_in[13];
    const float* nc1_b = (const float*)d_in[14];
    const float* nc2_w = (const float*)d_in[15];
    const float* nc2_b = (const float*)d_in[16];
    const float* ec1_w = (const float*)d_in[17];
    const float* ec1_b = (const float*)d_in[18];
    const float* ec2_w = (const float*)d_in[19];
    const float* ec2_b = (const float*)d_in[20];
    float* out = (float*)d_out;

    float *r, *z, *aggr, *xg, *logits;
    bf16* bfb;
    cudaGetSymbolAddress((void**)&r,      g_r);
    cudaGetSymbolAddress((void**)&z,      g_z);
    cudaGetSymbolAddress((void**)&aggr,   g_aggr);
    cudaGetSymbolAddress((void**)&xg,     g_xg);
    cudaGetSymbolAddress((void**)&logits, g_logits);
    cudaGetSymbolAddress((void**)&bfb,    g_bf);

    cudaFuncSetAttribute(gemm_tc, cudaFuncAttributeMaxDynamicSharedMemorySize, SMEM_DYN);

    // auxiliary stream + events for captured fork/join (created once)
    static cudaStream_t sB = nullptr;
    static cudaEvent_t evA = nullptr, evB = nullptr, evC = nullptr, evD = nullptr;
    if (sB == nullptr) {
        cudaStreamCreate(&sB);
        cudaEventCreateWithFlags(&evA, cudaEventDisableTiming);
        cudaEventCreateWithFlags(&evB, cudaEventDisableTiming);
        cudaEventCreateWithFlags(&evC, cudaEventDisableTiming);
        cudaEventCreateWithFlags(&evD, cudaEventDisableTiming);
    }

    bf16 *fH = bfb + O_FEATS_H, *fL = bfb + O_FEATS_L;
    bf16 *mH = bfb + O_MSG_H,  *mL = bfb + O_MSG_L;
    bf16 *sH = bfb + O_SUV_H,  *sL = bfb + O_SUV_L;
    bf16 *rH = bfb + O_RD_H,   *rL = bfb + O_RD_L;
    bf16 *xH = bfb + O_X_H,    *xL = bfb + O_X_L;
    bf16 *aH = bfb + O_AG_H,   *aL = bfb + O_AG_L;
    bf16 *gH = bfb + O_XG_H,   *gL = bfb + O_XG_L;
    bf16 *eH = bfb + O_XE_H,   *eL = bfb + O_XE_L;

    featsk<<<(NE * 48 + 255) / 256, 256>>>(x, ea, ei, fH, fL);

#define CONV(src, tot, K, stride, off, Kp, hi, lo) \
    convk<<<(int)(((long long)(tot) + 255) / 256), 256>>>(src, (long long)(tot), K, stride, off, Kp, hi, lo)

    CONV(x, (long long)NN * 128, 128, 128, 0, 128, xH, xL);
    CONV(Wz_w, 4 * 256 * 192, 160, 416, 0, 192, bfb + O_WZ1_H, bfb + O_WZ1_L);
    CONV(Wz_w, 4 * 256 * 256, 256, 416, 160, 256, bfb + O_WZ2_H, bfb + O_WZ2_L);
    CONV(Wr_w, 4 * 256 * 192, 160, 416, 0, 192, bfb + O_WR1_H, bfb + O_WR1_L);
    CONV(Wr_w, 4 * 256 * 256, 256, 416, 160, 256, bfb + O_WR2_H, bfb + O_WR2_L);
    CONV(W_w, 4 * 256 * 192, 160, 160, 0, 192, bfb + O_WW_H, bfb + O_WW_L);
    CONV(U_w, 4 * 256 * 256, 256, 256, 0, 256, bfb + O_UW_H, bfb + O_UW_L);
    CONV(mlp_w, 256 * 128, 128, 384, 0, 128, bfb + O_M1_H, bfb + O_M1_L);
    CONV(mlp_w, 256 * 256, 256, 384, 128, 256, bfb + O_M2_H, bfb + O_M2_L);
    CONV(nc1_w, 512 * 256, 256, 256, 0, 256, bfb + O_N1_H, bfb + O_N1_L);
    CONV(ec1_w, 512 * 512, 512, 512, 0, 512, bfb + O_E1_H, bfb + O_E1_L);

    // aggr must be zero before last-layer fused segment-sum
    cudaMemsetAsync(aggr, 0, (size_t)NN * 256 * 4, 0);
    cudaMemsetAsync(logits, 0, TLOG * 4, 0);

    const int MBE = (NE + 127) / 128;   // 938
    const int MBN = (NN + 127) / 128;   // 469
    const int MBP = (NP + 127) / 128;   // 469

    // ---- layer 0 (msg = 0): r unused, suv = rdash = 0; K=192 GEMMs only ----
    {
        bf16* wz1H = bfb + O_WZ1_H;
        bf16* wz1L = bfb + O_WZ1_L;
        bf16* wwH  = bfb + O_WW_H;
        bf16* wwL  = bfb + O_WW_L;
        gemm_tc<<<dim3(MBE, 2), 256, SMEM_DYN>>>(
            fH, fL, 192, wz1H, wz1L, nullptr, nullptr, 0, nullptr, nullptr,
            Wz_b, z, NE, 256, 0, nullptr, nullptr, nullptr, nullptr, nullptr,
            nullptr, nullptr);
        gemm_tc<<<dim3(MBE, 2), 256, SMEM_DYN>>>(
            fH, fL, 192, wwH, wwL, nullptr, nullptr, 0, nullptr, nullptr,
            U_b, nullptr, NE, 256, 1, z, nullptr, nullptr, mH, mL,
            nullptr, nullptr);
    }

    for (int l = 1; l < 4; ++l) {
        bf16* wz1H = bfb + O_WZ1_H + (size_t)l * 49152;
        bf16* wz1L = bfb + O_WZ1_L + (size_t)l * 49152;
        bf16* wz2H = bfb + O_WZ2_H + (size_t)l * 65536;
        bf16* wz2L = bfb + O_WZ2_L + (size_t)l * 65536;
        bf16* wr1H = bfb + O_WR1_H + (size_t)l * 49152;
        bf16* wr1L = bfb + O_WR1_L + (size_t)l * 49152;
        bf16* wr2H = bfb + O_WR2_H + (size_t)l * 65536;
        bf16* wr2L = bfb + O_WR2_L + (size_t)l * 65536;
        bf16* wwH  = bfb + O_WW_H + (size_t)l * 49152;
        bf16* wwL  = bfb + O_WW_L + (size_t)l * 49152;
        bf16* uwH  = bfb + O_UW_H + (size_t)l * 65536;
        bf16* uwL  = bfb + O_UW_L + (size_t)l * 65536;

        // fork: suvk (stream B) overlaps r-GEMM (stream 0); both read msg
        cudaEventRecord(evA, 0);
        cudaStreamWaitEvent(sB, evA, 0);
        suvk<<<(NE * 64 + 255) / 256, 256, 0, sB>>>(nbr, mH, mL, sH, sL);
        cudaEventRecord(evB, sB);

        // r = sigmoid([feats|msg] @ Wr^T + b)
        gemm_tc<<<dim3(MBE, 2), 256, SMEM_DYN>>>(
            fH, fL, 192, wr1H, wr1L, mH, mL, 256, wr2H, wr2L,
            Wr_b + (size_t)l * 256, r, NE, 256, 0, nullptr, nullptr, nullptr,
            nullptr, nullptr, nullptr, nullptr);
        cudaEventRecord(evC, 0);
        cudaStreamWaitEvent(sB, evC, 0);
        rdashk<<<(NE * 64 + 255) / 256, 256, 0, sB>>>(nbr, mH, mL, rH, rL);
        cudaEventRecord(evD, sB);

        // z = sigmoid([feats|suv] @ Wz^T + b)  (needs suvk done)
        cudaStreamWaitEvent(0, evB, 0);
        gemm_tc<<<dim3(MBE, 2), 256, SMEM_DYN>>>(
            fH, fL, 192, wz1H, wz1L, sH, sL, 256, wz2H, wz2L,
            Wz_b + (size_t)l * 256, z, NE, 256, 0, nullptr, nullptr, nullptr,
            nullptr, nullptr, nullptr, nullptr);

        // msg = (1-z)*suv + z*tanh(feats@W^T + rdash@U^T + b)
        cudaStreamWaitEvent(0, evD, 0);
        int md = (l == 3) ? 4 : 1;
        gemm_tc<<<dim3(MBE, 2), 256, SMEM_DYN>>>(
            fH, fL, 192, wwH, wwL, rH, rL, 256, uwH, uwL,
            U_b + (size_t)l * 256, nullptr, NE, 256, md, z, sH, sL,
            md == 4 ? nullptr : mH, md == 4 ? nullptr : mL,
            md == 4 ? (const float*)(ei + NE) : nullptr, md == 4 ? aggr : nullptr);
    }

    CONV(aggr, (long long)NN * 256, 256, 256, 0, 256, aH, aL);

    // xg = relu([x|aggr] @ mlp^T + b)
    gemm_tc<<<dim3(MBN, 2), 256, SMEM_DYN>>>(
        xH, xL, 128, bfb + O_M1_H, bfb + O_M1_L, aH, aL, 256, bfb + O_M2_H, bfb + O_M2_L,
        mlp_b, xg, NN, 256, 2, nullptr, nullptr, nullptr, gH, gL,
        nullptr, nullptr);
    cudaEventRecord(evA, 0);

    // edge path on stream B: xedgek -> edge head
    cudaStreamWaitEvent(sB, evA, 0);
    xedgek<<<(NP * 64 + 255) / 256, 256, 0, sB>>>(ei, eH, eL);
    gemm_tc<<<dim3(MBP, 4), 256, SMEM_DYN, sB>>>(
        eH, eL, 512, bfb + O_E1_H, bfb + O_E1_L, nullptr, nullptr, 0, nullptr, nullptr,
        ec1_b, nullptr, NP, 512, 3, nullptr, nullptr, nullptr, nullptr, nullptr,
        ec2_w, logits + NN);
    cudaEventRecord(evB, sB);

    // node head on stream 0 (concurrent with edge path)
    gemm_tc<<<dim3(MBN, 4), 256, SMEM_DYN>>>(
        gH, gL, 256, bfb + O_N1_H, bfb + O_N1_L, nullptr, nullptr, 0, nullptr, nullptr,
        nc1_b, nullptr, NN, 512, 3, nullptr, nullptr, nullptr, nullptr, nullptr,
        nc2_w, logits);

    cudaStreamWaitEvent(0, evB, 0);
    soft1k<<<1, 1024>>>(nc2_b, ec2_b);
    soft2k<<<(TLOG + 255) / 256, 256>>>(out, nc2_b, ec2_b);
}

// round 14
// speedup vs baseline: 1.5554x; 1.0301x over previous
#include <cuda_runtime.h>
#include <cuda_bf16.h>
#include <cstdint>
#include <math.h>

#define NN 60000
#define NE 119998
#define NP 59999
#define TLOG (NN + NP)

typedef __nv_bfloat16 bf16;

// ---------------- fp32 scratch --------------------------------------------
__device__ float g_r    [(size_t)NE * 256];
__device__ float g_z    [(size_t)NE * 256];
__device__ float g_aggr [(size_t)NN * 256];
__device__ float g_xg   [(size_t)NN * 256];
__device__ float g_logits[TLOG];
__device__ float g_red[2];

// ---------------- bf16 hi/lo scratch (one big arena) -----------------------
#define SZ_FEATS ((size_t)NE * 192)
#define SZ_E256  ((size_t)NE * 256)
#define SZ_X     ((size_t)NN * 128)
#define SZ_N256  ((size_t)NN * 256)
#define SZ_XE    ((size_t)NP * 512)

constexpr size_t O_FEATS_H = 0;
constexpr size_t O_FEATS_L = O_FEATS_H + SZ_FEATS;
constexpr size_t O_MSG_H   = O_FEATS_L + SZ_FEATS;
constexpr size_t O_MSG_L   = O_MSG_H + SZ_E256;
constexpr size_t O_SUV_H   = O_MSG_L + SZ_E256;
constexpr size_t O_SUV_L   = O_SUV_H + SZ_E256;
constexpr size_t O_RD_H    = O_SUV_L + SZ_E256;
constexpr size_t O_RD_L    = O_RD_H + SZ_E256;
constexpr size_t O_X_H     = O_RD_L + SZ_E256;
constexpr size_t O_X_L     = O_X_H + SZ_X;
constexpr size_t O_AG_H    = O_X_L + SZ_X;
constexpr size_t O_AG_L    = O_AG_H + SZ_N256;
constexpr size_t O_XG_H    = O_AG_L + SZ_N256;
constexpr size_t O_XG_L    = O_XG_H + SZ_N256;
constexpr size_t O_XE_H    = O_XG_L + SZ_N256;
constexpr size_t O_XE_L    = O_XE_H + SZ_XE;
constexpr size_t O_WZ1_H   = O_XE_L + SZ_XE;
constexpr size_t O_WZ1_L   = O_WZ1_H + 4 * 256 * 192;
constexpr size_t O_WZ2_H   = O_WZ1_L + 4 * 256 * 192;
constexpr size_t O_WZ2_L   = O_WZ2_H + 4 * 256 * 256;
constexpr size_t O_WR1_H   = O_WZ2_L + 4 * 256 * 256;
constexpr size_t O_WR1_L   = O_WR1_H + 4 * 256 * 192;
constexpr size_t O_WR2_H   = O_WR1_L + 4 * 256 * 192;
constexpr size_t O_WR2_L   = O_WR2_H + 4 * 256 * 256;
constexpr size_t O_WW_H    = O_WR2_L + 4 * 256 * 256;
constexpr size_t O_WW_L    = O_WW_H + 4 * 256 * 192;
constexpr size_t O_UW_H    = O_WW_L + 4 * 256 * 192;
constexpr size_t O_UW_L    = O_UW_H + 4 * 256 * 256;
constexpr size_t O_M1_H    = O_UW_L + 4 * 256 * 256;
constexpr size_t O_M1_L    = O_M1_H + 256 * 128;
constexpr size_t O_M2_H    = O_M1_L + 256 * 128;
constexpr size_t O_M2_L    = O_M2_H + 256 * 256;
constexpr size_t O_N1_H    = O_M2_L + 256 * 256;
constexpr size_t O_N1_L    = O_N1_H + 512 * 256;
constexpr size_t O_E1_H    = O_N1_L + 512 * 256;
constexpr size_t O_E1_L    = O_E1_H + 512 * 512;
constexpr size_t O_ZM_H    = O_E1_L + 512 * 512;   // l0 interleaved [Wz1|Ww], 512x192
constexpr size_t O_ZM_L    = O_ZM_H + 512 * 192;
constexpr size_t BF_TOTAL  = O_ZM_L + 512 * 192;

__device__ bf16 g_bf[BF_TOTAL];

// ---------------- helpers --------------------------------------------------
__device__ __forceinline__ uint32_t s2u(const void* p) {
    uint32_t a;
    asm("{ .reg .u64 t; cvta.to.shared.u64 t, %1; cvt.u32.u64 %0, t; }" : "=r"(a) : "l"(p));
    return a;
}

__device__ __forceinline__ void mma16816(float* c, const uint32_t* a, const uint32_t* b) {
    asm volatile(
        "mma.sync.aligned.m16n8k16.row.col.f32.bf16.bf16.f32 "
        "{%0,%1,%2,%3}, {%4,%5,%6,%7}, {%8,%9}, {%0,%1,%2,%3};"
        : "+f"(c[0]), "+f"(c[1]), "+f"(c[2]), "+f"(c[3])
        : "r"(a[0]), "r"(a[1]), "r"(a[2]), "r"(a[3]), "r"(b[0]), "r"(b[1]));
}

__device__ __forceinline__ void ldsm4(uint32_t* r, uint32_t addr) {
    asm volatile("ldmatrix.sync.aligned.m8n8.x4.shared.b16 {%0,%1,%2,%3}, [%4];"
                 : "=r"(r[0]), "=r"(r[1]), "=r"(r[2]), "=r"(r[3]) : "r"(addr));
}

__device__ __forceinline__ void store_hl4(bf16* hp, bf16* lp, float4 v) {
    bf16 h0 = __float2bfloat16(v.x), h1 = __float2bfloat16(v.y);
    bf16 h2 = __float2bfloat16(v.z), h3 = __float2bfloat16(v.w);
    bf16 l0 = __float2bfloat16(v.x - __bfloat162float(h0));
    bf16 l1 = __float2bfloat16(v.y - __bfloat162float(h1));
    bf16 l2 = __float2bfloat16(v.z - __bfloat162float(h2));
    bf16 l3 = __float2bfloat16(v.w - __bfloat162float(h3));
    ((__nv_bfloat162*)hp)[0] = __halves2bfloat162(h0, h1);
    ((__nv_bfloat162*)hp)[1] = __halves2bfloat162(h2, h3);
    ((__nv_bfloat162*)lp)[0] = __halves2bfloat162(l0, l1);
    ((__nv_bfloat162*)lp)[1] = __halves2bfloat162(l2, l3);
}

__device__ __forceinline__ void store_hl2(bf16* hp, bf16* lp, float v0, float v1) {
    bf16 h0 = __float2bfloat16(v0), h1 = __float2bfloat16(v1);
    bf16 l0 = __float2bfloat16(v0 - __bfloat162float(h0));
    bf16 l1 = __float2bfloat16(v1 - __bfloat162float(h1));
    *(__nv_bfloat162*)hp = __halves2bfloat162(h0, h1);
    *(__nv_bfloat162*)lp = __halves2bfloat162(l0, l1);
}

__device__ __forceinline__ float4 load_hl4(const bf16* hp, const bf16* lp) {
    uint2 vh = *(const uint2*)hp;
    uint2 vl = *(const uint2*)lp;
    float2 h0 = __bfloat1622float2(*(__nv_bfloat162*)&vh.x);
    float2 h1 = __bfloat1622float2(*(__nv_bfloat162*)&vh.y);
    float2 l0 = __bfloat1622float2(*(__nv_bfloat162*)&vl.x);
    float2 l1 = __bfloat1622float2(*(__nv_bfloat162*)&vl.y);
    return make_float4(h0.x + l0.x, h0.y + l0.y, h1.x + l1.x, h1.y + l1.y);
}

// ---------------- small kernels --------------------------------------------
__global__ void featsk(const float* __restrict__ x, const float* __restrict__ ea,
                       const int* __restrict__ ei,
                       bf16* __restrict__ fh, bf16* __restrict__ fl) {
    int i = blockIdx.x * blockDim.x + threadIdx.x;
    if (i >= NE * 48) return;
    int e = i / 48;
    int q = i - e * 48;
    float4 v = make_float4(0.f, 0.f, 0.f, 0.f);
    if (q < 32) {
        int t = ei[NE + e];
        v = ((const float4*)x)[(size_t)t * 32 + q];
    } else if (q < 40) {
        v = ((const float4*)ea)[(size_t)e * 8 + (q - 32)];
    }
    size_t o = (size_t)e * 192 + q * 4;
    store_hl4(fh + o, fl + o, v);
}

__global__ void suvk(const int* __restrict__ nbr, const bf16* __restrict__ mh,
                     const bf16* __restrict__ ml,
                     bf16* __restrict__ sh, bf16* __restrict__ sl) {
    int i = blockIdx.x * blockDim.x + threadIdx.x;
    if (i >= NE * 64) return;
    int e = i >> 6, q = i & 63;
    float4 acc = make_float4(0.f, 0.f, 0.f, 0.f);
#pragma unroll
    for (int j = 0; j < 3; ++j) {
        int idx = nbr[3 * (size_t)e + j];
        if (idx > 0) {
            size_t o = (size_t)(idx - 1) * 256 + q * 4;
            float4 v = load_hl4(mh + o, ml + o);
            acc.x += v.x; acc.y += v.y; acc.z += v.z; acc.w += v.w;
        }
    }
    size_t o = (size_t)e * 256 + q * 4;
    store_hl4(sh + o, sl + o, acc);
}

__global__ void rdashk(const int* __restrict__ nbr, const bf16* __restrict__ mh,
                       const bf16* __restrict__ ml,
                       bf16* __restrict__ rh, bf16* __restrict__ rl) {
    int i = blockIdx.x * blockDim.x + threadIdx.x;
    if (i >= NE * 64) return;
    int e = i >> 6, q = i & 63;
    const float4* r4 = (const float4*)g_r;
    float4 acc = make_float4(0.f, 0.f, 0.f, 0.f);
#pragma unroll
    for (int j = 0; j < 3; ++j) {
        int idx = nbr[3 * (size_t)e + j];
        if (idx > 0) {
            size_t o = (size_t)(idx - 1) * 256 + q * 4;
            float4 g = load_hl4(mh + o, ml + o);
            float4 rr = r4[(size_t)(idx - 1) * 64 + q];
            acc.x = fmaf(rr.x, g.x, acc.x);
            acc.y = fmaf(rr.y, g.y, acc.y);
            acc.z = fmaf(rr.z, g.z, acc.z);
            acc.w = fmaf(rr.w, g.w, acc.w);
        }
    }
    size_t o = (size_t)e * 256 + q * 4;
    store_hl4(rh + o, rl + o, acc);
}

__global__ void xedgek(const int* __restrict__ ei, bf16* __restrict__ xh, bf16* __restrict__ xl) {
    int i = blockIdx.x * blockDim.x + threadIdx.x;
    if (i >= NP * 64) return;
    int p = i >> 6, q = i & 63;
    int u = ei[2 * p];
    int v = ei[NE + 2 * p];
    const float4* X = (const float4*)g_xg;
    float4 a = X[(size_t)u * 64 + q];
    float4 b = X[(size_t)v * 64 + q];
    size_t o = (size_t)p * 512 + q * 4;
    store_hl4(xh + o, xl + o,
        make_float4(fabsf(a.x - b.x), fabsf(a.y - b.y), fabsf(a.z - b.z), fabsf(a.w - b.w)));
    store_hl4(xh + o + 256, xl + o + 256,
        make_float4(a.x + b.x, a.y + b.y, a.z + b.z, a.w + b.w));
}

// pad-convert fp32 -> bf16 hi/lo
__global__ void convk(const float* __restrict__ src, long long total, int K, int rowStride,
                      int colOff, int Kp, bf16* __restrict__ hi, bf16* __restrict__ lo) {
    long long i = (long long)blockIdx.x * blockDim.x + threadIdx.x;
    if (i >= total) return;
    int k = (int)(i % Kp);
    long long row = i / Kp;
    float v = (k < K) ? src[row * rowStride + colOff + k] : 0.f;
    bf16 h = __float2bfloat16(v);
    hi[i] = h;
    lo[i] = __float2bfloat16(v - __bfloat162float(h));
}

// l0 interleaved weights: B'[2j] = Wz1_l0 row j, B'[2j+1] = Ww_l0 row j (K=192)
__global__ void convzm(const float* __restrict__ Wz_w, const float* __restrict__ W_w,
                       bf16* __restrict__ hi, bf16* __restrict__ lo) {
    int i = blockIdx.x * blockDim.x + threadIdx.x;
    if (i >= 512 * 192) return;
    int row = i / 192, k = i - row * 192;
    int j = row >> 1;
    float v = 0.f;
    if (k < 160) v = (row & 1) ? W_w[j * 160 + k] : Wz_w[j * 416 + k];
    bf16 h = __float2bfloat16(v);
    hi[i] = h;
    lo[i] = __float2bfloat16(v - __bfloat162float(h));
}

// ---------------- split-bf16 mma.sync GEMM (R6 config, pinned) --------------
// CTA tile 128x128, 8 warps (2x4) of 64x32, K-chunk 32, double buffer, 2 CTA/SM.
// mode 0=sigmoid 1=GRU 2=relu 3=relu-dot->atomicAdd(lgt) 4=GRU->aggr atomics
//      5=interleaved sig(v0)*tanh(v1) -> msg hi/lo (w2 = second bias)
#define KC 32
#define ROWB 80
#define TILEB (128 * ROWB)            // 10240
#define STAGE_B (4 * TILEB)           // 40960
#define SMEM_DYN (2 * STAGE_B)        // 81920 -> 2 CTAs/SM

__global__ void __launch_bounds__(256, 2) gemm_tc(
    const bf16* __restrict__ A1h, const bf16* __restrict__ A1l, int K1p,
    const bf16* __restrict__ B1h, const bf16* __restrict__ B1l,
    const bf16* __restrict__ A2h, const bf16* __restrict__ A2l, int K2p,
    const bf16* __restrict__ B2h, const bf16* __restrict__ B2l,
    const float* __restrict__ bias, float* __restrict__ C, int M, int N, int mode,
    const float* __restrict__ zb, const bf16* __restrict__ sbH, const bf16* __restrict__ sbL,
    bf16* __restrict__ outH, bf16* __restrict__ outL,
    const float* __restrict__ w2, float* __restrict__ lgt)
{
    extern __shared__ char dsm[];
    const uint32_t smem_u = s2u(dsm);
    const int tid  = threadIdx.x;
    const int warp = tid >> 5;
    const int lane = tid & 31;
    const int g    = lane >> 2;
    const int t    = lane & 3;
    const int wm   = warp & 1;
    const int wn   = warp >> 1;
    const int m0   = blockIdx.x * 128;
    const int n0   = blockIdx.y * 128;

    const int nch1 = K1p >> 5;
    const int nch2 = B2h ? (K2p >> 5) : 0;
    const int nch  = nch1 + nch2;

    uint32_t aAddr[4], bAddr[2];
#pragma unroll
    for (int mt = 0; mt < 4; ++mt) {
        int row = wm * 64 + mt * 16 + ((lane >> 3) & 1) * 8 + (lane & 7);
        aAddr[mt] = (uint32_t)(row * ROWB + (lane >> 4) * 16);
    }
#pragma unroll
    for (int np = 0; np < 2; ++np) {
        int row = wn * 32 + np * 16 + ((lane >> 4) & 1) * 8 + (lane & 7);
        bAddr[np] = (uint32_t)(2 * TILEB + row * ROWB + ((lane >> 3) & 1) * 16);
    }

    float acc[4][4][4];
#pragma unroll
    for (int i = 0; i < 4; ++i)
#pragma unroll
        for (int j = 0; j < 4; ++j)
#pragma unroll
            for (int k = 0; k < 4; ++k) acc[i][j][k] = 0.f;

    auto issue = [&](int c) {
        const bf16 *Ah, *Al, *Bh, *Bl;
        int lda, kc;
        if (c < nch1) { Ah = A1h; Al = A1l; Bh = B1h; Bl = B1l; lda = K1p; kc = c << 5; }
        else          { Ah = A2h; Al = A2l; Bh = B2h; Bl = B2l; lda = K2p; kc = (c - nch1) << 5; }
        uint32_t dst0 = smem_u + (uint32_t)((c & 1) * STAGE_B);
#pragma unroll
        for (int it = 0; it < 8; ++it) {
            int u = tid + it * 256;
            int which = u >> 9;
            int rem   = u & 511;
            int row   = rem >> 2;
            int seg   = rem & 3;
            const bf16* sm = (which == 0) ? Ah : (which == 1) ? Al : (which == 2) ? Bh : Bl;
            int sz = 16;
            long long grow;
            if (which < 2) {
                int gm = m0 + row;
                if (gm >= M) { gm = M - 1; sz = 0; }
                grow = gm;
            } else {
                grow = n0 + row;
            }
            const char* src = (const char*)(sm + grow * (long long)lda + kc) + seg * 16;
            uint32_t du = dst0 + (uint32_t)(which * TILEB + row * ROWB + seg * 16);
            asm volatile("cp.async.cg.shared.global [%0], [%1], 16, %2;"
                         :: "r"(du), "l"(src), "r"(sz) : "memory");
        }
        asm volatile("cp.async.commit_group;" ::: "memory");
    };

    // one-sync-per-chunk pipeline: wait buf c -> barrier -> issue c+1 -> compute c
    issue(0);
    for (int c = 0; c < nch; ++c) {
        asm volatile("cp.async.wait_group 0;" ::: "memory");
        __syncthreads();
        if (c + 1 < nch) issue(c + 1);

        const uint32_t base = smem_u + (uint32_t)((c & 1) * STAGE_B);
#pragma unroll
        for (int ks = 0; ks < 2; ++ks) {
            const uint32_t ko = ks * 32;
            uint32_t ah[4][4], bh[2][4];
#pragma unroll
            for (int mt = 0; mt < 4; ++mt) ldsm4(ah[mt], base + aAddr[mt] + ko);
#pragma unroll
            for (int np = 0; np < 2; ++np) ldsm4(bh[np], base + bAddr[np] + ko);
#pragma unroll
            for (int mt = 0; mt < 4; ++mt)
#pragma unroll
                for (int nt = 0; nt < 4; ++nt)
                    mma16816(acc[mt][nt], ah[mt], &bh[nt >> 1][(nt & 1) * 2]);
            {   // ah x bl
                uint32_t bl[2][4];
#pragma unroll
                for (int np = 0; np < 2; ++np) ldsm4(bl[np], base + bAddr[np] + TILEB + ko);
#pragma unroll
                for (int mt = 0; mt < 4; ++mt)
#pragma unroll
                    for (int nt = 0; nt < 4; ++nt)
                        mma16816(acc[mt][nt], ah[mt], &bl[nt >> 1][(nt & 1) * 2]);
            }
            {   // al x bh
                uint32_t al[4][4];
#pragma unroll
                for (int mt = 0; mt < 4; ++mt) ldsm4(al[mt], base + aAddr[mt] + TILEB + ko);
#pragma unroll
                for (int mt = 0; mt < 4; ++mt)
#pragma unroll
                    for (int nt = 0; nt < 4; ++nt)
                        mma16816(acc[mt][nt], al[mt], &bh[nt >> 1][(nt & 1) * 2]);
            }
        }
    }

    // ---------------- epilogue ----------------
    if (mode == 3) {
#pragma unroll
        for (int mt = 0; mt < 4; ++mt) {
            int rg = m0 + wm * 64 + mt * 16 + g;
#pragma unroll
            for (int h = 0; h < 2; ++h) {
                int row = rg + h * 8;
                float s = 0.f;
#pragma unroll
                for (int nt = 0; nt < 4; ++nt) {
                    int cn = n0 + wn * 32 + nt * 8 + 2 * t;
                    float v0 = fmaxf(acc[mt][nt][2 * h]     + bias[cn],     0.f);
                    float v1 = fmaxf(acc[mt][nt][2 * h + 1] + bias[cn + 1], 0.f);
                    s = fmaf(v0, w2[cn], s);
                    s = fmaf(v1, w2[cn + 1], s);
                }
                s += __shfl_xor_sync(0xffffffffu, s, 1);
                s += __shfl_xor_sync(0xffffffffu, s, 2);
                if (t == 0 && row < M) atomicAdd(&lgt[row], s);
            }
        }
        return;
    }

    if (mode == 5) {
        // interleaved z|m: msg[row, j] = sigmoid(v0)*tanh(v1), j = cn/2
#pragma unroll
        for (int mt = 0; mt < 4; ++mt) {
            int rg = m0 + wm * 64 + mt * 16 + g;
#pragma unroll
            for (int nt = 0; nt < 4; ++nt) {
                int cn = n0 + wn * 32 + nt * 8 + 2 * t;
                int j = cn >> 1;
                float bz = bias[j], bu = w2[j];
#pragma unroll
                for (int h = 0; h < 2; ++h) {
                    int row = rg + h * 8;
                    if (row >= M) continue;
                    float v0 = acc[mt][nt][2 * h]     + bz;
                    float v1 = acc[mt][nt][2 * h + 1] + bu;
                    float m = (1.f / (1.f + expf(-v0))) * tanhf(v1);
                    bf16 hh = __float2bfloat16(m);
                    size_t oi = (size_t)row * 256 + j;
                    outH[oi] = hh;
                    outL[oi] = __float2bfloat16(m - __bfloat162float(hh));
                }
            }
        }
        return;
    }

#pragma unroll
    for (int mt = 0; mt < 4; ++mt) {
        int rg = m0 + wm * 64 + mt * 16 + g;
#pragma unroll
        for (int nt = 0; nt < 4; ++nt) {
            int cn = n0 + wn * 32 + nt * 8 + 2 * t;
            float b0 = bias[cn], b1 = bias[cn + 1];
#pragma unroll
            for (int h = 0; h < 2; ++h) {
                int row = rg + h * 8;
                if (row >= M) continue;
                float v0 = acc[mt][nt][2 * h]     + b0;
                float v1 = acc[mt][nt][2 * h + 1] + b1;
                size_t idx = (size_t)row * N + cn;
                if (mode == 0) {
                    v0 = 1.f / (1.f + expf(-v0));
                    v1 = 1.f / (1.f + expf(-v1));
                } else if (mode == 2) {
                    v0 = fmaxf(v0, 0.f);
                    v1 = fmaxf(v1, 0.f);
                } else {  // 1 or 4: GRU combine
                    float z0 = zb[idx], z1 = zb[idx + 1];
                    float s0 = 0.f, s1 = 0.f;
                    if (sbH) {
                        __nv_bfloat162 sh2 = *(const __nv_bfloat162*)(sbH + idx);
                        __nv_bfloat162 sl2 = *(const __nv_bfloat162*)(sbL + idx);
                        s0 = __bfloat162float(sh2.x) + __bfloat162float(sl2.x);
                        s1 = __bfloat162float(sh2.y) + __bfloat162float(sl2.y);
                    }
                    v0 = (1.f - z0) * s0 + z0 * tanhf(v0);
                    v1 = (1.f - z1) * s1 + z1 * tanhf(v1);
                }
                if (mode == 4) {
                    const int* tgt = (const int*)w2;
                    int tr = tgt[row];
                    atomicAdd(&lgt[(size_t)tr * 256 + cn], v0);
                    atomicAdd(&lgt[(size_t)tr * 256 + cn + 1], v1);
                } else {
                    if (C) *(float2*)(C + idx) = make_float2(v0, v1);
                    if (outH) store_hl2(outH + idx, outL + idx, v0, v1);
                }
            }
        }
    }
}

// ---------------- softmax (with per-segment scalar bias) --------------------
__global__ void soft1k(const float* __restrict__ ncb, const float* __restrict__ ecb) {
    __shared__ float sm[1024];
    int tid = threadIdx.x;
    float bn = ncb[0], be = ecb[0];
    float mx = -1e30f;
    for (int i = tid; i < TLOG; i += 1024)
        mx = fmaxf(mx, g_logits[i] + (i < NN ? bn : be));
    sm[tid] = mx;
    __syncthreads();
    for (int s = 512; s > 0; s >>= 1) {
        if (tid < s) sm[tid] = fmaxf(sm[tid], sm[tid + s]);
        __syncthreads();
    }
    float gmax = sm[0];
    __syncthreads();
    float sum = 0.f;
    for (int i = tid; i < TLOG; i += 1024)
        sum += expf(g_logits[i] + (i < NN ? bn : be) - gmax);
    sm[tid] = sum;
    __syncthreads();
    for (int s = 512; s > 0; s >>= 1) {
        if (tid < s) sm[tid] += sm[tid + s];
        __syncthreads();
    }
    if (tid == 0) { g_red[0] = gmax; g_red[1] = sm[0]; }
}

__global__ void soft2k(float* __restrict__ out, const float* __restrict__ ncb,
                       const float* __restrict__ ecb) {
    int i = blockIdx.x * blockDim.x + threadIdx.x;
    if (i < TLOG)
        out[i] = expf(g_logits[i] + (i < NN ? ncb[0] : ecb[0]) - g_red[0]) / g_red[1];
}

// ---------------------------------------------------------------------------
extern "C" void kernel_launch(void* const* d_in, const int* in_sizes, int n_in,
                              void* d_out, int out_size) {
    (void)in_sizes; (void)n_in; (void)out_size;
    const float* x     = (const float*)d_in[0];
    const float* ea    = (const float*)d_in[1];
    const int*   ei    = (const int*)d_in[2];
    const int*   nbr   = (const int*)d_in[3];
    const float* Wz_w  = (const float*)d_in[4];
    const float* Wz_b  = (const float*)d_in[5];
    const float* Wr_w  = (const float*)d_in[6];
    const float* Wr_b  = (const float*)d_in[7];
    const float* W_w   = (const float*)d_in[8];
    const float* U_w   = (const float*)d_in[9];
    const float* U_b   = (const float*)d_in[10];
    const float* mlp_w = (const float*)d_in[11];
    const float* mlp_b = (const float*)d_in[12];
    const float* nc1_w = (const float*)d_in[13];
    const float* nc1_b = (const float*)d_in[14];
    const float* nc2_w = (const float*)d_in[15];
    const float* nc2_b = (const float*)d_in[16];
    const float* ec1_w = (const float*)d_in[17];
    const float* ec1_b = (const float*)d_in[18];
    const float* ec2_w = (const float*)d_in[19];
    const float* ec2_b = (const float*)d_in[20];
    float* out = (float*)d_out;

    float *r, *z, *aggr, *xg, *logits;
    bf16* bfb;
    cudaGetSymbolAddress((void**)&r,      g_r);
    cudaGetSymbolAddress((void**)&z,      g_z);
    cudaGetSymbolAddress((void**)&aggr,   g_aggr);
    cudaGetSymbolAddress((void**)&xg,     g_xg);
    cudaGetSymbolAddress((void**)&logits, g_logits);
    cudaGetSymbolAddress((void**)&bfb,    g_bf);

    cudaFuncSetAttribute(gemm_tc, cudaFuncAttributeMaxDynamicSharedMemorySize, SMEM_DYN);

    // auxiliary stream + events for captured fork/join (created once)
    static cudaStream_t sB = nullptr;
    static cudaEvent_t evA = nullptr, evB = nullptr, evC = nullptr, evD = nullptr;
    static cudaEvent_t evF = nullptr, evW = nullptr;
    if (sB == nullptr) {
        cudaStreamCreate(&sB);
        cudaEventCreateWithFlags(&evA, cudaEventDisableTiming);
        cudaEventCreateWithFlags(&evB, cudaEventDisableTiming);
        cudaEventCreateWithFlags(&evC, cudaEventDisableTiming);
        cudaEventCreateWithFlags(&evD, cudaEventDisableTiming);
        cudaEventCreateWithFlags(&evF, cudaEventDisableTiming);
        cudaEventCreateWithFlags(&evW, cudaEventDisableTiming);
    }

    bf16 *fH = bfb + O_FEATS_H, *fL = bfb + O_FEATS_L;
    bf16 *mH = bfb + O_MSG_H,  *mL = bfb + O_MSG_L;
    bf16 *sH = bfb + O_SUV_H,  *sL = bfb + O_SUV_L;
    bf16 *rH = bfb + O_RD_H,   *rL = bfb + O_RD_L;
    bf16 *xH = bfb + O_X_H,    *xL = bfb + O_X_L;
    bf16 *aH = bfb + O_AG_H,   *aL = bfb + O_AG_L;
    bf16 *gH = bfb + O_XG_H,   *gL = bfb + O_XG_L;
    bf16 *eH = bfb + O_XE_H,   *eL = bfb + O_XE_L;

#define CONVS(st, src, tot, K, stride, off, Kp, hi, lo) \
    convk<<<(int)(((long long)(tot) + 255) / 256), 256, 0, st>>>( \
        src, (long long)(tot), K, stride, off, Kp, hi, lo)

    // fork sB FROM the capture origin stream first (capture-legal), then convs on sB
    cudaEventRecord(evF, 0);
    cudaStreamWaitEvent(sB, evF, 0);

    CONVS(sB, Wz_w, 4 * 256 * 192, 160, 416, 0, 192, bfb + O_WZ1_H, bfb + O_WZ1_L);
    CONVS(sB, Wz_w, 4 * 256 * 256, 256, 416, 160, 256, bfb + O_WZ2_H, bfb + O_WZ2_L);
    CONVS(sB, Wr_w, 4 * 256 * 192, 160, 416, 0, 192, bfb + O_WR1_H, bfb + O_WR1_L);
    CONVS(sB, Wr_w, 4 * 256 * 256, 256, 416, 160, 256, bfb + O_WR2_H, bfb + O_WR2_L);
    CONVS(sB, W_w, 4 * 256 * 192, 160, 160, 0, 192, bfb + O_WW_H, bfb + O_WW_L);
    CONVS(sB, U_w, 4 * 256 * 256, 256, 256, 0, 256, bfb + O_UW_H, bfb + O_UW_L);
    CONVS(sB, mlp_w, 256 * 128, 128, 384, 0, 128, bfb + O_M1_H, bfb + O_M1_L);
    CONVS(sB, mlp_w, 256 * 256, 256, 384, 128, 256, bfb + O_M2_H, bfb + O_M2_L);
    CONVS(sB, nc1_w, 512 * 256, 256, 256, 0, 256, bfb + O_N1_H, bfb + O_N1_L);
    CONVS(sB, ec1_w, 512 * 512, 512, 512, 0, 512, bfb + O_E1_H, bfb + O_E1_L);
    convzm<<<(512 * 192 + 255) / 256, 256, 0, sB>>>(Wz_w, W_w, bfb + O_ZM_H, bfb + O_ZM_L);
    cudaEventRecord(evW, sB);

    // stream 0: activation-side prep (overlaps weight convs)
    featsk<<<(NE * 48 + 255) / 256, 256>>>(x, ea, ei, fH, fL);
    CONVS(0, x, (long long)NN * 128, 128, 128, 0, 128, xH, xL);
    cudaMemsetAsync(aggr, 0, (size_t)NN * 256 * 4, 0);
    cudaMemsetAsync(logits, 0, TLOG * 4, 0);

    const int MBE = (NE + 127) / 128;   // 938
    const int MBN = (NN + 127) / 128;   // 469
    const int MBP = (NP + 127) / 128;   // 469

    // join weights before first GEMM
    cudaStreamWaitEvent(0, evW, 0);

    // ---- layer 0 fused: msg = sigmoid(feats@Wz1+bz) * tanh(feats@Ww+bu) ----
    gemm_tc<<<dim3(MBE, 4), 256, SMEM_DYN>>>(
        fH, fL, 192, bfb + O_ZM_H, bfb + O_ZM_L, nullptr, nullptr, 0, nullptr, nullptr,
        Wz_b, nullptr, NE, 512, 5, nullptr, nullptr, nullptr, mH, mL,
        U_b, nullptr);

    for (int l = 1; l < 4; ++l) {
        bf16* wz1H = bfb + O_WZ1_H + (size_t)l * 49152;
        bf16* wz1L = bfb + O_WZ1_L + (size_t)l * 49152;
        bf16* wz2H = bfb + O_WZ2_H + (size_t)l * 65536;
        bf16* wz2L = bfb + O_WZ2_L + (size_t)l * 65536;
        bf16* wr1H = bfb + O_WR1_H + (size_t)l * 49152;
        bf16* wr1L = bfb + O_WR1_L + (size_t)l * 49152;
        bf16* wr2H = bfb + O_WR2_H + (size_t)l * 65536;
        bf16* wr2L = bfb + O_WR2_L + (size_t)l * 65536;
        bf16* wwH  = bfb + O_WW_H + (size_t)l * 49152;
        bf16* wwL  = bfb + O_WW_L + (size_t)l * 49152;
        bf16* uwH  = bfb + O_UW_H + (size_t)l * 65536;
        bf16* uwL  = bfb + O_UW_L + (size_t)l * 65536;

        // fork: suvk (stream B) overlaps r-GEMM (stream 0); both read msg
        cudaEventRecord(evA, 0);
        cudaStreamWaitEvent(sB, evA, 0);
        suvk<<<(NE * 64 + 255) / 256, 256, 0, sB>>>(nbr, mH, mL, sH, sL);
        cudaEventRecord(evB, sB);

        // r = sigmoid([feats|msg] @ Wr^T + b)
        gemm_tc<<<dim3(MBE, 2), 256, SMEM_DYN>>>(
            fH, fL, 192, wr1H, wr1L, mH, mL, 256, wr2H, wr2L,
            Wr_b + (size_t)l * 256, r, NE, 256, 0, nullptr, nullptr, nullptr,
            nullptr, nullptr, nullptr, nullptr);
        cudaEventRecord(evC, 0);
        cudaStreamWaitEvent(sB, evC, 0);
        rdashk<<<(NE * 64 + 255) / 256, 256, 0, sB>>>(nbr, mH, mL, rH, rL);
        cudaEventRecord(evD, sB);

        // z = sigmoid([feats|suv] @ Wz^T + b)  (needs suvk done)
        cudaStreamWaitEvent(0, evB, 0);
        gemm_tc<<<dim3(MBE, 2), 256, SMEM_DYN>>>(
            fH, fL, 192, wz1H, wz1L, sH, sL, 256, wz2H, wz2L,
            Wz_b + (size_t)l * 256, z, NE, 256, 0, nullptr, nullptr, nullptr,
            nullptr, nullptr, nullptr, nullptr);

        // msg = (1-z)*suv + z*tanh(feats@W^T + rdash@U^T + b)
        cudaStreamWaitEvent(0, evD, 0);
        int md = (l == 3) ? 4 : 1;
        gemm_tc<<<dim3(MBE, 2), 256, SMEM_DYN>>>(
            fH, fL, 192, wwH, wwL, rH, rL, 256, uwH, uwL,
            U_b + (size_t)l * 256, nullptr, NE, 256, md, z, sH, sL,
            md == 4 ? nullptr : mH, md == 4 ? nullptr : mL,
            md == 4 ? (const float*)(ei + NE) : nullptr, md == 4 ? aggr : nullptr);
    }

    CONVS(0, aggr, (long long)NN * 256, 256, 256, 0, 256, aH, aL);

    // xg = relu([x|aggr] @ mlp^T + b)
    gemm_tc<<<dim3(MBN, 2), 256, SMEM_DYN>>>(
        xH, xL, 128, bfb + O_M1_H, bfb + O_M1_L, aH, aL, 256, bfb + O_M2_H, bfb + O_M2_L,
        mlp_b, xg, NN, 256, 2, nullptr, nullptr, nullptr, gH, gL,
        nullptr, nullptr);
    cudaEventRecord(evA, 0);

    // edge path on stream B: xedgek -> edge head
    cudaStreamWaitEvent(sB, evA, 0);
    xedgek<<<(NP * 64 + 255) / 256, 256, 0, sB>>>(ei, eH, eL);
    gemm_tc<<<dim3(MBP, 4), 256, SMEM_DYN, sB>>>(
        eH, eL, 512, bfb + O_E1_H, bfb + O_E1_L, nullptr, nullptr, 0, nullptr, nullptr,
        ec1_b, nullptr, NP, 512, 3, nullptr, nullptr, nullptr, nullptr, nullptr,
        ec2_w, logits + NN);
    cudaEventRecord(evB, sB);

    // node head on stream 0 (concurrent with edge path)
    gemm_tc<<<dim3(MBN, 4), 256, SMEM_DYN>>>(
        gH, gL, 256, bfb + O_N1_H, bfb + O_N1_L, nullptr, nullptr, 0, nullptr, nullptr,
        nc1_b, nullptr, NN, 512, 3, nullptr, nullptr, nullptr, nullptr, nullptr,
        nc2_w, logits);

    cudaStreamWaitEvent(0, evB, 0);
    soft1k<<<1, 1024>>>(nc2_b, ec2_b);
    soft2k<<<(TLOG + 255) / 256, 256>>>(out, nc2_b, ec2_b);
}

// round 15
// speedup vs baseline: 2.1545x; 1.3852x over previous
#include <cuda_runtime.h>
#include <cuda_fp16.h>
#include <cstdint>
#include <math.h>

#define NN 60000
#define NE 119998
#define NP 59999
#define TLOG (NN + NP)

typedef __half hf;

// ---------------- fp32 scratch --------------------------------------------
__device__ float g_aggr [(size_t)NN * 256];
__device__ float g_logits[TLOG];
__device__ float g_red[2];

// ---------------- fp16 scratch arena ---------------------------------------
constexpr size_t O_FEATS = 0;                                  // NE*192
constexpr size_t O_MSG   = O_FEATS + (size_t)NE * 192;         // NE*256
constexpr size_t O_SUV   = O_MSG   + (size_t)NE * 256;
constexpr size_t O_RD    = O_SUV   + (size_t)NE * 256;
constexpr size_t O_R     = O_RD    + (size_t)NE * 256;
constexpr size_t O_Z     = O_R     + (size_t)NE * 256;
constexpr size_t O_X     = O_Z     + (size_t)NE * 256;         // NN*128
constexpr size_t O_AG    = O_X     + (size_t)NN * 128;         // NN*256
constexpr size_t O_XG    = O_AG    + (size_t)NN * 256;
constexpr size_t O_XE    = O_XG    + (size_t)NN * 256;         // NP*512
constexpr size_t O_WZ1_H = O_XE    + (size_t)NP * 512;
constexpr size_t O_WZ1_L = O_WZ1_H + 4 * 256 * 192;
constexpr size_t O_WZ2_H = O_WZ1_L + 4 * 256 * 192;
constexpr size_t O_WZ2_L = O_WZ2_H + 4 * 256 * 256;
constexpr size_t O_WR1_H = O_WZ2_L + 4 * 256 * 256;
constexpr size_t O_WR1_L = O_WR1_H + 4 * 256 * 192;
constexpr size_t O_WR2_H = O_WR1_L + 4 * 256 * 192;
constexpr size_t O_WR2_L = O_WR2_H + 4 * 256 * 256;
constexpr size_t O_WW_H  = O_WR2_L + 4 * 256 * 256;
constexpr size_t O_WW_L  = O_WW_H  + 4 * 256 * 192;
constexpr size_t O_UW_H  = O_WW_L  + 4 * 256 * 192;
constexpr size_t O_UW_L  = O_UW_H  + 4 * 256 * 256;
constexpr size_t O_M1_H  = O_UW_L  + 4 * 256 * 256;
constexpr size_t O_M1_L  = O_M1_H  + 256 * 128;
constexpr size_t O_M2_H  = O_M1_L  + 256 * 128;
constexpr size_t O_M2_L  = O_M2_H  + 256 * 256;
constexpr size_t O_N1_H  = O_M2_L  + 256 * 256;
constexpr size_t O_N1_L  = O_N1_H  + 512 * 256;
constexpr size_t O_E1_H  = O_N1_L  + 512 * 256;
constexpr size_t O_E1_L  = O_E1_H  + 512 * 512;
constexpr size_t O_ZM_H  = O_E1_L  + 512 * 512;   // l0 interleaved [Wz1|Ww], 512x192
constexpr size_t O_ZM_L  = O_ZM_H  + 512 * 192;
constexpr size_t HF_TOTAL = O_ZM_L + 512 * 192;

__device__ hf g_hf[HF_TOTAL];

// ---------------- helpers --------------------------------------------------
__device__ __forceinline__ uint32_t s2u(const void* p) {
    uint32_t a;
    asm("{ .reg .u64 t; cvta.to.shared.u64 t, %1; cvt.u32.u64 %0, t; }" : "=r"(a) : "l"(p));
    return a;
}

__device__ __forceinline__ void mma16816(float* c, const uint32_t* a, const uint32_t* b) {
    asm volatile(
        "mma.sync.aligned.m16n8k16.row.col.f32.f16.f16.f32 "
        "{%0,%1,%2,%3}, {%4,%5,%6,%7}, {%8,%9}, {%0,%1,%2,%3};"
        : "+f"(c[0]), "+f"(c[1]), "+f"(c[2]), "+f"(c[3])
        : "r"(a[0]), "r"(a[1]), "r"(a[2]), "r"(a[3]), "r"(b[0]), "r"(b[1]));
}

__device__ __forceinline__ void ldsm4(uint32_t* r, uint32_t addr) {
    asm volatile("ldmatrix.sync.aligned.m8n8.x4.shared.b16 {%0,%1,%2,%3}, [%4];"
                 : "=r"(r[0]), "=r"(r[1]), "=r"(r[2]), "=r"(r[3]) : "r"(addr));
}

__device__ __forceinline__ void store_h4(hf* p, float4 v) {
    ((__half2*)p)[0] = __floats2half2_rn(v.x, v.y);
    ((__half2*)p)[1] = __floats2half2_rn(v.z, v.w);
}

__device__ __forceinline__ float4 load_h4(const hf* p) {
    uint2 u = *(const uint2*)p;
    float2 a = __half22float2(*(__half2*)&u.x);
    float2 b = __half22float2(*(__half2*)&u.y);
    return make_float4(a.x, a.y, b.x, b.y);
}

// ---------------- small kernels --------------------------------------------
__global__ void featsk(const float* __restrict__ x, const float* __restrict__ ea,
                       const int* __restrict__ ei, hf* __restrict__ f) {
    int i = blockIdx.x * blockDim.x + threadIdx.x;
    if (i >= NE * 48) return;
    int e = i / 48;
    int q = i - e * 48;
    float4 v = make_float4(0.f, 0.f, 0.f, 0.f);
    if (q < 32) {
        int t = ei[NE + e];
        v = ((const float4*)x)[(size_t)t * 32 + q];
    } else if (q < 40) {
        v = ((const float4*)ea)[(size_t)e * 8 + (q - 32)];
    }
    store_h4(f + (size_t)e * 192 + q * 4, v);
}

__global__ void suvk(const int* __restrict__ nbr, const hf* __restrict__ m,
                     hf* __restrict__ s) {
    int i = blockIdx.x * blockDim.x + threadIdx.x;
    if (i >= NE * 64) return;
    int e = i >> 6, q = i & 63;
    float4 acc = make_float4(0.f, 0.f, 0.f, 0.f);
#pragma unroll
    for (int j = 0; j < 3; ++j) {
        int idx = nbr[3 * (size_t)e + j];
        if (idx > 0) {
            float4 v = load_h4(m + (size_t)(idx - 1) * 256 + q * 4);
            acc.x += v.x; acc.y += v.y; acc.z += v.z; acc.w += v.w;
        }
    }
    store_h4(s + (size_t)e * 256 + q * 4, acc);
}

__global__ void rdashk(const int* __restrict__ nbr, const hf* __restrict__ m,
                       const hf* __restrict__ r, hf* __restrict__ rd) {
    int i = blockIdx.x * blockDim.x + threadIdx.x;
    if (i >= NE * 64) return;
    int e = i >> 6, q = i & 63;
    float4 acc = make_float4(0.f, 0.f, 0.f, 0.f);
#pragma unroll
    for (int j = 0; j < 3; ++j) {
        int idx = nbr[3 * (size_t)e + j];
        if (idx > 0) {
            size_t o = (size_t)(idx - 1) * 256 + q * 4;
            float4 g = load_h4(m + o);
            float4 rr = load_h4(r + o);
            acc.x = fmaf(rr.x, g.x, acc.x);
            acc.y = fmaf(rr.y, g.y, acc.y);
            acc.z = fmaf(rr.z, g.z, acc.z);
            acc.w = fmaf(rr.w, g.w, acc.w);
        }
    }
    store_h4(rd + (size_t)e * 256 + q * 4, acc);
}

__global__ void xedgek(const int* __restrict__ ei, const hf* __restrict__ xg,
                       hf* __restrict__ xe) {
    int i = blockIdx.x * blockDim.x + threadIdx.x;
    if (i >= NP * 64) return;
    int p = i >> 6, q = i & 63;
    int u = ei[2 * p];
    int v = ei[NE + 2 * p];
    float4 a = load_h4(xg + (size_t)u * 256 + q * 4);
    float4 b = load_h4(xg + (size_t)v * 256 + q * 4);
    size_t o = (size_t)p * 512 + q * 4;
    store_h4(xe + o,
        make_float4(fabsf(a.x - b.x), fabsf(a.y - b.y), fabsf(a.z - b.z), fabsf(a.w - b.w)));
    store_h4(xe + o + 256,
        make_float4(a.x + b.x, a.y + b.y, a.z + b.z, a.w + b.w));
}

// fp32 -> fp16 single (activations)
__global__ void convk1(const float* __restrict__ src, long long total, int K, int rowStride,
                       int colOff, int Kp, hf* __restrict__ out) {
    long long i = (long long)blockIdx.x * blockDim.x + threadIdx.x;
    if (i >= total) return;
    int k = (int)(i % Kp);
    long long row = i / Kp;
    float v = (k < K) ? src[row * rowStride + colOff + k] : 0.f;
    out[i] = __float2half_rn(v);
}

// fp32 -> fp16 hi/lo (weights)
__global__ void convk(const float* __restrict__ src, long long total, int K, int rowStride,
                      int colOff, int Kp, hf* __restrict__ hi, hf* __restrict__ lo) {
    long long i = (long long)blockIdx.x * blockDim.x + threadIdx.x;
    if (i >= total) return;
    int k = (int)(i % Kp);
    long long row = i / Kp;
    float v = (k < K) ? src[row * rowStride + colOff + k] : 0.f;
    hf h = __float2half_rn(v);
    hi[i] = h;
    lo[i] = __float2half_rn(v - __half2float(h));
}

// l0 interleaved weights: B'[2j] = Wz1_l0 row j, B'[2j+1] = Ww_l0 row j (K=192)
__global__ void convzm(const float* __restrict__ Wz_w, const float* __restrict__ W_w,
                       hf* __restrict__ hi, hf* __restrict__ lo) {
    int i = blockIdx.x * blockDim.x + threadIdx.x;
    if (i >= 512 * 192) return;
    int row = i / 192, k = i - row * 192;
    int j = row >> 1;
    float v = 0.f;
    if (k < 160) v = (row & 1) ? W_w[j * 160 + k] : Wz_w[j * 416 + k];
    hf h = __float2half_rn(v);
    hi[i] = h;
    lo[i] = __float2half_rn(v - __half2float(h));
}

// ---------------- fp16 2-term mma.sync GEMM ---------------------------------
// C = act(A1@(B1h+B1l)^T + A2@(B2h+B2l)^T + bias); A single fp16, B hi/lo.
// CTA tile 128x128, 8 warps (2x4) of 64x32, K-chunk 32, 3-stage, 2 CTA/SM.
// mode 0=sigmoid 1=GRU 2=relu 3=relu-dot->atomicAdd(lgt) 4=GRU->aggr atomics
//      5=interleaved sig(v0)*tanh(v1) -> msg (w2 = second bias)
#define ROWB 80
#define TILEB (128 * ROWB)            // 10240
#define STAGE_B (3 * TILEB)           // 30720: A, Bh, Bl
#define SMEM_DYN (3 * STAGE_B)        // 92160 -> 2 CTAs/SM

__global__ void __launch_bounds__(256, 2) gemm_tc(
    const hf* __restrict__ A1, int K1p,
    const hf* __restrict__ B1h, const hf* __restrict__ B1l,
    const hf* __restrict__ A2, int K2p,
    const hf* __restrict__ B2h, const hf* __restrict__ B2l,
    const float* __restrict__ bias, int M, int N, int mode,
    const hf* __restrict__ zb, const hf* __restrict__ sb,
    hf* __restrict__ outH,
    const float* __restrict__ w2, float* __restrict__ lgt)
{
    extern __shared__ char dsm[];
    const uint32_t smem_u = s2u(dsm);
    const int tid  = threadIdx.x;
    const int warp = tid >> 5;
    const int lane = tid & 31;
    const int g    = lane >> 2;
    const int t    = lane & 3;
    const int wm   = warp & 1;
    const int wn   = warp >> 1;
    const int m0   = blockIdx.x * 128;
    const int n0   = blockIdx.y * 128;

    const int nch1 = K1p >> 5;
    const int nch2 = B2h ? (K2p >> 5) : 0;
    const int nch  = nch1 + nch2;

    uint32_t aAddr[4], bAddr[2];
#pragma unroll
    for (int mt = 0; mt < 4; ++mt) {
        int row = wm * 64 + mt * 16 + ((lane >> 3) & 1) * 8 + (lane & 7);
        aAddr[mt] = (uint32_t)(row * ROWB + (lane >> 4) * 16);
    }
#pragma unroll
    for (int np = 0; np < 2; ++np) {
        int row = wn * 32 + np * 16 + ((lane >> 4) & 1) * 8 + (lane & 7);
        bAddr[np] = (uint32_t)(TILEB + row * ROWB + ((lane >> 3) & 1) * 16);
    }

    float acc[4][4][4];
#pragma unroll
    for (int i = 0; i < 4; ++i)
#pragma unroll
        for (int j = 0; j < 4; ++j)
#pragma unroll
            for (int k = 0; k < 4; ++k) acc[i][j][k] = 0.f;

    auto issue = [&](int c) {
        const hf *A, *Bh, *Bl;
        int lda, kc;
        if (c < nch1) { A = A1; Bh = B1h; Bl = B1l; lda = K1p; kc = c << 5; }
        else          { A = A2; Bh = B2h; Bl = B2l; lda = K2p; kc = (c - nch1) << 5; }
        uint32_t dst0 = smem_u + (uint32_t)((c % 3) * STAGE_B);
#pragma unroll
        for (int it = 0; it < 6; ++it) {
            int u = tid + it * 256;
            int which = u >> 9;            // 0 A, 1 Bh, 2 Bl
            int rem   = u & 511;
            int row   = rem >> 2;
            int seg   = rem & 3;
            const hf* sm = (which == 0) ? A : (which == 1) ? Bh : Bl;
            int sz = 16;
            long long grow;
            if (which == 0) {
                int gm = m0 + row;
                if (gm >= M) { gm = M - 1; sz = 0; }
                grow = gm;
            } else {
                grow = n0 + row;
            }
            const char* src = (const char*)(sm + grow * (long long)lda + kc) + seg * 16;
            uint32_t du = dst0 + (uint32_t)(which * TILEB + row * ROWB + seg * 16);
            asm volatile("cp.async.cg.shared.global [%0], [%1], 16, %2;"
                         :: "r"(du), "l"(src), "r"(sz) : "memory");
        }
        asm volatile("cp.async.commit_group;" ::: "memory");
    };

    issue(0);
    if (nch > 1) issue(1);
    for (int c = 0; c < nch; ++c) {
        if (c + 1 < nch) asm volatile("cp.async.wait_group 1;" ::: "memory");
        else             asm volatile("cp.async.wait_group 0;" ::: "memory");
        __syncthreads();
        if (c + 2 < nch) issue(c + 2);

        const uint32_t base = smem_u + (uint32_t)((c % 3) * STAGE_B);
#pragma unroll
        for (int ks = 0; ks < 2; ++ks) {
            const uint32_t ko = ks * 32;
            uint32_t ah[4][4], bh[2][4], bl[2][4];
#pragma unroll
            for (int mt = 0; mt < 4; ++mt) ldsm4(ah[mt], base + aAddr[mt] + ko);
#pragma unroll
            for (int np = 0; np < 2; ++np) ldsm4(bh[np], base + bAddr[np] + ko);
#pragma unroll
            for (int mt = 0; mt < 4; ++mt)
#pragma unroll
                for (int nt = 0; nt < 4; ++nt)
                    mma16816(acc[mt][nt], ah[mt], &bh[nt >> 1][(nt & 1) * 2]);
#pragma unroll
            for (int np = 0; np < 2; ++np) ldsm4(bl[np], base + bAddr[np] + TILEB + ko);
#pragma unroll
            for (int mt = 0; mt < 4; ++mt)
#pragma unroll
                for (int nt = 0; nt < 4; ++nt)
                    mma16816(acc[mt][nt], ah[mt], &bl[nt >> 1][(nt & 1) * 2]);
        }
    }

    // ---------------- epilogue ----------------
    if (mode == 3) {
#pragma unroll
        for (int mt = 0; mt < 4; ++mt) {
            int rg = m0 + wm * 64 + mt * 16 + g;
#pragma unroll
            for (int h = 0; h < 2; ++h) {
                int row = rg + h * 8;
                float s = 0.f;
#pragma unroll
                for (int nt = 0; nt < 4; ++nt) {
                    int cn = n0 + wn * 32 + nt * 8 + 2 * t;
                    float v0 = fmaxf(acc[mt][nt][2 * h]     + bias[cn],     0.f);
                    float v1 = fmaxf(acc[mt][nt][2 * h + 1] + bias[cn + 1], 0.f);
                    s = fmaf(v0, w2[cn], s);
                    s = fmaf(v1, w2[cn + 1], s);
                }
                s += __shfl_xor_sync(0xffffffffu, s, 1);
                s += __shfl_xor_sync(0xffffffffu, s, 2);
                if (t == 0 && row < M) atomicAdd(&lgt[row], s);
            }
        }
        return;
    }

    if (mode == 5) {
#pragma unroll
        for (int mt = 0; mt < 4; ++mt) {
            int rg = m0 + wm * 64 + mt * 16 + g;
#pragma unroll
            for (int nt = 0; nt < 4; ++nt) {
                int cn = n0 + wn * 32 + nt * 8 + 2 * t;
                int j = cn >> 1;
                float bz = bias[j], bu = w2[j];
#pragma unroll
                for (int h = 0; h < 2; ++h) {
                    int row = rg + h * 8;
                    if (row >= M) continue;
                    float v0 = acc[mt][nt][2 * h]     + bz;
                    float v1 = acc[mt][nt][2 * h + 1] + bu;
                    float m = (1.f / (1.f + expf(-v0))) * tanhf(v1);
                    outH[(size_t)row * 256 + j] = __float2half_rn(m);
                }
            }
        }
        return;
    }

#pragma unroll
    for (int mt = 0; mt < 4; ++mt) {
        int rg = m0 + wm * 64 + mt * 16 + g;
#pragma unroll
        for (int nt = 0; nt < 4; ++nt) {
            int cn = n0 + wn * 32 + nt * 8 + 2 * t;
            float b0 = bias[cn], b1 = bias[cn + 1];
#pragma unroll
            for (int h = 0; h < 2; ++h) {
                int row = rg + h * 8;
                if (row >= M) continue;
                float v0 = acc[mt][nt][2 * h]     + b0;
                float v1 = acc[mt][nt][2 * h + 1] + b1;
                size_t idx = (size_t)row * N + cn;
                if (mode == 0) {
                    v0 = 1.f / (1.f + expf(-v0));
                    v1 = 1.f / (1.f + expf(-v1));
                } else if (mode == 2) {
                    v0 = fmaxf(v0, 0.f);
                    v1 = fmaxf(v1, 0.f);
                } else {  // 1 or 4: GRU combine
                    float2 zz = __half22float2(*(const __half2*)(zb + idx));
                    float2 ss = __half22float2(*(const __half2*)(sb + idx));
                    v0 = (1.f - zz.x) * ss.x + zz.x * tanhf(v0);
                    v1 = (1.f - zz.y) * ss.y + zz.y * tanhf(v1);
                }
                if (mode == 4) {
                    const int* tgt = (const int*)w2;
                    int tr = tgt[row];
                    atomicAdd(&lgt[(size_t)tr * 256 + cn], v0);
                    atomicAdd(&lgt[(size_t)tr * 256 + cn + 1], v1);
                } else {
                    *(__half2*)(outH + idx) = __floats2half2_rn(v0, v1);
                }
            }
        }
    }
}

// ---------------- softmax (with per-segment scalar bias) --------------------
__global__ void soft1k(const float* __restrict__ ncb, const float* __restrict__ ecb) {
    __shared__ float sm[1024];
    int tid = threadIdx.x;
    float bn = ncb[0], be = ecb[0];
    float mx = -1e30f;
    for (int i = tid; i < TLOG; i += 1024)
        mx = fmaxf(mx, g_logits[i] + (i < NN ? bn : be));
    sm[tid] = mx;
    __syncthreads();
    for (int s = 512; s > 0; s >>= 1) {
        if (tid < s) sm[tid] = fmaxf(sm[tid], sm[tid + s]);
        __syncthreads();
    }
    float gmax = sm[0];
    __syncthreads();
    float sum = 0.f;
    for (int i = tid; i < TLOG; i += 1024)
        sum += expf(g_logits[i] + (i < NN ? bn : be) - gmax);
    sm[tid] = sum;
    __syncthreads();
    for (int s = 512; s > 0; s >>= 1) {
        if (tid < s) sm[tid] += sm[tid + s];
        __syncthreads();
    }
    if (tid == 0) { g_red[0] = gmax; g_red[1] = sm[0]; }
}

__global__ void soft2k(float* __restrict__ out, const float* __restrict__ ncb,
                       const float* __restrict__ ecb) {
    int i = blockIdx.x * blockDim.x + threadIdx.x;
    if (i < TLOG)
        out[i] = expf(g_logits[i] + (i < NN ? ncb[0] : ecb[0]) - g_red[0]) / g_red[1];
}

// ---------------------------------------------------------------------------
extern "C" void kernel_launch(void* const* d_in, const int* in_sizes, int n_in,
                              void* d_out, int out_size) {
    (void)in_sizes; (void)n_in; (void)out_size;
    const float* x     = (const float*)d_in[0];
    const float* ea    = (const float*)d_in[1];
    const int*   ei    = (const int*)d_in[2];
    const int*   nbr   = (const int*)d_in[3];
    const float* Wz_w  = (const float*)d_in[4];
    const float* Wz_b  = (const float*)d_in[5];
    const float* Wr_w  = (const float*)d_in[6];
    const float* Wr_b  = (const float*)d_in[7];
    const float* W_w   = (const float*)d_in[8];
    const float* U_w   = (const float*)d_in[9];
    const float* U_b   = (const float*)d_in[10];
    const float* mlp_w = (const float*)d_in[11];
    const float* mlp_b = (const float*)d_in[12];
    const float* nc1_w = (const float*)d_in[13];
    const float* nc1_b = (const float*)d_in[14];
    const float* nc2_w = (const float*)d_in[15];
    const float* nc2_b = (const float*)d_in[16];
    const float* ec1_w = (const float*)d_in[17];
    const float* ec1_b = (const float*)d_in[18];
    const float* ec2_w = (const float*)d_in[19];
    const float* ec2_b = (const float*)d_in[20];
    float* out = (float*)d_out;

    float *aggr, *logits;
    hf* hb;
    cudaGetSymbolAddress((void**)&aggr,   g_aggr);
    cudaGetSymbolAddress((void**)&logits, g_logits);
    cudaGetSymbolAddress((void**)&hb,     g_hf);

    cudaFuncSetAttribute(gemm_tc, cudaFuncAttributeMaxDynamicSharedMemorySize, SMEM_DYN);

    static cudaStream_t sB = nullptr;
    static cudaEvent_t evA = nullptr, evB = nullptr, evC = nullptr, evD = nullptr;
    static cudaEvent_t evF = nullptr, evW = nullptr;
    if (sB == nullptr) {
        cudaStreamCreate(&sB);
        cudaEventCreateWithFlags(&evA, cudaEventDisableTiming);
        cudaEventCreateWithFlags(&evB, cudaEventDisableTiming);
        cudaEventCreateWithFlags(&evC, cudaEventDisableTiming);
        cudaEventCreateWithFlags(&evD, cudaEventDisableTiming);
        cudaEventCreateWithFlags(&evF, cudaEventDisableTiming);
        cudaEventCreateWithFlags(&evW, cudaEventDisableTiming);
    }

    hf *fA = hb + O_FEATS, *mA = hb + O_MSG, *sA = hb + O_SUV, *rdA = hb + O_RD;
    hf *rA = hb + O_R, *zA = hb + O_Z, *xA = hb + O_X, *aA = hb + O_AG;
    hf *gA = hb + O_XG, *eA = hb + O_XE;

#define CONVW(st, src, tot, K, stride, off, Kp, hi, lo) \
    convk<<<(int)(((long long)(tot) + 255) / 256), 256, 0, st>>>( \
        src, (long long)(tot), K, stride, off, Kp, hi, lo)
#define CONV1(st, src, tot, K, stride, off, Kp, dst) \
    convk1<<<(int)(((long long)(tot) + 255) / 256), 256, 0, st>>>( \
        src, (long long)(tot), K, stride, off, Kp, dst)

    // fork sB from capture-origin stream, then weight convs on sB
    cudaEventRecord(evF, 0);
    cudaStreamWaitEvent(sB, evF, 0);
    CONVW(sB, Wz_w, 4 * 256 * 192, 160, 416, 0, 192, hb + O_WZ1_H, hb + O_WZ1_L);
    CONVW(sB, Wz_w, 4 * 256 * 256, 256, 416, 160, 256, hb + O_WZ2_H, hb + O_WZ2_L);
    CONVW(sB, Wr_w, 4 * 256 * 192, 160, 416, 0, 192, hb + O_WR1_H, hb + O_WR1_L);
    CONVW(sB, Wr_w, 4 * 256 * 256, 256, 416, 160, 256, hb + O_WR2_H, hb + O_WR2_L);
    CONVW(sB, W_w, 4 * 256 * 192, 160, 160, 0, 192, hb + O_WW_H, hb + O_WW_L);
    CONVW(sB, U_w, 4 * 256 * 256, 256, 256, 0, 256, hb + O_UW_H, hb + O_UW_L);
    CONVW(sB, mlp_w, 256 * 128, 128, 384, 0, 128, hb + O_M1_H, hb + O_M1_L);
    CONVW(sB, mlp_w, 256 * 256, 256, 384, 128, 256, hb + O_M2_H, hb + O_M2_L);
    CONVW(sB, nc1_w, 512 * 256, 256, 256, 0, 256, hb + O_N1_H, hb + O_N1_L);
    CONVW(sB, ec1_w, 512 * 512, 512, 512, 0, 512, hb + O_E1_H, hb + O_E1_L);
    convzm<<<(512 * 192 + 255) / 256, 256, 0, sB>>>(Wz_w, W_w, hb + O_ZM_H, hb + O_ZM_L);
    cudaEventRecord(evW, sB);

    // stream 0: activation prep (overlaps weight convs)
    featsk<<<(NE * 48 + 255) / 256, 256>>>(x, ea, ei, fA);
    CONV1(0, x, (long long)NN * 128, 128, 128, 0, 128, xA);
    cudaMemsetAsync(aggr, 0, (size_t)NN * 256 * 4, 0);
    cudaMemsetAsync(logits, 0, TLOG * 4, 0);

    const int MBE = (NE + 127) / 128;   // 938
    const int MBN = (NN + 127) / 128;   // 469
    const int MBP = (NP + 127) / 128;   // 469

    cudaStreamWaitEvent(0, evW, 0);

    // ---- layer 0 fused: msg = sigmoid(feats@Wz1+bz) * tanh(feats@Ww+bu) ----
    gemm_tc<<<dim3(MBE, 4), 256, SMEM_DYN>>>(
        fA, 192, hb + O_ZM_H, hb + O_ZM_L, nullptr, 0, nullptr, nullptr,
        Wz_b, NE, 512, 5, nullptr, nullptr, mA, U_b, nullptr);

    for (int l = 1; l < 4; ++l) {
        hf* wz1H = hb + O_WZ1_H + (size_t)l * 49152;
        hf* wz1L = hb + O_WZ1_L + (size_t)l * 49152;
        hf* wz2H = hb + O_WZ2_H + (size_t)l * 65536;
        hf* wz2L = hb + O_WZ2_L + (size_t)l * 65536;
        hf* wr1H = hb + O_WR1_H + (size_t)l * 49152;
        hf* wr1L = hb + O_WR1_L + (size_t)l * 49152;
        hf* wr2H = hb + O_WR2_H + (size_t)l * 65536;
        hf* wr2L = hb + O_WR2_L + (size_t)l * 65536;
        hf* wwH  = hb + O_WW_H + (size_t)l * 49152;
        hf* wwL  = hb + O_WW_L + (size_t)l * 49152;
        hf* uwH  = hb + O_UW_H + (size_t)l * 65536;
        hf* uwL  = hb + O_UW_L + (size_t)l * 65536;

        // fork: suvk (sB) overlaps r-GEMM (stream 0)
        cudaEventRecord(evA, 0);
        cudaStreamWaitEvent(sB, evA, 0);
        suvk<<<(NE * 64 + 255) / 256, 256, 0, sB>>>(nbr, mA, sA);
        cudaEventRecord(evB, sB);

        // r = sigmoid([feats|msg] @ Wr^T + b) -> fp16
        gemm_tc<<<dim3(MBE, 2), 256, SMEM_DYN>>>(
            fA, 192, wr1H, wr1L, mA, 256, wr2H, wr2L,
            Wr_b + (size_t)l * 256, NE, 256, 0, nullptr, nullptr, rA, nullptr, nullptr);
        cudaEventRecord(evC, 0);
        cudaStreamWaitEvent(sB, evC, 0);
        rdashk<<<(NE * 64 + 255) / 256, 256, 0, sB>>>(nbr, mA, rA, rdA);
        cudaEventRecord(evD, sB);

        // z = sigmoid([feats|suv] @ Wz^T + b) -> fp16
        cudaStreamWaitEvent(0, evB, 0);
        gemm_tc<<<dim3(MBE, 2), 256, SMEM_DYN>>>(
            fA, 192, wz1H, wz1L, sA, 256, wz2H, wz2L,
            Wz_b + (size_t)l * 256, NE, 256, 0, nullptr, nullptr, zA, nullptr, nullptr);

        // msg = (1-z)*suv + z*tanh(feats@W^T + rdash@U^T + b)
        cudaStreamWaitEvent(0, evD, 0);
        int md = (l == 3) ? 4 : 1;
        gemm_tc<<<dim3(MBE, 2), 256, SMEM_DYN>>>(
            fA, 192, wwH, wwL, rdA, 256, uwH, uwL,
            U_b + (size_t)l * 256, NE, 256, md, zA, sA,
            md == 4 ? nullptr : mA,
            md == 4 ? (const float*)(ei + NE) : nullptr, md == 4 ? aggr : nullptr);
    }

    CONV1(0, aggr, (long long)NN * 256, 256, 256, 0, 256, aA);

    // xg = relu([x|aggr] @ mlp^T + b) -> fp16
    gemm_tc<<<dim3(MBN, 2), 256, SMEM_DYN>>>(
        xA, 128, hb + O_M1_H, hb + O_M1_L, aA, 256, hb + O_M2_H, hb + O_M2_L,
        mlp_b, NN, 256, 2, nullptr, nullptr, gA, nullptr, nullptr);
    cudaEventRecord(evA, 0);

    // edge path on sB: xedgek -> edge head
    cudaStreamWaitEvent(sB, evA, 0);
    xedgek<<<(NP * 64 + 255) / 256, 256, 0, sB>>>(ei, gA, eA);
    gemm_tc<<<dim3(MBP, 4), 256, SMEM_DYN, sB>>>(
        eA, 512, hb + O_E1_H, hb + O_E1_L, nullptr, 0, nullptr, nullptr,
        ec1_b, NP, 512, 3, nullptr, nullptr, nullptr, ec2_w, logits + NN);
    cudaEventRecord(evB, sB);

    // node head on stream 0 (concurrent)
    gemm_tc<<<dim3(MBN, 4), 256, SMEM_DYN>>>(
        gA, 256, hb + O_N1_H, hb + O_N1_L, nullptr, 0, nullptr, nullptr,
        nc1_b, NN, 512, 3, nullptr, nullptr, nullptr, nc2_w, logits);

    cudaStreamWaitEvent(0, evB, 0);
    soft1k<<<1, 1024>>>(nc2_b, ec2_b);
    soft2k<<<(TLOG + 255) / 256, 256>>>(out, nc2_b, ec2_b);
}